// round 2
// baseline (speedup 1.0000x reference)
#include <cuda_runtime.h>
#include <math.h>

#define B_ 2
#define C3_ 128
#define DZ_ 32
#define HH_ 24
#define WW_ 24
#define HW_ 576
#define C2_ 96
#define K_ 8
#define E_ 256
#define NH_ 4
#define HD_ 64
#define TOPO_ 64
#define LN_EPS 1e-5f

// ------------------------- device scratch (no allocation) -------------------
__device__ float g_w1t[C2_ * 9 * TOPO_];
__device__ float g_h[B_ * K_ * HW_ * TOPO_];
__device__ float g_topo[B_ * K_ * HW_];
__device__ float g_Q[B_ * NH_ * DZ_ * HW_ * HD_];   // (b,h,z,p,c), pre-scaled by 1/8
__device__ float g_K[B_ * NH_ * K_ * HW_ * HD_];    // (b,h,k,p,c)
__device__ float g_V[B_ * NH_ * K_ * HW_ * HD_];
__device__ float g_O[B_ * DZ_ * HW_ * E_];          // (b,z,p,e)

__device__ __forceinline__ int flex_int(const void* p, int dflt) {
    int v = *(const int*)p;
    if (v >= 1 && v <= 1000000) return v;
    float f = *(const float*)p;
    if (f >= 1.f && f <= 1000000.f) return (int)f;
    return dflt;
}

// ------------------------- kernel 0: transpose conv1 weights ----------------
__global__ void k_wtrans(const float* __restrict__ w1) {
    int i = blockIdx.x * 256 + threadIdx.x;
    if (i < TOPO_ * C2_ * 9) {
        int o = i / (C2_ * 9);
        int r = i % (C2_ * 9);
        int c = r / 9, tap = r % 9;
        g_w1t[(c * 9 + tap) * TOPO_ + o] = w1[i];
    }
}

// ------------------- kernel 1: conv1 3x3 (96->64) + BN + ReLU ---------------
__global__ __launch_bounds__(384) void k_conv1(const float* __restrict__ F2,
                                               const float* __restrict__ bng,
                                               const float* __restrict__ bnb) {
    __shared__ float in_s[16][6][26];
    __shared__ float w_s[16 * 9 * 64];
    int bk = blockIdx.y;                 // b*8+k
    int b = bk >> 3, k = bk & 7;
    int y0 = blockIdx.x * 4;
    int tid = threadIdx.x;
    int ig = tid >> 4;                   // 0..23: pixel group (4 consecutive x)
    int j = tid & 15;                    // 16 groups of 4 output channels
    int pl = ig * 4;
    int yrel = pl / 24;
    int x0 = pl % 24;
    int o0 = j * 4;
    float acc[4][4];
#pragma unroll
    for (int u = 0; u < 4; u++)
#pragma unroll
        for (int v = 0; v < 4; v++) acc[u][v] = 0.f;

    for (int c0 = 0; c0 < C2_; c0 += 16) {
        __syncthreads();
        for (int idx = tid; idx < 16 * 6 * 26; idx += 384) {
            int cc = idx / 156, rem = idx % 156;
            int yy = rem / 26, xx = rem % 26;
            int y = y0 - 1 + yy, x = xx - 1;
            float v = 0.f;
            if ((unsigned)y < 24u && (unsigned)x < 24u)
                v = F2[((b * C2_ + c0 + cc) * HW_ + y * 24 + x) * K_ + k];
            in_s[cc][yy][xx] = v;
        }
        for (int idx = tid; idx < 16 * 9 * 64; idx += 384)
            w_s[idx] = g_w1t[c0 * 9 * 64 + idx];
        __syncthreads();
        for (int cc = 0; cc < 16; cc++) {
#pragma unroll
            for (int dy = 0; dy < 3; dy++) {
                float rv[6];
#pragma unroll
                for (int u = 0; u < 6; u++) rv[u] = in_s[cc][yrel + dy][x0 + u];
#pragma unroll
                for (int dx = 0; dx < 3; dx++) {
                    float4 w4 = *(const float4*)&w_s[(cc * 9 + dy * 3 + dx) * 64 + o0];
#pragma unroll
                    for (int u = 0; u < 4; u++) {
                        float a = rv[u + dx];
                        acc[u][0] += a * w4.x;
                        acc[u][1] += a * w4.y;
                        acc[u][2] += a * w4.z;
                        acc[u][3] += a * w4.w;
                    }
                }
            }
        }
    }
    float invs = rsqrtf(1.f + LN_EPS);
    float s0 = bng[o0] * invs, s1 = bng[o0 + 1] * invs;
    float s2 = bng[o0 + 2] * invs, s3 = bng[o0 + 3] * invs;
    float b0 = bnb[o0], b1 = bnb[o0 + 1], b2 = bnb[o0 + 2], b3 = bnb[o0 + 3];
#pragma unroll
    for (int u = 0; u < 4; u++) {
        int p = (y0 + yrel) * 24 + x0 + u;
        float4 hv;
        hv.x = fmaxf(acc[u][0] * s0 + b0, 0.f);
        hv.y = fmaxf(acc[u][1] * s1 + b1, 0.f);
        hv.z = fmaxf(acc[u][2] * s2 + b2, 0.f);
        hv.w = fmaxf(acc[u][3] * s3 + b3, 0.f);
        *(float4*)&g_h[(bk * HW_ + p) * TOPO_ + o0] = hv;
    }
}

// ------------------- kernel 2: conv2 1x1 + neighbor-sum -> topo -------------
__global__ __launch_bounds__(192) void k_topo(const float* __restrict__ w2,
                                              const float* __restrict__ w2b) {
    __shared__ float sp[HW_];
    __shared__ float wsh[64];
    int bk = blockIdx.x;
    int tid = threadIdx.x;
    if (tid < 64) wsh[tid] = w2[tid];
    __syncthreads();
    for (int p = tid; p < HW_; p += 192) {
        const float* hp = &g_h[(bk * HW_ + p) * TOPO_];
        float s = w2b[0];
#pragma unroll
        for (int o = 0; o < 64; o += 4) {
            float4 hv = *(const float4*)&hp[o];
            s += hv.x * wsh[o] + hv.y * wsh[o + 1] + hv.z * wsh[o + 2] + hv.w * wsh[o + 3];
        }
        sp[p] = s;
    }
    __syncthreads();
    for (int p = tid; p < HW_; p += 192) {
        int y = p / 24, x = p % 24;
        float s = 0.f;
#pragma unroll
        for (int dy = -1; dy <= 1; dy++)
#pragma unroll
            for (int dx = -1; dx <= 1; dx++) {
                if (dy == 0 && dx == 0) continue;
                int yy = y + dy, xx = x + dx;
                if ((unsigned)yy < 24u && (unsigned)xx < 24u) s += sp[yy * 24 + xx];
            }
        g_topo[bk * HW_ + p] = sp[p] + 0.5f * s;
    }
}

// ------------------- kernel 3: K/V projection + LayerNorm -------------------
// grid: B*K*(HW/32) blocks, 256 threads. Each block: 32 rows.
__global__ __launch_bounds__(256) void k_kvproj(const float* __restrict__ F2,
                                                const float* __restrict__ Wk,
                                                const float* __restrict__ Wv,
                                                const float* __restrict__ lng,
                                                const float* __restrict__ lnb) {
    __shared__ float x_s[32][97];
    __shared__ float s_o[32 * 256];
    __shared__ float smean[32], srstd[32];
    int rg0 = blockIdx.x * 32;
    int b = rg0 / (K_ * HW_);
    int k = (rg0 / HW_) & 7;
    int pbase = rg0 % HW_;
    int tid = threadIdx.x;
    int tc = tid & 63;
    int c0 = tc * 4;
    int tr = tid >> 6;
    int r0 = tr * 8;

    for (int idx = tid; idx < 32 * C2_; idx += 256) {
        int r = idx & 31, c = idx >> 5;
        x_s[r][c] = F2[((b * C2_ + c) * HW_ + pbase + r) * K_ + k];
    }
    __syncthreads();

    float ak[8][4], av[8][4];
#pragma unroll
    for (int i = 0; i < 8; i++)
#pragma unroll
        for (int jj = 0; jj < 4; jj++) { ak[i][jj] = 0.f; av[i][jj] = 0.f; }

    for (int kd = 0; kd < C2_; kd++) {
        float4 wk4 = *(const float4*)&Wk[kd * E_ + c0];
        float4 wv4 = *(const float4*)&Wv[kd * E_ + c0];
#pragma unroll
        for (int i = 0; i < 8; i++) {
            float a = x_s[r0 + i][kd];
            ak[i][0] += a * wk4.x; ak[i][1] += a * wk4.y;
            ak[i][2] += a * wk4.z; ak[i][3] += a * wk4.w;
            av[i][0] += a * wv4.x; av[i][1] += a * wv4.y;
            av[i][2] += a * wv4.z; av[i][3] += a * wv4.w;
        }
    }

    int warp = tid >> 5, lane = tid & 31;
    float4 g4 = *(const float4*)&lng[c0];
    float4 b4 = *(const float4*)&lnb[c0];

#pragma unroll
    for (int mat = 0; mat < 2; mat++) {
        // stage to smem for row reduction
#pragma unroll
        for (int i = 0; i < 8; i++)
#pragma unroll
            for (int jj = 0; jj < 4; jj++)
                s_o[(r0 + i) * 256 + c0 + jj] = (mat == 0 ? ak[i][jj] : av[i][jj]);
        __syncthreads();
#pragma unroll
        for (int rr = 0; rr < 4; rr++) {
            int row = warp * 4 + rr;
            float s = 0.f, q = 0.f;
#pragma unroll
            for (int jj = 0; jj < 8; jj++) {
                float v = s_o[row * 256 + lane + 32 * jj];
                s += v; q += v * v;
            }
#pragma unroll
            for (int off = 16; off >= 1; off >>= 1) {
                s += __shfl_xor_sync(0xffffffffu, s, off);
                q += __shfl_xor_sync(0xffffffffu, q, off);
            }
            if (lane == 0) {
                float mu = s * (1.f / 256.f);
                smean[row] = mu;
                srstd[row] = rsqrtf(q * (1.f / 256.f) - mu * mu + LN_EPS);
            }
        }
        __syncthreads();
        int h = c0 >> 6, cc = c0 & 63;
        float* dst = (mat == 0) ? g_K : g_V;
#pragma unroll
        for (int i = 0; i < 8; i++) {
            float mu = smean[r0 + i], rs = srstd[r0 + i];
            float4 o4;
            float v0 = (mat == 0 ? ak[i][0] : av[i][0]);
            float v1 = (mat == 0 ? ak[i][1] : av[i][1]);
            float v2 = (mat == 0 ? ak[i][2] : av[i][2]);
            float v3 = (mat == 0 ? ak[i][3] : av[i][3]);
            o4.x = (v0 - mu) * rs * g4.x + b4.x;
            o4.y = (v1 - mu) * rs * g4.y + b4.y;
            o4.z = (v2 - mu) * rs * g4.z + b4.z;
            o4.w = (v3 - mu) * rs * g4.w + b4.w;
            *(float4*)&dst[((((b * NH_ + h) * K_ + k) * HW_) + pbase + r0 + i) * HD_ + cc] = o4;
        }
        __syncthreads();
    }
}

// ------------------- kernel 4: Q projection + LayerNorm + scale -------------
// grid: B*Dz*(HW/32) blocks, 256 threads.
__global__ __launch_bounds__(256) void k_qproj(const float* __restrict__ F3,
                                               const float* __restrict__ Wq,
                                               const float* __restrict__ lng,
                                               const float* __restrict__ lnb) {
    __shared__ float s_o[32 * 256];   // also aliased as x tile (32x129) first
    __shared__ float smean[32], srstd[32];
    float* x_s = s_o;                 // stride 129
    int rg0 = blockIdx.x * 32;
    int b = rg0 / (DZ_ * HW_);
    int rem = rg0 % (DZ_ * HW_);
    int z = rem / HW_;
    int pbase = rem % HW_;
    int tid = threadIdx.x;
    int tc = tid & 63;
    int c0 = tc * 4;
    int tr = tid >> 6;
    int r0 = tr * 8;

    for (int idx = tid; idx < 32 * C3_; idx += 256) {
        int r = idx & 31, c = idx >> 5;
        x_s[r * 129 + c] = F3[(b * C3_ + c) * (DZ_ * HW_) + z * HW_ + pbase + r];
    }
    __syncthreads();

    float ak[8][4];
#pragma unroll
    for (int i = 0; i < 8; i++)
#pragma unroll
        for (int jj = 0; jj < 4; jj++) ak[i][jj] = 0.f;

    for (int kd = 0; kd < C3_; kd++) {
        float4 w4 = *(const float4*)&Wq[kd * E_ + c0];
#pragma unroll
        for (int i = 0; i < 8; i++) {
            float a = x_s[(r0 + i) * 129 + kd];
            ak[i][0] += a * w4.x; ak[i][1] += a * w4.y;
            ak[i][2] += a * w4.z; ak[i][3] += a * w4.w;
        }
    }
    __syncthreads();   // everyone done reading x_s before s_o overwrite

#pragma unroll
    for (int i = 0; i < 8; i++)
#pragma unroll
        for (int jj = 0; jj < 4; jj++)
            s_o[(r0 + i) * 256 + c0 + jj] = ak[i][jj];
    __syncthreads();

    int warp = tid >> 5, lane = tid & 31;
#pragma unroll
    for (int rr = 0; rr < 4; rr++) {
        int row = warp * 4 + rr;
        float s = 0.f, q = 0.f;
#pragma unroll
        for (int jj = 0; jj < 8; jj++) {
            float v = s_o[row * 256 + lane + 32 * jj];
            s += v; q += v * v;
        }
#pragma unroll
        for (int off = 16; off >= 1; off >>= 1) {
            s += __shfl_xor_sync(0xffffffffu, s, off);
            q += __shfl_xor_sync(0xffffffffu, q, off);
        }
        if (lane == 0) {
            float mu = s * (1.f / 256.f);
            smean[row] = mu;
            srstd[row] = rsqrtf(q * (1.f / 256.f) - mu * mu + LN_EPS);
        }
    }
    __syncthreads();

    float4 g4 = *(const float4*)&lng[c0];
    float4 b4 = *(const float4*)&lnb[c0];
    int h = c0 >> 6, cc = c0 & 63;
    const float qscale = 0.125f;   // 1/sqrt(64)
#pragma unroll
    for (int i = 0; i < 8; i++) {
        float mu = smean[r0 + i], rs = srstd[r0 + i];
        float4 o4;
        o4.x = ((ak[i][0] - mu) * rs * g4.x + b4.x) * qscale;
        o4.y = ((ak[i][1] - mu) * rs * g4.y + b4.y) * qscale;
        o4.z = ((ak[i][2] - mu) * rs * g4.z + b4.z) * qscale;
        o4.w = ((ak[i][3] - mu) * rs * g4.w + b4.w) * qscale;
        *(float4*)&g_Q[((((b * NH_ + h) * DZ_ + z) * HW_) + pbase + r0 + i) * HD_ + cc] = o4;
    }
}

// ------------------- kernel 5: slab-local flash attention -------------------
// grid: B*NH*Dz*(HW/64) blocks, 256 threads, dynamic smem 4*64*65 floats.
__global__ __launch_bounds__(256) void k_attn(const float* __restrict__ lam_p,
                                              const void* __restrict__ D0_p,
                                              const void* __restrict__ slab_p) {
    extern __shared__ float sm[];
    float* Qs = sm;                 // [64][65]
    float* Ks = sm + 64 * 65;       // [64][65]
    float* Vs = sm + 2 * 64 * 65;   // [64][65]
    float* Ps = sm + 3 * 64 * 65;   // [64][65]

    int bid = blockIdx.x;
    int p0 = (bid % 9) * 64;
    int z = (bid / 9) % DZ_;
    int h = (bid / (9 * DZ_)) % NH_;
    int b = bid / (9 * DZ_ * NH_);

    int D0 = flex_int(D0_p, 128);
    int slab = flex_int(slab_p, 16);
    int z0 = (int)llrint((double)(D0 - 1) * (double)z / (double)(DZ_ - 1));
    int kk = z0 / slab;
    if (kk < 0) kk = 0;
    if (kk > K_ - 1) kk = K_ - 1;
    float lamv = *lam_p;

    int tid = threadIdx.x;
    int ty = tid >> 4;          // 0..15 -> 4 q rows
    int tx = tid & 15;          // 0..15 -> 4 k cols / 4 dims
    int r0 = ty * 4;
    int c0 = tx * 4;

    // load Q tile
    {
        long long qb = ((((long long)(b * NH_ + h) * DZ_ + z) * HW_) + p0) * HD_;
        for (int idx = tid; idx < 64 * 64; idx += 256) {
            int r = idx >> 6, d = idx & 63;
            Qs[r * 65 + d] = g_Q[qb + r * 64 + d];
        }
    }

    float m[4], l[4], O[4][4];
#pragma unroll
    for (int i = 0; i < 4; i++) {
        m[i] = -1e30f; l[i] = 0.f;
#pragma unroll
        for (int jj = 0; jj < 4; jj++) O[i][jj] = 0.f;
    }

    int clo = (kk - 1 < 0) ? 0 : kk - 1;
    int chi = (kk + 1 > K_ - 1) ? K_ - 1 : kk + 1;

    for (int c = clo; c <= chi; c++) {
        float bias = (c == kk) ? 0.f : -0.5f;
        long long kb = ((((long long)(b * NH_ + h) * K_ + c) * HW_)) * HD_;
        const float* topo_c = &g_topo[(b * K_ + c) * HW_];
        for (int pk0 = 0; pk0 < HW_; pk0 += 64) {
            __syncthreads();
            for (int idx = tid; idx < 64 * 64; idx += 256) {
                int r = idx >> 6, d = idx & 63;
                long long off = kb + (long long)(pk0 + r) * 64 + d;
                Ks[r * 65 + d] = g_K[off];
                Vs[r * 65 + d] = g_V[off];
            }
            __syncthreads();

            float acc[4][4];
#pragma unroll
            for (int i = 0; i < 4; i++)
#pragma unroll
                for (int jj = 0; jj < 4; jj++) acc[i][jj] = 0.f;

#pragma unroll 8
            for (int d = 0; d < 64; d++) {
                float a0 = Qs[(r0 + 0) * 65 + d];
                float a1 = Qs[(r0 + 1) * 65 + d];
                float a2 = Qs[(r0 + 2) * 65 + d];
                float a3 = Qs[(r0 + 3) * 65 + d];
                float b0 = Ks[(c0 + 0) * 65 + d];
                float b1 = Ks[(c0 + 1) * 65 + d];
                float b2 = Ks[(c0 + 2) * 65 + d];
                float b3 = Ks[(c0 + 3) * 65 + d];
                acc[0][0] += a0 * b0; acc[0][1] += a0 * b1; acc[0][2] += a0 * b2; acc[0][3] += a0 * b3;
                acc[1][0] += a1 * b0; acc[1][1] += a1 * b1; acc[1][2] += a1 * b2; acc[1][3] += a1 * b3;
                acc[2][0] += a2 * b0; acc[2][1] += a2 * b1; acc[2][2] += a2 * b2; acc[2][3] += a2 * b3;
                acc[3][0] += a3 * b0; acc[3][1] += a3 * b1; acc[3][2] += a3 * b2; acc[3][3] += a3 * b3;
            }

            // bias + diagonal topo term
#pragma unroll
            for (int i = 0; i < 4; i++) {
                int pq = p0 + r0 + i;
#pragma unroll
                for (int jj = 0; jj < 4; jj++) {
                    int pk = pk0 + c0 + jj;
                    float s = acc[i][jj] + bias;
                    if (pq == pk) s += lamv * topo_c[pk];
                    acc[i][jj] = s;
                }
            }

            // online softmax (row reduce over 16 lanes of the half-warp)
#pragma unroll
            for (int i = 0; i < 4; i++) {
                float mx = fmaxf(fmaxf(acc[i][0], acc[i][1]), fmaxf(acc[i][2], acc[i][3]));
#pragma unroll
                for (int off = 8; off >= 1; off >>= 1)
                    mx = fmaxf(mx, __shfl_xor_sync(0xffffffffu, mx, off));
                float mn = fmaxf(m[i], mx);
                float corr = __expf(m[i] - mn);
                float rs = 0.f;
#pragma unroll
                for (int jj = 0; jj < 4; jj++) {
                    float p = __expf(acc[i][jj] - mn);
                    Ps[(r0 + i) * 65 + c0 + jj] = p;
                    rs += p;
                }
#pragma unroll
                for (int off = 8; off >= 1; off >>= 1)
                    rs += __shfl_xor_sync(0xffffffffu, rs, off);
                l[i] = l[i] * corr + rs;
                m[i] = mn;
                O[i][0] *= corr; O[i][1] *= corr; O[i][2] *= corr; O[i][3] *= corr;
            }
            __syncthreads();

            // PV: O[i][j] += sum_k Ps[r0+i][k] * Vs[k][c0+j]
#pragma unroll 8
            for (int kx = 0; kx < 64; kx++) {
                float a0 = Ps[(r0 + 0) * 65 + kx];
                float a1 = Ps[(r0 + 1) * 65 + kx];
                float a2 = Ps[(r0 + 2) * 65 + kx];
                float a3 = Ps[(r0 + 3) * 65 + kx];
                float b0 = Vs[kx * 65 + c0 + 0];
                float b1 = Vs[kx * 65 + c0 + 1];
                float b2 = Vs[kx * 65 + c0 + 2];
                float b3 = Vs[kx * 65 + c0 + 3];
                O[0][0] += a0 * b0; O[0][1] += a0 * b1; O[0][2] += a0 * b2; O[0][3] += a0 * b3;
                O[1][0] += a1 * b0; O[1][1] += a1 * b1; O[1][2] += a1 * b2; O[1][3] += a1 * b3;
                O[2][0] += a2 * b0; O[2][1] += a2 * b1; O[2][2] += a2 * b2; O[2][3] += a2 * b3;
                O[3][0] += a3 * b0; O[3][1] += a3 * b1; O[3][2] += a3 * b2; O[3][3] += a3 * b3;
            }
        }
    }

    long long ob = (((long long)(b * DZ_ + z) * HW_) + p0) * E_ + h * HD_;
#pragma unroll
    for (int i = 0; i < 4; i++) {
        float inv = 1.f / l[i];
        float4 o4;
        o4.x = O[i][0] * inv; o4.y = O[i][1] * inv;
        o4.z = O[i][2] * inv; o4.w = O[i][3] * inv;
        *(float4*)&g_O[ob + (long long)(r0 + i) * E_ + c0] = o4;
    }
}

// ------------------- kernel 6: output projection + residual -----------------
// grid: B*Dz*(HW/32) blocks, 256 threads.
__global__ __launch_bounds__(256) void k_oproj(const float* __restrict__ Wp,
                                               const float* __restrict__ F3,
                                               float* __restrict__ out) {
    __shared__ float x_s[32 * 257];
    int rg0 = blockIdx.x * 32;
    int b = rg0 / (DZ_ * HW_);
    int rem = rg0 % (DZ_ * HW_);
    int z = rem / HW_;
    int pbase = rem % HW_;
    int tid = threadIdx.x;
    int tr = tid >> 5;            // 0..7 -> 4 rows each
    int r0 = tr * 4;
    int tc = tid & 31;            // 0..31 -> 4 cols each
    int c0 = tc * 4;

    for (int idx = tid; idx < 32 * E_; idx += 256) {
        int r = idx >> 8, c = idx & 255;
        x_s[r * 257 + c] = g_O[(((long long)(b * DZ_ + z) * HW_) + pbase + r) * E_ + c];
    }
    __syncthreads();

    float acc[4][4];
#pragma unroll
    for (int i = 0; i < 4; i++)
#pragma unroll
        for (int jj = 0; jj < 4; jj++) acc[i][jj] = 0.f;

    for (int kd = 0; kd < E_; kd++) {
        float4 w4 = *(const float4*)&Wp[kd * C3_ + c0];
#pragma unroll
        for (int i = 0; i < 4; i++) {
            float a = x_s[(r0 + i) * 257 + kd];
            acc[i][0] += a * w4.x; acc[i][1] += a * w4.y;
            acc[i][2] += a * w4.z; acc[i][3] += a * w4.w;
        }
    }

#pragma unroll
    for (int i = 0; i < 4; i++) {
        int p = pbase + r0 + i;
#pragma unroll
        for (int jj = 0; jj < 4; jj++) {
            long long oi = (long long)(b * C3_ + c0 + jj) * (DZ_ * HW_) + z * HW_ + p;
            out[oi] = F3[oi] + acc[i][jj];
        }
    }
}

// ----------------------------------- launch ---------------------------------
extern "C" void kernel_launch(void* const* d_in, const int* in_sizes, int n_in,
                              void* d_out, int out_size) {
    const float* F3  = (const float*)d_in[0];
    const float* F2  = (const float*)d_in[1];
    const float* Wq  = (const float*)d_in[2];
    const float* Wk  = (const float*)d_in[3];
    const float* Wv  = (const float*)d_in[4];
    const float* Wp  = (const float*)d_in[5];
    const float* lnqg = (const float*)d_in[6];
    const float* lnqb = (const float*)d_in[7];
    const float* lnkg = (const float*)d_in[8];
    const float* lnkb = (const float*)d_in[9];
    const float* w1   = (const float*)d_in[10];
    const float* bng  = (const float*)d_in[11];
    const float* bnb  = (const float*)d_in[12];
    const float* w2   = (const float*)d_in[13];
    const float* w2b  = (const float*)d_in[14];
    const float* lam  = (const float*)d_in[15];
    const void*  D0p  = d_in[16];
    const void*  slabp = d_in[17];
    float* out = (float*)d_out;

    k_wtrans<<<(TOPO_ * C2_ * 9 + 255) / 256, 256>>>(w1);
    k_conv1<<<dim3(6, B_ * K_), 384>>>(F2, bng, bnb);
    k_topo<<<B_ * K_, 192>>>(w2, w2b);
    k_kvproj<<<B_ * K_ * (HW_ / 32), 256>>>(F2, Wk, Wv, lnkg, lnkb);
    k_qproj<<<B_ * DZ_ * (HW_ / 32), 256>>>(F3, Wq, lnqg, lnqb);

    int attn_smem = 4 * 64 * 65 * (int)sizeof(float);
    static int attn_cfg_done = 0;
    if (!attn_cfg_done) {
        cudaFuncSetAttribute(k_attn, cudaFuncAttributeMaxDynamicSharedMemorySize, attn_smem);
        attn_cfg_done = 1;
    }
    k_attn<<<B_ * NH_ * DZ_ * (HW_ / 64), 256, attn_smem>>>(lam, D0p, slabp);

    k_oproj<<<B_ * DZ_ * (HW_ / 32), 256>>>(Wp, F3, out);
}

// round 3
// speedup vs baseline: 2.1881x; 2.1881x over previous
#include <cuda_runtime.h>
#include <math.h>

#define B_ 2
#define C3_ 128
#define DZ_ 32
#define HW_ 576
#define C2_ 96
#define K_ 8
#define E_ 256
#define NH_ 4
#define HD_ 64
#define TOPO_ 64
#define LN_EPS 1e-5f

// ------------------------- device scratch (no allocation) -------------------
__device__ float g_w1t[C2_ * 9 * TOPO_];
__device__ float g_h[B_ * K_ * HW_ * TOPO_];
__device__ float g_topo[B_ * K_ * HW_];
__device__ float g_Q[B_ * NH_ * DZ_ * HW_ * HD_];   // (b,h,z,p,c), pre-scaled by 1/8
__device__ float g_K[B_ * NH_ * K_ * HW_ * HD_];    // (b,h,k,p,c)
__device__ float g_V[B_ * NH_ * K_ * HW_ * HD_];
__device__ float g_O[B_ * DZ_ * HW_ * E_];          // (b,z,p,e)

__device__ __forceinline__ int flex_int(const void* p, int dflt) {
    int v = *(const int*)p;
    if (v >= 1 && v <= 1000000) return v;
    float f = *(const float*)p;
    if (f >= 1.f && f <= 1000000.f) return (int)f;
    return dflt;
}

__device__ __forceinline__ float tf32r(float x) {
    unsigned u;
    asm("cvt.rna.tf32.f32 %0, %1;" : "=r"(u) : "f"(x));
    return __uint_as_float(u);
}

__device__ __forceinline__ void mma_tf32(float4& d,
                                         unsigned a0, unsigned a1, unsigned a2, unsigned a3,
                                         unsigned b0, unsigned b1) {
    asm volatile(
        "mma.sync.aligned.m16n8k8.row.col.f32.tf32.tf32.f32 "
        "{%0,%1,%2,%3}, {%4,%5,%6,%7}, {%8,%9}, {%0,%1,%2,%3};"
        : "+f"(d.x), "+f"(d.y), "+f"(d.z), "+f"(d.w)
        : "r"(a0), "r"(a1), "r"(a2), "r"(a3), "r"(b0), "r"(b1));
}

// ------------------------- kernel 0: transpose conv1 weights ----------------
__global__ void k_wtrans(const float* __restrict__ w1) {
    int i = blockIdx.x * 256 + threadIdx.x;
    if (i < TOPO_ * C2_ * 9) {
        int o = i / (C2_ * 9);
        int r = i % (C2_ * 9);
        int c = r / 9, tap = r % 9;
        g_w1t[(c * 9 + tap) * TOPO_ + o] = w1[i];
    }
}

// ------------------- kernel 1: conv1 3x3 (96->64) + BN + ReLU ---------------
__global__ __launch_bounds__(384) void k_conv1(const float* __restrict__ F2,
                                               const float* __restrict__ bng,
                                               const float* __restrict__ bnb) {
    __shared__ float in_s[16][6][26];
    __shared__ float w_s[16 * 9 * 64];
    int bk = blockIdx.y;
    int b = bk >> 3, k = bk & 7;
    int y0 = blockIdx.x * 4;
    int tid = threadIdx.x;
    int ig = tid >> 4;
    int j = tid & 15;
    int pl = ig * 4;
    int yrel = pl / 24;
    int x0 = pl % 24;
    int o0 = j * 4;
    float acc[4][4];
#pragma unroll
    for (int u = 0; u < 4; u++)
#pragma unroll
        for (int v = 0; v < 4; v++) acc[u][v] = 0.f;

    for (int c0 = 0; c0 < C2_; c0 += 16) {
        __syncthreads();
        for (int idx = tid; idx < 16 * 6 * 26; idx += 384) {
            int cc = idx / 156, rem = idx % 156;
            int yy = rem / 26, xx = rem % 26;
            int y = y0 - 1 + yy, x = xx - 1;
            float v = 0.f;
            if ((unsigned)y < 24u && (unsigned)x < 24u)
                v = F2[((b * C2_ + c0 + cc) * HW_ + y * 24 + x) * K_ + k];
            in_s[cc][yy][xx] = v;
        }
        for (int idx = tid; idx < 16 * 9 * 64; idx += 384)
            w_s[idx] = g_w1t[c0 * 9 * 64 + idx];
        __syncthreads();
        for (int cc = 0; cc < 16; cc++) {
#pragma unroll
            for (int dy = 0; dy < 3; dy++) {
                float rv[6];
#pragma unroll
                for (int u = 0; u < 6; u++) rv[u] = in_s[cc][yrel + dy][x0 + u];
#pragma unroll
                for (int dx = 0; dx < 3; dx++) {
                    float4 w4 = *(const float4*)&w_s[(cc * 9 + dy * 3 + dx) * 64 + o0];
#pragma unroll
                    for (int u = 0; u < 4; u++) {
                        float a = rv[u + dx];
                        acc[u][0] += a * w4.x;
                        acc[u][1] += a * w4.y;
                        acc[u][2] += a * w4.z;
                        acc[u][3] += a * w4.w;
                    }
                }
            }
        }
    }
    float invs = rsqrtf(1.f + LN_EPS);
    float s0 = bng[o0] * invs, s1 = bng[o0 + 1] * invs;
    float s2 = bng[o0 + 2] * invs, s3 = bng[o0 + 3] * invs;
    float b0 = bnb[o0], b1 = bnb[o0 + 1], b2 = bnb[o0 + 2], b3 = bnb[o0 + 3];
#pragma unroll
    for (int u = 0; u < 4; u++) {
        int p = (y0 + yrel) * 24 + x0 + u;
        float4 hv;
        hv.x = fmaxf(acc[u][0] * s0 + b0, 0.f);
        hv.y = fmaxf(acc[u][1] * s1 + b1, 0.f);
        hv.z = fmaxf(acc[u][2] * s2 + b2, 0.f);
        hv.w = fmaxf(acc[u][3] * s3 + b3, 0.f);
        *(float4*)&g_h[(bk * HW_ + p) * TOPO_ + o0] = hv;
    }
}

// ------------------- kernel 2: conv2 1x1 + neighbor-sum -> topo -------------
__global__ __launch_bounds__(192) void k_topo(const float* __restrict__ w2,
                                              const float* __restrict__ w2b) {
    __shared__ float sp[HW_];
    __shared__ float wsh[64];
    int bk = blockIdx.x;
    int tid = threadIdx.x;
    if (tid < 64) wsh[tid] = w2[tid];
    __syncthreads();
    for (int p = tid; p < HW_; p += 192) {
        const float* hp = &g_h[(bk * HW_ + p) * TOPO_];
        float s = w2b[0];
#pragma unroll
        for (int o = 0; o < 64; o += 4) {
            float4 hv = *(const float4*)&hp[o];
            s += hv.x * wsh[o] + hv.y * wsh[o + 1] + hv.z * wsh[o + 2] + hv.w * wsh[o + 3];
        }
        sp[p] = s;
    }
    __syncthreads();
    for (int p = tid; p < HW_; p += 192) {
        int y = p / 24, x = p % 24;
        float s = 0.f;
#pragma unroll
        for (int dy = -1; dy <= 1; dy++)
#pragma unroll
            for (int dx = -1; dx <= 1; dx++) {
                if (dy == 0 && dx == 0) continue;
                int yy = y + dy, xx = x + dx;
                if ((unsigned)yy < 24u && (unsigned)xx < 24u) s += sp[yy * 24 + xx];
            }
        g_topo[bk * HW_ + p] = sp[p] + 0.5f * s;
    }
}

// ------------------- kernel 3: K/V projection + LayerNorm -------------------
__global__ __launch_bounds__(256) void k_kvproj(const float* __restrict__ F2,
                                                const float* __restrict__ Wk,
                                                const float* __restrict__ Wv,
                                                const float* __restrict__ lng,
                                                const float* __restrict__ lnb) {
    __shared__ float x_s[32][97];
    __shared__ float s_o[32 * 256];
    __shared__ float smean[32], srstd[32];
    int rg0 = blockIdx.x * 32;
    int b = rg0 / (K_ * HW_);
    int k = (rg0 / HW_) & 7;
    int pbase = rg0 % HW_;
    int tid = threadIdx.x;
    int tc = tid & 63;
    int c0 = tc * 4;
    int tr = tid >> 6;
    int r0 = tr * 8;

    for (int idx = tid; idx < 32 * C2_; idx += 256) {
        int r = idx & 31, c = idx >> 5;
        x_s[r][c] = F2[((b * C2_ + c) * HW_ + pbase + r) * K_ + k];
    }
    __syncthreads();

    float ak[8][4], av[8][4];
#pragma unroll
    for (int i = 0; i < 8; i++)
#pragma unroll
        for (int jj = 0; jj < 4; jj++) { ak[i][jj] = 0.f; av[i][jj] = 0.f; }

    for (int kd = 0; kd < C2_; kd++) {
        float4 wk4 = *(const float4*)&Wk[kd * E_ + c0];
        float4 wv4 = *(const float4*)&Wv[kd * E_ + c0];
#pragma unroll
        for (int i = 0; i < 8; i++) {
            float a = x_s[r0 + i][kd];
            ak[i][0] += a * wk4.x; ak[i][1] += a * wk4.y;
            ak[i][2] += a * wk4.z; ak[i][3] += a * wk4.w;
            av[i][0] += a * wv4.x; av[i][1] += a * wv4.y;
            av[i][2] += a * wv4.z; av[i][3] += a * wv4.w;
        }
    }

    int warp = tid >> 5, lane = tid & 31;
    float4 g4 = *(const float4*)&lng[c0];
    float4 b4 = *(const float4*)&lnb[c0];

#pragma unroll
    for (int mat = 0; mat < 2; mat++) {
#pragma unroll
        for (int i = 0; i < 8; i++)
#pragma unroll
            for (int jj = 0; jj < 4; jj++)
                s_o[(r0 + i) * 256 + c0 + jj] = (mat == 0 ? ak[i][jj] : av[i][jj]);
        __syncthreads();
#pragma unroll
        for (int rr = 0; rr < 4; rr++) {
            int row = warp * 4 + rr;
            float s = 0.f, q = 0.f;
#pragma unroll
            for (int jj = 0; jj < 8; jj++) {
                float v = s_o[row * 256 + lane + 32 * jj];
                s += v; q += v * v;
            }
#pragma unroll
            for (int off = 16; off >= 1; off >>= 1) {
                s += __shfl_xor_sync(0xffffffffu, s, off);
                q += __shfl_xor_sync(0xffffffffu, q, off);
            }
            if (lane == 0) {
                float mu = s * (1.f / 256.f);
                smean[row] = mu;
                srstd[row] = rsqrtf(q * (1.f / 256.f) - mu * mu + LN_EPS);
            }
        }
        __syncthreads();
        int h = c0 >> 6, cc = c0 & 63;
        float* dst = (mat == 0) ? g_K : g_V;
#pragma unroll
        for (int i = 0; i < 8; i++) {
            float mu = smean[r0 + i], rs = srstd[r0 + i];
            float4 o4;
            float v0 = (mat == 0 ? ak[i][0] : av[i][0]);
            float v1 = (mat == 0 ? ak[i][1] : av[i][1]);
            float v2 = (mat == 0 ? ak[i][2] : av[i][2]);
            float v3 = (mat == 0 ? ak[i][3] : av[i][3]);
            o4.x = (v0 - mu) * rs * g4.x + b4.x;
            o4.y = (v1 - mu) * rs * g4.y + b4.y;
            o4.z = (v2 - mu) * rs * g4.z + b4.z;
            o4.w = (v3 - mu) * rs * g4.w + b4.w;
            *(float4*)&dst[((((b * NH_ + h) * K_ + k) * HW_) + pbase + r0 + i) * HD_ + cc] = o4;
        }
        __syncthreads();
    }
}

// ------------------- kernel 4: Q projection + LayerNorm + scale -------------
__global__ __launch_bounds__(256) void k_qproj(const float* __restrict__ F3,
                                               const float* __restrict__ Wq,
                                               const float* __restrict__ lng,
                                               const float* __restrict__ lnb) {
    __shared__ float s_o[32 * 256];
    __shared__ float smean[32], srstd[32];
    float* x_s = s_o;
    int rg0 = blockIdx.x * 32;
    int b = rg0 / (DZ_ * HW_);
    int rem = rg0 % (DZ_ * HW_);
    int z = rem / HW_;
    int pbase = rem % HW_;
    int tid = threadIdx.x;
    int tc = tid & 63;
    int c0 = tc * 4;
    int tr = tid >> 6;
    int r0 = tr * 8;

    for (int idx = tid; idx < 32 * C3_; idx += 256) {
        int r = idx & 31, c = idx >> 5;
        x_s[r * 129 + c] = F3[(b * C3_ + c) * (DZ_ * HW_) + z * HW_ + pbase + r];
    }
    __syncthreads();

    float ak[8][4];
#pragma unroll
    for (int i = 0; i < 8; i++)
#pragma unroll
        for (int jj = 0; jj < 4; jj++) ak[i][jj] = 0.f;

    for (int kd = 0; kd < C3_; kd++) {
        float4 w4 = *(const float4*)&Wq[kd * E_ + c0];
#pragma unroll
        for (int i = 0; i < 8; i++) {
            float a = x_s[(r0 + i) * 129 + kd];
            ak[i][0] += a * w4.x; ak[i][1] += a * w4.y;
            ak[i][2] += a * w4.z; ak[i][3] += a * w4.w;
        }
    }
    __syncthreads();

#pragma unroll
    for (int i = 0; i < 8; i++)
#pragma unroll
        for (int jj = 0; jj < 4; jj++)
            s_o[(r0 + i) * 256 + c0 + jj] = ak[i][jj];
    __syncthreads();

    int warp = tid >> 5, lane = tid & 31;
#pragma unroll
    for (int rr = 0; rr < 4; rr++) {
        int row = warp * 4 + rr;
        float s = 0.f, q = 0.f;
#pragma unroll
        for (int jj = 0; jj < 8; jj++) {
            float v = s_o[row * 256 + lane + 32 * jj];
            s += v; q += v * v;
        }
#pragma unroll
        for (int off = 16; off >= 1; off >>= 1) {
            s += __shfl_xor_sync(0xffffffffu, s, off);
            q += __shfl_xor_sync(0xffffffffu, q, off);
        }
        if (lane == 0) {
            float mu = s * (1.f / 256.f);
            smean[row] = mu;
            srstd[row] = rsqrtf(q * (1.f / 256.f) - mu * mu + LN_EPS);
        }
    }
    __syncthreads();

    float4 g4 = *(const float4*)&lng[c0];
    float4 b4 = *(const float4*)&lnb[c0];
    int h = c0 >> 6, cc = c0 & 63;
    const float qscale = 0.125f;
#pragma unroll
    for (int i = 0; i < 8; i++) {
        float mu = smean[r0 + i], rs = srstd[r0 + i];
        float4 o4;
        o4.x = ((ak[i][0] - mu) * rs * g4.x + b4.x) * qscale;
        o4.y = ((ak[i][1] - mu) * rs * g4.y + b4.y) * qscale;
        o4.z = ((ak[i][2] - mu) * rs * g4.z + b4.z) * qscale;
        o4.w = ((ak[i][3] - mu) * rs * g4.w + b4.w) * qscale;
        *(float4*)&g_Q[((((b * NH_ + h) * DZ_ + z) * HW_) + pbase + r0 + i) * HD_ + cc] = o4;
    }
}

// ------------------- kernel 5: slab-local flash attention (tf32 MMA) --------
// grid: B*NH*Dz*9 blocks, 128 threads (4 warps). Warp w owns query rows
// p0 + 16w .. p0 + 16w+15. smem: Qs/Ks/Vs 64x68, Ps 4x16x68 (all tf32-rounded).
#define ATT_STRIDE 68
__global__ __launch_bounds__(128) void k_attn(const float* __restrict__ lam_p,
                                              const void* __restrict__ D0_p,
                                              const void* __restrict__ slab_p) {
    extern __shared__ float sm[];
    float* Qs = sm;                          // [64][68]
    float* Ks = sm + 64 * ATT_STRIDE;        // [64][68]
    float* Vs = sm + 2 * 64 * ATT_STRIDE;    // [64][68]
    float* Ps = sm + 3 * 64 * ATT_STRIDE;    // [4][16][68]

    int bid = blockIdx.x;
    int p0 = (bid % 9) * 64;
    int z = (bid / 9) % DZ_;
    int h = (bid / (9 * DZ_)) % NH_;
    int b = bid / (9 * DZ_ * NH_);

    int D0 = flex_int(D0_p, 128);
    int slab = flex_int(slab_p, 16);
    int z0 = (int)llrint((double)(D0 - 1) * (double)z / (double)(DZ_ - 1));
    int kk = z0 / slab;
    if (kk < 0) kk = 0;
    if (kk > K_ - 1) kk = K_ - 1;
    float lamv = *lam_p;

    int tid = threadIdx.x;
    int w = tid >> 5;
    int lane = tid & 31;
    int g = lane >> 2;        // group id (row within 16-row stripe)
    int t = lane & 3;         // thread-in-group

    // load Q tile (tf32-rounded) into smem
    {
        long long qb = ((((long long)(b * NH_ + h) * DZ_ + z) * HW_) + p0) * HD_;
        for (int idx = tid; idx < 64 * 16; idx += 128) {
            int r = idx >> 4, v = (idx & 15) * 4;
            float4 q4 = *(const float4*)&g_Q[qb + (long long)r * 64 + v];
            float* d = &Qs[r * ATT_STRIDE + v];
            d[0] = tf32r(q4.x); d[1] = tf32r(q4.y);
            d[2] = tf32r(q4.z); d[3] = tf32r(q4.w);
        }
    }

    float m0 = -1e30f, m1 = -1e30f, l0 = 0.f, l1 = 0.f;
    float4 O[8];
#pragma unroll
    for (int n = 0; n < 8; n++) O[n] = make_float4(0.f, 0.f, 0.f, 0.f);

    int clo = (kk - 1 < 0) ? 0 : kk - 1;
    int chi = (kk + 1 > K_ - 1) ? K_ - 1 : kk + 1;

    int rq0 = p0 + w * 16 + g;      // global query row for c0/c1
    float* Pw = &Ps[w * 16 * ATT_STRIDE];

    for (int c = clo; c <= chi; c++) {
        float bias = (c == kk) ? 0.f : -0.5f;
        long long kb = (((long long)(b * NH_ + h) * K_ + c) * HW_) * HD_;
        const float* topo_c = &g_topo[(b * K_ + c) * HW_];
        for (int pk0 = 0; pk0 < HW_; pk0 += 64) {
            __syncthreads();
            for (int idx = tid; idx < 64 * 16; idx += 128) {
                int r = idx >> 4, v = (idx & 15) * 4;
                long long off = kb + (long long)(pk0 + r) * 64 + v;
                float4 k4 = *(const float4*)&g_K[off];
                float4 v4 = *(const float4*)&g_V[off];
                float* dk = &Ks[r * ATT_STRIDE + v];
                float* dv = &Vs[r * ATT_STRIDE + v];
                dk[0] = tf32r(k4.x); dk[1] = tf32r(k4.y);
                dk[2] = tf32r(k4.z); dk[3] = tf32r(k4.w);
                dv[0] = tf32r(v4.x); dv[1] = tf32r(v4.y);
                dv[2] = tf32r(v4.z); dv[3] = tf32r(v4.w);
            }
            __syncthreads();

            // S = Q * K^T  (16x64 per warp)
            float4 S[8];
#pragma unroll
            for (int n = 0; n < 8; n++) S[n] = make_float4(0.f, 0.f, 0.f, 0.f);
#pragma unroll
            for (int kc = 0; kc < 8; kc++) {
                const float* qrow0 = &Qs[(w * 16 + g) * ATT_STRIDE + kc * 8];
                const float* qrow1 = qrow0 + 8 * ATT_STRIDE;
                unsigned a0 = __float_as_uint(qrow0[t]);
                unsigned a1 = __float_as_uint(qrow1[t]);
                unsigned a2 = __float_as_uint(qrow0[t + 4]);
                unsigned a3 = __float_as_uint(qrow1[t + 4]);
#pragma unroll
                for (int n = 0; n < 8; n++) {
                    const float* krow = &Ks[(n * 8 + g) * ATT_STRIDE + kc * 8];
                    unsigned b0 = __float_as_uint(krow[t]);
                    unsigned b1 = __float_as_uint(krow[t + 4]);
                    mma_tf32(S[n], a0, a1, a2, a3, b0, b1);
                }
            }

            // bias + diagonal topo
#pragma unroll
            for (int n = 0; n < 8; n++) {
                int j0 = pk0 + n * 8 + 2 * t;
                int j1 = j0 + 1;
                float s00 = S[n].x + bias, s01 = S[n].y + bias;
                float s10 = S[n].z + bias, s11 = S[n].w + bias;
                if (rq0 == j0) s00 += lamv * topo_c[j0];
                if (rq0 == j1) s01 += lamv * topo_c[j1];
                if (rq0 + 8 == j0) s10 += lamv * topo_c[j0];
                if (rq0 + 8 == j1) s11 += lamv * topo_c[j1];
                S[n].x = s00; S[n].y = s01; S[n].z = s10; S[n].w = s11;
            }

            // online softmax
            float mx0 = -1e30f, mx1 = -1e30f;
#pragma unroll
            for (int n = 0; n < 8; n++) {
                mx0 = fmaxf(mx0, fmaxf(S[n].x, S[n].y));
                mx1 = fmaxf(mx1, fmaxf(S[n].z, S[n].w));
            }
            mx0 = fmaxf(mx0, __shfl_xor_sync(0xffffffffu, mx0, 1));
            mx0 = fmaxf(mx0, __shfl_xor_sync(0xffffffffu, mx0, 2));
            mx1 = fmaxf(mx1, __shfl_xor_sync(0xffffffffu, mx1, 1));
            mx1 = fmaxf(mx1, __shfl_xor_sync(0xffffffffu, mx1, 2));
            float mn0 = fmaxf(m0, mx0), mn1 = fmaxf(m1, mx1);
            float corr0 = __expf(m0 - mn0), corr1 = __expf(m1 - mn1);
            float rs0 = 0.f, rs1 = 0.f;
#pragma unroll
            for (int n = 0; n < 8; n++) {
                float p00 = __expf(S[n].x - mn0);
                float p01 = __expf(S[n].y - mn0);
                float p10 = __expf(S[n].z - mn1);
                float p11 = __expf(S[n].w - mn1);
                rs0 += p00 + p01;
                rs1 += p10 + p11;
                float* pr0 = &Pw[g * ATT_STRIDE + n * 8 + 2 * t];
                float* pr1 = pr0 + 8 * ATT_STRIDE;
                pr0[0] = tf32r(p00); pr0[1] = tf32r(p01);
                pr1[0] = tf32r(p10); pr1[1] = tf32r(p11);
            }
            rs0 += __shfl_xor_sync(0xffffffffu, rs0, 1);
            rs0 += __shfl_xor_sync(0xffffffffu, rs0, 2);
            rs1 += __shfl_xor_sync(0xffffffffu, rs1, 1);
            rs1 += __shfl_xor_sync(0xffffffffu, rs1, 2);
            l0 = l0 * corr0 + rs0;
            l1 = l1 * corr1 + rs1;
            m0 = mn0; m1 = mn1;
#pragma unroll
            for (int n = 0; n < 8; n++) {
                O[n].x *= corr0; O[n].y *= corr0;
                O[n].z *= corr1; O[n].w *= corr1;
            }
            __syncwarp();

            // O += P * V  (16x64 per warp)
#pragma unroll
            for (int kc = 0; kc < 8; kc++) {
                const float* prow0 = &Pw[g * ATT_STRIDE + kc * 8];
                const float* prow1 = prow0 + 8 * ATT_STRIDE;
                unsigned a0 = __float_as_uint(prow0[t]);
                unsigned a1 = __float_as_uint(prow1[t]);
                unsigned a2 = __float_as_uint(prow0[t + 4]);
                unsigned a3 = __float_as_uint(prow1[t + 4]);
#pragma unroll
                for (int n = 0; n < 8; n++) {
                    const float* vrow = &Vs[(kc * 8 + t) * ATT_STRIDE + n * 8 + g];
                    unsigned b0 = __float_as_uint(vrow[0]);
                    unsigned b1 = __float_as_uint(vrow[4 * ATT_STRIDE]);
                    mma_tf32(O[n], a0, a1, a2, a3, b0, b1);
                }
            }
        }
    }

    float inv0 = 1.f / l0, inv1 = 1.f / l1;
    long long ob = ((long long)(b * DZ_ + z) * HW_) * E_ + h * HD_;
#pragma unroll
    for (int n = 0; n < 8; n++) {
        float2 o0 = make_float2(O[n].x * inv0, O[n].y * inv0);
        float2 o1 = make_float2(O[n].z * inv1, O[n].w * inv1);
        *(float2*)&g_O[ob + (long long)rq0 * E_ + n * 8 + 2 * t] = o0;
        *(float2*)&g_O[ob + (long long)(rq0 + 8) * E_ + n * 8 + 2 * t] = o1;
    }
}

// ------------------- kernel 6: output projection + residual -----------------
__global__ __launch_bounds__(256) void k_oproj(const float* __restrict__ Wp,
                                               const float* __restrict__ F3,
                                               float* __restrict__ out) {
    __shared__ float x_s[32 * 257];
    int rg0 = blockIdx.x * 32;
    int b = rg0 / (DZ_ * HW_);
    int rem = rg0 % (DZ_ * HW_);
    int z = rem / HW_;
    int pbase = rem % HW_;
    int tid = threadIdx.x;
    int tr = tid >> 5;
    int r0 = tr * 4;
    int tc = tid & 31;
    int c0 = tc * 4;

    for (int idx = tid; idx < 32 * E_; idx += 256) {
        int r = idx >> 8, c = idx & 255;
        x_s[r * 257 + c] = g_O[(((long long)(b * DZ_ + z) * HW_) + pbase + r) * E_ + c];
    }
    __syncthreads();

    float acc[4][4];
#pragma unroll
    for (int i = 0; i < 4; i++)
#pragma unroll
        for (int jj = 0; jj < 4; jj++) acc[i][jj] = 0.f;

    for (int kd = 0; kd < E_; kd++) {
        float4 w4 = *(const float4*)&Wp[kd * C3_ + c0];
#pragma unroll
        for (int i = 0; i < 4; i++) {
            float a = x_s[(r0 + i) * 257 + kd];
            acc[i][0] += a * w4.x; acc[i][1] += a * w4.y;
            acc[i][2] += a * w4.z; acc[i][3] += a * w4.w;
        }
    }

#pragma unroll
    for (int i = 0; i < 4; i++) {
        int p = pbase + r0 + i;
#pragma unroll
        for (int jj = 0; jj < 4; jj++) {
            long long oi = (long long)(b * C3_ + c0 + jj) * (DZ_ * HW_) + z * HW_ + p;
            out[oi] = F3[oi] + acc[i][jj];
        }
    }
}

// ----------------------------------- launch ---------------------------------
extern "C" void kernel_launch(void* const* d_in, const int* in_sizes, int n_in,
                              void* d_out, int out_size) {
    const float* F3  = (const float*)d_in[0];
    const float* F2  = (const float*)d_in[1];
    const float* Wq  = (const float*)d_in[2];
    const float* Wk  = (const float*)d_in[3];
    const float* Wv  = (const float*)d_in[4];
    const float* Wp  = (const float*)d_in[5];
    const float* lnqg = (const float*)d_in[6];
    const float* lnqb = (const float*)d_in[7];
    const float* lnkg = (const float*)d_in[8];
    const float* lnkb = (const float*)d_in[9];
    const float* w1   = (const float*)d_in[10];
    const float* bng  = (const float*)d_in[11];
    const float* bnb  = (const float*)d_in[12];
    const float* w2   = (const float*)d_in[13];
    const float* w2b  = (const float*)d_in[14];
    const float* lam  = (const float*)d_in[15];
    const void*  D0p  = d_in[16];
    const void*  slabp = d_in[17];
    float* out = (float*)d_out;

    k_wtrans<<<(TOPO_ * C2_ * 9 + 255) / 256, 256>>>(w1);
    k_conv1<<<dim3(6, B_ * K_), 384>>>(F2, bng, bnb);
    k_topo<<<B_ * K_, 192>>>(w2, w2b);
    k_kvproj<<<B_ * K_ * (HW_ / 32), 256>>>(F2, Wk, Wv, lnkg, lnkb);
    k_qproj<<<B_ * DZ_ * (HW_ / 32), 256>>>(F3, Wq, lnqg, lnqb);

    int attn_smem = 4 * 64 * ATT_STRIDE * (int)sizeof(float);
    static int attn_cfg_done = 0;
    if (!attn_cfg_done) {
        cudaFuncSetAttribute(k_attn, cudaFuncAttributeMaxDynamicSharedMemorySize, attn_smem);
        attn_cfg_done = 1;
    }
    k_attn<<<B_ * NH_ * DZ_ * 9, 128, attn_smem>>>(lam, D0p, slabp);

    k_oproj<<<B_ * DZ_ * (HW_ / 32), 256>>>(Wp, F3, out);
}

// round 4
// speedup vs baseline: 2.4764x; 1.1318x over previous
#include <cuda_runtime.h>
#include <math.h>

#define B_ 2
#define C3_ 128
#define DZ_ 32
#define HW_ 576
#define C2_ 96
#define K_ 8
#define E_ 256
#define NH_ 4
#define HD_ 64
#define TOPO_ 64
#define LN_EPS 1e-5f

// ------------------------- device scratch (no allocation) -------------------
__device__ float g_w1t[C2_ * 9 * TOPO_];
__device__ float g_h[B_ * K_ * HW_ * TOPO_];
__device__ float g_topo[B_ * K_ * HW_];
__device__ float g_Q[B_ * NH_ * DZ_ * HW_ * HD_];   // tf32-rounded, pre-scaled 1/8
__device__ float g_K[B_ * NH_ * K_ * HW_ * HD_];    // tf32-rounded
__device__ float g_V[B_ * NH_ * K_ * HW_ * HD_];    // tf32-rounded
__device__ float g_O[B_ * DZ_ * HW_ * E_];

__device__ __forceinline__ int flex_int(const void* p, int dflt) {
    int v = *(const int*)p;
    if (v >= 1 && v <= 1000000) return v;
    float f = *(const float*)p;
    if (f >= 1.f && f <= 1000000.f) return (int)f;
    return dflt;
}

__device__ __forceinline__ float tf32r(float x) {
    unsigned u;
    asm("cvt.rna.tf32.f32 %0, %1;" : "=r"(u) : "f"(x));
    return __uint_as_float(u);
}

__device__ __forceinline__ void mma_tf32(float4& d,
                                         unsigned a0, unsigned a1, unsigned a2, unsigned a3,
                                         unsigned b0, unsigned b1) {
    asm volatile(
        "mma.sync.aligned.m16n8k8.row.col.f32.tf32.tf32.f32 "
        "{%0,%1,%2,%3}, {%4,%5,%6,%7}, {%8,%9}, {%0,%1,%2,%3};"
        : "+f"(d.x), "+f"(d.y), "+f"(d.z), "+f"(d.w)
        : "r"(a0), "r"(a1), "r"(a2), "r"(a3), "r"(b0), "r"(b1));
}

// ------------------------- kernel 0: transpose conv1 weights ----------------
__global__ void k_wtrans(const float* __restrict__ w1) {
    int i = blockIdx.x * 256 + threadIdx.x;
    if (i < TOPO_ * C2_ * 9) {
        int o = i / (C2_ * 9);
        int r = i % (C2_ * 9);
        int c = r / 9, tap = r % 9;
        g_w1t[(c * 9 + tap) * TOPO_ + o] = w1[i];
    }
}

// ------------------- kernel 1: conv1 3x3 (96->64) + BN + ReLU ---------------
__global__ __launch_bounds__(384) void k_conv1(const float* __restrict__ F2,
                                               const float* __restrict__ bng,
                                               const float* __restrict__ bnb) {
    __shared__ float in_s[16][6][26];
    __shared__ float w_s[16 * 9 * 64];
    int bk = blockIdx.y;
    int b = bk >> 3, k = bk & 7;
    int y0 = blockIdx.x * 4;
    int tid = threadIdx.x;
    int ig = tid >> 4;
    int j = tid & 15;
    int pl = ig * 4;
    int yrel = pl / 24;
    int x0 = pl % 24;
    int o0 = j * 4;
    float acc[4][4];
#pragma unroll
    for (int u = 0; u < 4; u++)
#pragma unroll
        for (int v = 0; v < 4; v++) acc[u][v] = 0.f;

    for (int c0 = 0; c0 < C2_; c0 += 16) {
        __syncthreads();
        for (int idx = tid; idx < 16 * 6 * 26; idx += 384) {
            int cc = idx / 156, rem = idx % 156;
            int yy = rem / 26, xx = rem % 26;
            int y = y0 - 1 + yy, x = xx - 1;
            float v = 0.f;
            if ((unsigned)y < 24u && (unsigned)x < 24u)
                v = F2[((b * C2_ + c0 + cc) * HW_ + y * 24 + x) * K_ + k];
            in_s[cc][yy][xx] = v;
        }
        for (int idx = tid; idx < 16 * 9 * 64; idx += 384)
            w_s[idx] = g_w1t[c0 * 9 * 64 + idx];
        __syncthreads();
        for (int cc = 0; cc < 16; cc++) {
#pragma unroll
            for (int dy = 0; dy < 3; dy++) {
                float rv[6];
#pragma unroll
                for (int u = 0; u < 6; u++) rv[u] = in_s[cc][yrel + dy][x0 + u];
#pragma unroll
                for (int dx = 0; dx < 3; dx++) {
                    float4 w4 = *(const float4*)&w_s[(cc * 9 + dy * 3 + dx) * 64 + o0];
#pragma unroll
                    for (int u = 0; u < 4; u++) {
                        float a = rv[u + dx];
                        acc[u][0] += a * w4.x;
                        acc[u][1] += a * w4.y;
                        acc[u][2] += a * w4.z;
                        acc[u][3] += a * w4.w;
                    }
                }
            }
        }
    }
    float invs = rsqrtf(1.f + LN_EPS);
    float s0 = bng[o0] * invs, s1 = bng[o0 + 1] * invs;
    float s2 = bng[o0 + 2] * invs, s3 = bng[o0 + 3] * invs;
    float b0 = bnb[o0], b1 = bnb[o0 + 1], b2 = bnb[o0 + 2], b3 = bnb[o0 + 3];
#pragma unroll
    for (int u = 0; u < 4; u++) {
        int p = (y0 + yrel) * 24 + x0 + u;
        float4 hv;
        hv.x = fmaxf(acc[u][0] * s0 + b0, 0.f);
        hv.y = fmaxf(acc[u][1] * s1 + b1, 0.f);
        hv.z = fmaxf(acc[u][2] * s2 + b2, 0.f);
        hv.w = fmaxf(acc[u][3] * s3 + b3, 0.f);
        *(float4*)&g_h[(bk * HW_ + p) * TOPO_ + o0] = hv;
    }
}

// ------------------- kernel 2: conv2 1x1 + neighbor-sum -> topo -------------
__global__ __launch_bounds__(192) void k_topo(const float* __restrict__ w2,
                                              const float* __restrict__ w2b) {
    __shared__ float sp[HW_];
    __shared__ float wsh[64];
    int bk = blockIdx.x;
    int tid = threadIdx.x;
    if (tid < 64) wsh[tid] = w2[tid];
    __syncthreads();
    for (int p = tid; p < HW_; p += 192) {
        const float* hp = &g_h[(bk * HW_ + p) * TOPO_];
        float s = w2b[0];
#pragma unroll
        for (int o = 0; o < 64; o += 4) {
            float4 hv = *(const float4*)&hp[o];
            s += hv.x * wsh[o] + hv.y * wsh[o + 1] + hv.z * wsh[o + 2] + hv.w * wsh[o + 3];
        }
        sp[p] = s;
    }
    __syncthreads();
    for (int p = tid; p < HW_; p += 192) {
        int y = p / 24, x = p % 24;
        float s = 0.f;
#pragma unroll
        for (int dy = -1; dy <= 1; dy++)
#pragma unroll
            for (int dx = -1; dx <= 1; dx++) {
                if (dy == 0 && dx == 0) continue;
                int yy = y + dy, xx = x + dx;
                if ((unsigned)yy < 24u && (unsigned)xx < 24u) s += sp[yy * 24 + xx];
            }
        g_topo[bk * HW_ + p] = sp[p] + 0.5f * s;
    }
}

// ------------------- kernel 3: K/V projection + LayerNorm (16 rows/block) ---
__global__ __launch_bounds__(256) void k_kvproj(const float* __restrict__ F2,
                                                const float* __restrict__ Wk,
                                                const float* __restrict__ Wv,
                                                const float* __restrict__ lng,
                                                const float* __restrict__ lnb) {
    __shared__ float x_s[16][97];
    __shared__ float s_o[16 * 256];
    __shared__ float smean[16], srstd[16];
    int rg0 = blockIdx.x * 16;
    int b = rg0 / (K_ * HW_);
    int k = (rg0 / HW_) & 7;
    int pbase = rg0 % HW_;
    int tid = threadIdx.x;
    int tc = tid & 63;
    int c0 = tc * 4;
    int tr = tid >> 6;
    int r0 = tr * 4;

    for (int idx = tid; idx < 16 * C2_; idx += 256) {
        int r = idx & 15, c = idx >> 4;
        x_s[r][c] = F2[((b * C2_ + c) * HW_ + pbase + r) * K_ + k];
    }
    __syncthreads();

    float ak[4][4], av[4][4];
#pragma unroll
    for (int i = 0; i < 4; i++)
#pragma unroll
        for (int jj = 0; jj < 4; jj++) { ak[i][jj] = 0.f; av[i][jj] = 0.f; }

#pragma unroll 4
    for (int kd = 0; kd < C2_; kd++) {
        float4 wk4 = *(const float4*)&Wk[kd * E_ + c0];
        float4 wv4 = *(const float4*)&Wv[kd * E_ + c0];
#pragma unroll
        for (int i = 0; i < 4; i++) {
            float a = x_s[r0 + i][kd];
            ak[i][0] += a * wk4.x; ak[i][1] += a * wk4.y;
            ak[i][2] += a * wk4.z; ak[i][3] += a * wk4.w;
            av[i][0] += a * wv4.x; av[i][1] += a * wv4.y;
            av[i][2] += a * wv4.z; av[i][3] += a * wv4.w;
        }
    }

    int warp = tid >> 5, lane = tid & 31;
    float4 g4 = *(const float4*)&lng[c0];
    float4 b4 = *(const float4*)&lnb[c0];

#pragma unroll
    for (int mat = 0; mat < 2; mat++) {
#pragma unroll
        for (int i = 0; i < 4; i++)
#pragma unroll
            for (int jj = 0; jj < 4; jj++)
                s_o[(r0 + i) * 256 + c0 + jj] = (mat == 0 ? ak[i][jj] : av[i][jj]);
        __syncthreads();
#pragma unroll
        for (int rr = 0; rr < 2; rr++) {
            int row = warp * 2 + rr;
            float s = 0.f, q = 0.f;
#pragma unroll
            for (int jj = 0; jj < 8; jj++) {
                float v = s_o[row * 256 + lane + 32 * jj];
                s += v; q += v * v;
            }
#pragma unroll
            for (int off = 16; off >= 1; off >>= 1) {
                s += __shfl_xor_sync(0xffffffffu, s, off);
                q += __shfl_xor_sync(0xffffffffu, q, off);
            }
            if (lane == 0) {
                float mu = s * (1.f / 256.f);
                smean[row] = mu;
                srstd[row] = rsqrtf(q * (1.f / 256.f) - mu * mu + LN_EPS);
            }
        }
        __syncthreads();
        int h = c0 >> 6, cc = c0 & 63;
        float* dst = (mat == 0) ? g_K : g_V;
#pragma unroll
        for (int i = 0; i < 4; i++) {
            float mu = smean[r0 + i], rs = srstd[r0 + i];
            float v0 = (mat == 0 ? ak[i][0] : av[i][0]);
            float v1 = (mat == 0 ? ak[i][1] : av[i][1]);
            float v2 = (mat == 0 ? ak[i][2] : av[i][2]);
            float v3 = (mat == 0 ? ak[i][3] : av[i][3]);
            float4 o4;
            o4.x = tf32r((v0 - mu) * rs * g4.x + b4.x);
            o4.y = tf32r((v1 - mu) * rs * g4.y + b4.y);
            o4.z = tf32r((v2 - mu) * rs * g4.z + b4.z);
            o4.w = tf32r((v3 - mu) * rs * g4.w + b4.w);
            *(float4*)&dst[((((b * NH_ + h) * K_ + k) * HW_) + pbase + r0 + i) * HD_ + cc] = o4;
        }
        __syncthreads();
    }
}

// ------------------- kernel 4: Q projection + LN + scale (16 rows/block) ----
__global__ __launch_bounds__(256) void k_qproj(const float* __restrict__ F3,
                                               const float* __restrict__ Wq,
                                               const float* __restrict__ lng,
                                               const float* __restrict__ lnb) {
    __shared__ float x_s[16 * 129];
    __shared__ float s_o[16 * 256];
    __shared__ float smean[16], srstd[16];
    int rg0 = blockIdx.x * 16;
    int b = rg0 / (DZ_ * HW_);
    int rem = rg0 % (DZ_ * HW_);
    int z = rem / HW_;
    int pbase = rem % HW_;
    int tid = threadIdx.x;
    int tc = tid & 63;
    int c0 = tc * 4;
    int tr = tid >> 6;
    int r0 = tr * 4;

    for (int idx = tid; idx < 16 * C3_; idx += 256) {
        int r = idx & 15, c = idx >> 4;
        x_s[r * 129 + c] = F3[(b * C3_ + c) * (DZ_ * HW_) + z * HW_ + pbase + r];
    }
    __syncthreads();

    float ak[4][4];
#pragma unroll
    for (int i = 0; i < 4; i++)
#pragma unroll
        for (int jj = 0; jj < 4; jj++) ak[i][jj] = 0.f;

#pragma unroll 4
    for (int kd = 0; kd < C3_; kd++) {
        float4 w4 = *(const float4*)&Wq[kd * E_ + c0];
#pragma unroll
        for (int i = 0; i < 4; i++) {
            float a = x_s[(r0 + i) * 129 + kd];
            ak[i][0] += a * w4.x; ak[i][1] += a * w4.y;
            ak[i][2] += a * w4.z; ak[i][3] += a * w4.w;
        }
    }

#pragma unroll
    for (int i = 0; i < 4; i++)
#pragma unroll
        for (int jj = 0; jj < 4; jj++)
            s_o[(r0 + i) * 256 + c0 + jj] = ak[i][jj];
    __syncthreads();

    int warp = tid >> 5, lane = tid & 31;
#pragma unroll
    for (int rr = 0; rr < 2; rr++) {
        int row = warp * 2 + rr;
        float s = 0.f, q = 0.f;
#pragma unroll
        for (int jj = 0; jj < 8; jj++) {
            float v = s_o[row * 256 + lane + 32 * jj];
            s += v; q += v * v;
        }
#pragma unroll
        for (int off = 16; off >= 1; off >>= 1) {
            s += __shfl_xor_sync(0xffffffffu, s, off);
            q += __shfl_xor_sync(0xffffffffu, q, off);
        }
        if (lane == 0) {
            float mu = s * (1.f / 256.f);
            smean[row] = mu;
            srstd[row] = rsqrtf(q * (1.f / 256.f) - mu * mu + LN_EPS);
        }
    }
    __syncthreads();

    float4 g4 = *(const float4*)&lng[c0];
    float4 b4 = *(const float4*)&lnb[c0];
    int h = c0 >> 6, cc = c0 & 63;
    const float qscale = 0.125f;
#pragma unroll
    for (int i = 0; i < 4; i++) {
        float mu = smean[r0 + i], rs = srstd[r0 + i];
        float4 o4;
        o4.x = tf32r(((ak[i][0] - mu) * rs * g4.x + b4.x) * qscale);
        o4.y = tf32r(((ak[i][1] - mu) * rs * g4.y + b4.y) * qscale);
        o4.z = tf32r(((ak[i][2] - mu) * rs * g4.z + b4.z) * qscale);
        o4.w = tf32r(((ak[i][3] - mu) * rs * g4.w + b4.w) * qscale);
        *(float4*)&g_Q[((((b * NH_ + h) * DZ_ + z) * HW_) + pbase + r0 + i) * HD_ + cc] = o4;
    }
}

// ------------------- kernel 5: flash attention, 2 z-planes per block --------
// grid: B*NH*(DZ/2)*9 blocks, 128 threads (4 warps). Warp w: z = z0+(w>>1),
// rows p0 + (w&1)*32 .. +31 (2 mma stripes). K/V tiles shared by all 4 warps.
#define ST 68
__global__ __launch_bounds__(128) void k_attn(const float* __restrict__ lam_p,
                                              const void* __restrict__ D0_p,
                                              const void* __restrict__ slab_p) {
    extern __shared__ float sm[];
    float* Qs = sm;                       // [128][ST]
    float* Ks = sm + 128 * ST;            // [64][ST]
    float* Vs = sm + 192 * ST;            // [64][ST]
    float* Ps = sm + 256 * ST;            // [128][ST]

    int bid = blockIdx.x;
    int p0 = (bid % 9) * 64;
    int zp = (bid / 9) % (DZ_ / 2);
    int h = (bid / (9 * (DZ_ / 2))) % NH_;
    int b = bid / (9 * (DZ_ / 2) * NH_);
    int z0 = zp * 2;

    int D0 = flex_int(D0_p, 128);
    int slab = flex_int(slab_p, 16);
    float lamv = *lam_p;

    int kkz[2], cloz[2], chiz[2];
#pragma unroll
    for (int i = 0; i < 2; i++) {
        int zz = z0 + i;
        int zq = (int)llrint((double)(D0 - 1) * (double)zz / (double)(DZ_ - 1));
        int kk = zq / slab;
        if (kk < 0) kk = 0;
        if (kk > K_ - 1) kk = K_ - 1;
        kkz[i] = kk;
        cloz[i] = (kk - 1 < 0) ? 0 : kk - 1;
        chiz[i] = (kk + 1 > K_ - 1) ? K_ - 1 : kk + 1;
    }
    int cU_lo = min(cloz[0], cloz[1]);
    int cU_hi = max(chiz[0], chiz[1]);

    int tid = threadIdx.x;
    int w = tid >> 5;
    int lane = tid & 31;
    int g = lane >> 2;
    int t = lane & 3;

    int wz = w >> 1;                 // which z this warp handles
    int zw = z0 + wz;
    int kk_w = kkz[wz], clo_w = cloz[wz], chi_w = chiz[wz];
    int prow = p0 + (w & 1) * 32;    // warp's pixel-row base
    int qrow = w * 32;               // warp's Qs row base

    // load Q (128 rows = 2 z-planes)
    {
        long long qb0 = ((((long long)(b * NH_ + h) * DZ_ + z0) * HW_) + p0) * HD_;
#pragma unroll
        for (int it = 0; it < 16; it++) {
            int idx = tid + it * 128;
            int r = idx >> 4, v = (idx & 15) * 4;
            long long src = qb0 + (long long)(r >> 6) * (HW_ * HD_) + (long long)(r & 63) * 64 + v;
            *(float4*)&Qs[r * ST + v] = *(const float4*)&g_Q[src];
        }
    }

    float m00 = -1e30f, m01 = -1e30f, m10 = -1e30f, m11 = -1e30f;
    float l00 = 0.f, l01 = 0.f, l10 = 0.f, l11 = 0.f;
    float4 O0[8], O1[8];
#pragma unroll
    for (int n = 0; n < 8; n++) {
        O0[n] = make_float4(0.f, 0.f, 0.f, 0.f);
        O1[n] = make_float4(0.f, 0.f, 0.f, 0.f);
    }

    float* Pw = &Ps[(long long)qrow * ST];

    for (int c = cU_lo; c <= cU_hi; c++) {
        bool active = (c >= clo_w) && (c <= chi_w);
        float bias = (c == kk_w) ? 0.f : -0.5f;
        long long kb = (((long long)(b * NH_ + h) * K_ + c) * HW_) * HD_;
        const float* topo_c = &g_topo[(b * K_ + c) * HW_];
        for (int pk0 = 0; pk0 < HW_; pk0 += 64) {
            __syncthreads();
#pragma unroll
            for (int it = 0; it < 8; it++) {
                int idx = tid + it * 128;
                int r = idx >> 4, v = (idx & 15) * 4;
                long long off = kb + (long long)(pk0 + r) * 64 + v;
                *(float4*)&Ks[r * ST + v] = *(const float4*)&g_K[off];
                *(float4*)&Vs[r * ST + v] = *(const float4*)&g_V[off];
            }
            __syncthreads();
            if (!active) continue;

            // ---- S = Q*K^T for both stripes ----
            float4 S0[8], S1[8];
#pragma unroll
            for (int n = 0; n < 8; n++) {
                S0[n] = make_float4(0.f, 0.f, 0.f, 0.f);
                S1[n] = make_float4(0.f, 0.f, 0.f, 0.f);
            }
#pragma unroll
            for (int kc = 0; kc < 8; kc++) {
                const float* qa = &Qs[(qrow + g) * ST + kc * 8];
                unsigned a00 = __float_as_uint(qa[t]);
                unsigned a02 = __float_as_uint(qa[t + 4]);
                unsigned a01 = __float_as_uint(qa[8 * ST + t]);
                unsigned a03 = __float_as_uint(qa[8 * ST + t + 4]);
                unsigned a10 = __float_as_uint(qa[16 * ST + t]);
                unsigned a12 = __float_as_uint(qa[16 * ST + t + 4]);
                unsigned a11 = __float_as_uint(qa[24 * ST + t]);
                unsigned a13 = __float_as_uint(qa[24 * ST + t + 4]);
#pragma unroll
                for (int n = 0; n < 8; n++) {
                    const float* kr = &Ks[(n * 8 + g) * ST + kc * 8];
                    unsigned b0 = __float_as_uint(kr[t]);
                    unsigned b1 = __float_as_uint(kr[t + 4]);
                    mma_tf32(S0[n], a00, a01, a02, a03, b0, b1);
                    mma_tf32(S1[n], a10, a11, a12, a13, b0, b1);
                }
            }

            // ---- bias + diag topo ----
            int rq0 = prow + g;        // stripe0 rows rq0, rq0+8
            int rq1 = prow + 16 + g;   // stripe1 rows rq1, rq1+8
#pragma unroll
            for (int n = 0; n < 8; n++) {
                int j0 = pk0 + n * 8 + 2 * t;
                int j1 = j0 + 1;
                S0[n].x += bias; S0[n].y += bias; S0[n].z += bias; S0[n].w += bias;
                S1[n].x += bias; S1[n].y += bias; S1[n].z += bias; S1[n].w += bias;
                if (rq0 == j0)     S0[n].x += lamv * topo_c[j0];
                if (rq0 == j1)     S0[n].y += lamv * topo_c[j1];
                if (rq0 + 8 == j0) S0[n].z += lamv * topo_c[j0];
                if (rq0 + 8 == j1) S0[n].w += lamv * topo_c[j1];
                if (rq1 == j0)     S1[n].x += lamv * topo_c[j0];
                if (rq1 == j1)     S1[n].y += lamv * topo_c[j1];
                if (rq1 + 8 == j0) S1[n].z += lamv * topo_c[j0];
                if (rq1 + 8 == j1) S1[n].w += lamv * topo_c[j1];
            }

            // ---- online softmax (both stripes) ----
            float mxa = -1e30f, mxb = -1e30f, mxc = -1e30f, mxd = -1e30f;
#pragma unroll
            for (int n = 0; n < 8; n++) {
                mxa = fmaxf(mxa, fmaxf(S0[n].x, S0[n].y));
                mxb = fmaxf(mxb, fmaxf(S0[n].z, S0[n].w));
                mxc = fmaxf(mxc, fmaxf(S1[n].x, S1[n].y));
                mxd = fmaxf(mxd, fmaxf(S1[n].z, S1[n].w));
            }
#pragma unroll
            for (int off = 1; off <= 2; off <<= 1) {
                mxa = fmaxf(mxa, __shfl_xor_sync(0xffffffffu, mxa, off));
                mxb = fmaxf(mxb, __shfl_xor_sync(0xffffffffu, mxb, off));
                mxc = fmaxf(mxc, __shfl_xor_sync(0xffffffffu, mxc, off));
                mxd = fmaxf(mxd, __shfl_xor_sync(0xffffffffu, mxd, off));
            }
            float n00 = fmaxf(m00, mxa), n01 = fmaxf(m01, mxb);
            float n10 = fmaxf(m10, mxc), n11 = fmaxf(m11, mxd);
            float c00 = __expf(m00 - n00), c01 = __expf(m01 - n01);
            float c10 = __expf(m10 - n10), c11 = __expf(m11 - n11);
            float r00 = 0.f, r01 = 0.f, r10 = 0.f, r11 = 0.f;
#pragma unroll
            for (int n = 0; n < 8; n++) {
                float p0a = __expf(S0[n].x - n00), p0b = __expf(S0[n].y - n00);
                float p0c = __expf(S0[n].z - n01), p0d = __expf(S0[n].w - n01);
                float p1a = __expf(S1[n].x - n10), p1b = __expf(S1[n].y - n10);
                float p1c = __expf(S1[n].z - n11), p1d = __expf(S1[n].w - n11);
                r00 += p0a + p0b; r01 += p0c + p0d;
                r10 += p1a + p1b; r11 += p1c + p1d;
                float* q0 = &Pw[g * ST + n * 8 + 2 * t];
                q0[0] = tf32r(p0a); q0[1] = tf32r(p0b);
                q0[8 * ST] = tf32r(p0c); q0[8 * ST + 1] = tf32r(p0d);
                q0[16 * ST] = tf32r(p1a); q0[16 * ST + 1] = tf32r(p1b);
                q0[24 * ST] = tf32r(p1c); q0[24 * ST + 1] = tf32r(p1d);
            }
#pragma unroll
            for (int off = 1; off <= 2; off <<= 1) {
                r00 += __shfl_xor_sync(0xffffffffu, r00, off);
                r01 += __shfl_xor_sync(0xffffffffu, r01, off);
                r10 += __shfl_xor_sync(0xffffffffu, r10, off);
                r11 += __shfl_xor_sync(0xffffffffu, r11, off);
            }
            l00 = l00 * c00 + r00; l01 = l01 * c01 + r01;
            l10 = l10 * c10 + r10; l11 = l11 * c11 + r11;
            m00 = n00; m01 = n01; m10 = n10; m11 = n11;
#pragma unroll
            for (int n = 0; n < 8; n++) {
                O0[n].x *= c00; O0[n].y *= c00; O0[n].z *= c01; O0[n].w *= c01;
                O1[n].x *= c10; O1[n].y *= c10; O1[n].z *= c11; O1[n].w *= c11;
            }
            __syncwarp();

            // ---- O += P*V for both stripes ----
#pragma unroll
            for (int kc = 0; kc < 8; kc++) {
                const float* pa = &Pw[g * ST + kc * 8];
                unsigned a00 = __float_as_uint(pa[t]);
                unsigned a02 = __float_as_uint(pa[t + 4]);
                unsigned a01 = __float_as_uint(pa[8 * ST + t]);
                unsigned a03 = __float_as_uint(pa[8 * ST + t + 4]);
                unsigned a10 = __float_as_uint(pa[16 * ST + t]);
                unsigned a12 = __float_as_uint(pa[16 * ST + t + 4]);
                unsigned a11 = __float_as_uint(pa[24 * ST + t]);
                unsigned a13 = __float_as_uint(pa[24 * ST + t + 4]);
#pragma unroll
                for (int n = 0; n < 8; n++) {
                    const float* vr = &Vs[(kc * 8 + t) * ST + n * 8 + g];
                    unsigned b0 = __float_as_uint(vr[0]);
                    unsigned b1 = __float_as_uint(vr[4 * ST]);
                    mma_tf32(O0[n], a00, a01, a02, a03, b0, b1);
                    mma_tf32(O1[n], a10, a11, a12, a13, b0, b1);
                }
            }
        }
    }

    float i00 = 1.f / l00, i01 = 1.f / l01, i10 = 1.f / l10, i11 = 1.f / l11;
    long long ob = ((long long)(b * DZ_ + zw) * HW_) * E_ + h * HD_;
    int rq0 = prow + g, rq1 = prow + 16 + g;
#pragma unroll
    for (int n = 0; n < 8; n++) {
        int col = n * 8 + 2 * t;
        *(float2*)&g_O[ob + (long long)rq0 * E_ + col] = make_float2(O0[n].x * i00, O0[n].y * i00);
        *(float2*)&g_O[ob + (long long)(rq0 + 8) * E_ + col] = make_float2(O0[n].z * i01, O0[n].w * i01);
        *(float2*)&g_O[ob + (long long)rq1 * E_ + col] = make_float2(O1[n].x * i10, O1[n].y * i10);
        *(float2*)&g_O[ob + (long long)(rq1 + 8) * E_ + col] = make_float2(O1[n].z * i11, O1[n].w * i11);
    }
}

// ------------------- kernel 6: output projection + residual (16 rows) -------
__global__ __launch_bounds__(256) void k_oproj(const float* __restrict__ Wp,
                                               const float* __restrict__ F3,
                                               float* __restrict__ out) {
    __shared__ float x_s[16 * 257];
    int rg0 = blockIdx.x * 16;
    int b = rg0 / (DZ_ * HW_);
    int rem = rg0 % (DZ_ * HW_);
    int z = rem / HW_;
    int pbase = rem % HW_;
    int tid = threadIdx.x;
    int tr = tid >> 5;            // 0..7 -> 2 rows each
    int r0 = tr * 2;
    int tc = tid & 31;
    int c0 = tc * 4;

    for (int idx = tid; idx < 16 * E_; idx += 256) {
        int r = idx >> 8, c = idx & 255;
        x_s[r * 257 + c] = g_O[(((long long)(b * DZ_ + z) * HW_) + pbase + r) * E_ + c];
    }
    __syncthreads();

    float acc[2][4];
#pragma unroll
    for (int i = 0; i < 2; i++)
#pragma unroll
        for (int jj = 0; jj < 4; jj++) acc[i][jj] = 0.f;

#pragma unroll 4
    for (int kd = 0; kd < E_; kd++) {
        float4 w4 = *(const float4*)&Wp[kd * C3_ + c0];
#pragma unroll
        for (int i = 0; i < 2; i++) {
            float a = x_s[(r0 + i) * 257 + kd];
            acc[i][0] += a * w4.x; acc[i][1] += a * w4.y;
            acc[i][2] += a * w4.z; acc[i][3] += a * w4.w;
        }
    }

#pragma unroll
    for (int i = 0; i < 2; i++) {
        int p = pbase + r0 + i;
#pragma unroll
        for (int jj = 0; jj < 4; jj++) {
            long long oi = (long long)(b * C3_ + c0 + jj) * (DZ_ * HW_) + z * HW_ + p;
            out[oi] = F3[oi] + acc[i][jj];
        }
    }
}

// ----------------------------------- launch ---------------------------------
extern "C" void kernel_launch(void* const* d_in, const int* in_sizes, int n_in,
                              void* d_out, int out_size) {
    const float* F3  = (const float*)d_in[0];
    const float* F2  = (const float*)d_in[1];
    const float* Wq  = (const float*)d_in[2];
    const float* Wk  = (const float*)d_in[3];
    const float* Wv  = (const float*)d_in[4];
    const float* Wp  = (const float*)d_in[5];
    const float* lnqg = (const float*)d_in[6];
    const float* lnqb = (const float*)d_in[7];
    const float* lnkg = (const float*)d_in[8];
    const float* lnkb = (const float*)d_in[9];
    const float* w1   = (const float*)d_in[10];
    const float* bng  = (const float*)d_in[11];
    const float* bnb  = (const float*)d_in[12];
    const float* w2   = (const float*)d_in[13];
    const float* w2b  = (const float*)d_in[14];
    const float* lam  = (const float*)d_in[15];
    const void*  D0p  = d_in[16];
    const void*  slabp = d_in[17];
    float* out = (float*)d_out;

    k_wtrans<<<(TOPO_ * C2_ * 9 + 255) / 256, 256>>>(w1);
    k_conv1<<<dim3(6, B_ * K_), 384>>>(F2, bng, bnb);
    k_topo<<<B_ * K_, 192>>>(w2, w2b);
    k_kvproj<<<B_ * K_ * (HW_ / 16), 256>>>(F2, Wk, Wv, lnkg, lnkb);
    k_qproj<<<B_ * DZ_ * (HW_ / 16), 256>>>(F3, Wq, lnqg, lnqb);

    int attn_smem = 384 * ST * (int)sizeof(float);   // 104448 B
    static int attn_cfg_done = 0;
    if (!attn_cfg_done) {
        cudaFuncSetAttribute(k_attn, cudaFuncAttributeMaxDynamicSharedMemorySize, attn_smem);
        attn_cfg_done = 1;
    }
    k_attn<<<B_ * NH_ * (DZ_ / 2) * 9, 128, attn_smem>>>(lam, D0p, slabp);

    k_oproj<<<B_ * DZ_ * (HW_ / 16), 256>>>(Wp, F3, out);
}

// round 5
// speedup vs baseline: 3.1526x; 1.2730x over previous
#include <cuda_runtime.h>
#include <math.h>

#define B_ 2
#define C3_ 128
#define DZ_ 32
#define HW_ 576
#define C2_ 96
#define K_ 8
#define E_ 256
#define NH_ 4
#define HD_ 64
#define TOPO_ 64
#define LN_EPS 1e-5f

// ------------------------- device scratch (no allocation) -------------------
__device__ float g_w1t[C2_ * 9 * TOPO_];
__device__ float g_h[B_ * K_ * HW_ * TOPO_];
__device__ float g_topo[B_ * K_ * HW_];
__device__ float g_Q[B_ * NH_ * DZ_ * HW_ * HD_];   // tf32-rounded, pre-scaled 1/8
__device__ float g_K[B_ * NH_ * K_ * HW_ * HD_];    // tf32-rounded
__device__ float g_V[B_ * NH_ * K_ * HW_ * HD_];    // tf32-rounded
__device__ float g_O[B_ * DZ_ * HW_ * E_];
__device__ float g_WqT[E_ * C3_];                   // WqT[e][c3]
__device__ float g_WpT[C3_ * E_];                   // WpT[c3][e]

__device__ __forceinline__ int flex_int(const void* p, int dflt) {
    int v = *(const int*)p;
    if (v >= 1 && v <= 1000000) return v;
    float f = *(const float*)p;
    if (f >= 1.f && f <= 1000000.f) return (int)f;
    return dflt;
}

__device__ __forceinline__ float tf32r(float x) {
    unsigned u;
    asm("cvt.rna.tf32.f32 %0, %1;" : "=r"(u) : "f"(x));
    return __uint_as_float(u);
}

__device__ __forceinline__ void mma_tf32(float4& d,
                                         unsigned a0, unsigned a1, unsigned a2, unsigned a3,
                                         unsigned b0, unsigned b1) {
    asm volatile(
        "mma.sync.aligned.m16n8k8.row.col.f32.tf32.tf32.f32 "
        "{%0,%1,%2,%3}, {%4,%5,%6,%7}, {%8,%9}, {%0,%1,%2,%3};"
        : "+f"(d.x), "+f"(d.y), "+f"(d.z), "+f"(d.w)
        : "r"(a0), "r"(a1), "r"(a2), "r"(a3), "r"(b0), "r"(b1));
}

// re-fragment an S/P accumulator fragment (m16n8 D layout) into an A fragment
// (m16k8) using quad shuffles. All 32 lanes must participate (warp-uniform).
__device__ __forceinline__ void pfrag(const float4 S, int s0, bool odd,
                                      unsigned& a0, unsigned& a1,
                                      unsigned& a2, unsigned& a3) {
    float x0 = __shfl_sync(0xffffffffu, S.x, s0);
    float y0 = __shfl_sync(0xffffffffu, S.y, s0);
    float z0 = __shfl_sync(0xffffffffu, S.z, s0);
    float w0 = __shfl_sync(0xffffffffu, S.w, s0);
    float x1 = __shfl_sync(0xffffffffu, S.x, s0 + 2);
    float y1 = __shfl_sync(0xffffffffu, S.y, s0 + 2);
    float z1 = __shfl_sync(0xffffffffu, S.z, s0 + 2);
    float w1 = __shfl_sync(0xffffffffu, S.w, s0 + 2);
    a0 = __float_as_uint(odd ? y0 : x0);
    a1 = __float_as_uint(odd ? w0 : z0);
    a2 = __float_as_uint(odd ? y1 : x1);
    a3 = __float_as_uint(odd ? w1 : z1);
}

// ------------------------- kernel 0a: transpose conv1 weights ---------------
__global__ void k_wtrans(const float* __restrict__ w1) {
    int i = blockIdx.x * 256 + threadIdx.x;
    if (i < TOPO_ * C2_ * 9) {
        int o = i / (C2_ * 9);
        int r = i % (C2_ * 9);
        int c = r / 9, tap = r % 9;
        g_w1t[(c * 9 + tap) * TOPO_ + o] = w1[i];
    }
}

// ------------------------- kernel 0b: transpose Wq / Wp ---------------------
__global__ void k_wprep(const float* __restrict__ Wq, const float* __restrict__ Wp) {
    int i = blockIdx.x * 256 + threadIdx.x;
    if (i < C3_ * E_) {
        int e = i / C3_, c = i % C3_;
        g_WqT[i] = Wq[c * E_ + e];          // WqT[e][c] = Wq[c][e]
        g_WpT[c * E_ + e] = Wp[i];          // WpT[c][e] = Wp[e][c]
    }
}

// ------------------- kernel 1: conv1 3x3 (96->64) + BN + ReLU ---------------
__global__ __launch_bounds__(384) void k_conv1(const float* __restrict__ F2,
                                               const float* __restrict__ bng,
                                               const float* __restrict__ bnb) {
    __shared__ float in_s[16][6][26];
    __shared__ float w_s[16 * 9 * 64];
    int bk = blockIdx.y;
    int b = bk >> 3, k = bk & 7;
    int y0 = blockIdx.x * 4;
    int tid = threadIdx.x;
    int ig = tid >> 4;
    int j = tid & 15;
    int pl = ig * 4;
    int yrel = pl / 24;
    int x0 = pl % 24;
    int o0 = j * 4;
    float acc[4][4];
#pragma unroll
    for (int u = 0; u < 4; u++)
#pragma unroll
        for (int v = 0; v < 4; v++) acc[u][v] = 0.f;

    for (int c0 = 0; c0 < C2_; c0 += 16) {
        __syncthreads();
        for (int idx = tid; idx < 16 * 6 * 26; idx += 384) {
            int cc = idx / 156, rem = idx % 156;
            int yy = rem / 26, xx = rem % 26;
            int y = y0 - 1 + yy, x = xx - 1;
            float v = 0.f;
            if ((unsigned)y < 24u && (unsigned)x < 24u)
                v = F2[((b * C2_ + c0 + cc) * HW_ + y * 24 + x) * K_ + k];
            in_s[cc][yy][xx] = v;
        }
        for (int idx = tid; idx < 16 * 9 * 64; idx += 384)
            w_s[idx] = g_w1t[c0 * 9 * 64 + idx];
        __syncthreads();
        for (int cc = 0; cc < 16; cc++) {
#pragma unroll
            for (int dy = 0; dy < 3; dy++) {
                float rv[6];
#pragma unroll
                for (int u = 0; u < 6; u++) rv[u] = in_s[cc][yrel + dy][x0 + u];
#pragma unroll
                for (int dx = 0; dx < 3; dx++) {
                    float4 w4 = *(const float4*)&w_s[(cc * 9 + dy * 3 + dx) * 64 + o0];
#pragma unroll
                    for (int u = 0; u < 4; u++) {
                        float a = rv[u + dx];
                        acc[u][0] += a * w4.x;
                        acc[u][1] += a * w4.y;
                        acc[u][2] += a * w4.z;
                        acc[u][3] += a * w4.w;
                    }
                }
            }
        }
    }
    float invs = rsqrtf(1.f + LN_EPS);
    float s0 = bng[o0] * invs, s1 = bng[o0 + 1] * invs;
    float s2 = bng[o0 + 2] * invs, s3 = bng[o0 + 3] * invs;
    float b0 = bnb[o0], b1 = bnb[o0 + 1], b2 = bnb[o0 + 2], b3 = bnb[o0 + 3];
#pragma unroll
    for (int u = 0; u < 4; u++) {
        int p = (y0 + yrel) * 24 + x0 + u;
        float4 hv;
        hv.x = fmaxf(acc[u][0] * s0 + b0, 0.f);
        hv.y = fmaxf(acc[u][1] * s1 + b1, 0.f);
        hv.z = fmaxf(acc[u][2] * s2 + b2, 0.f);
        hv.w = fmaxf(acc[u][3] * s3 + b3, 0.f);
        *(float4*)&g_h[(bk * HW_ + p) * TOPO_ + o0] = hv;
    }
}

// ------------------- kernel 2: conv2 1x1 + neighbor-sum -> topo -------------
__global__ __launch_bounds__(192) void k_topo(const float* __restrict__ w2,
                                              const float* __restrict__ w2b) {
    __shared__ float sp[HW_];
    __shared__ float wsh[64];
    int bk = blockIdx.x;
    int tid = threadIdx.x;
    if (tid < 64) wsh[tid] = w2[tid];
    __syncthreads();
    for (int p = tid; p < HW_; p += 192) {
        const float* hp = &g_h[(bk * HW_ + p) * TOPO_];
        float s = w2b[0];
#pragma unroll
        for (int o = 0; o < 64; o += 4) {
            float4 hv = *(const float4*)&hp[o];
            s += hv.x * wsh[o] + hv.y * wsh[o + 1] + hv.z * wsh[o + 2] + hv.w * wsh[o + 3];
        }
        sp[p] = s;
    }
    __syncthreads();
    for (int p = tid; p < HW_; p += 192) {
        int y = p / 24, x = p % 24;
        float s = 0.f;
#pragma unroll
        for (int dy = -1; dy <= 1; dy++)
#pragma unroll
            for (int dx = -1; dx <= 1; dx++) {
                if (dy == 0 && dx == 0) continue;
                int yy = y + dy, xx = x + dx;
                if ((unsigned)yy < 24u && (unsigned)xx < 24u) s += sp[yy * 24 + xx];
            }
        g_topo[bk * HW_ + p] = sp[p] + 0.5f * s;
    }
}

// ------------------- kernel 3: K/V projection + LayerNorm (SIMT) ------------
__global__ __launch_bounds__(256) void k_kvproj(const float* __restrict__ F2,
                                                const float* __restrict__ Wk,
                                                const float* __restrict__ Wv,
                                                const float* __restrict__ lng,
                                                const float* __restrict__ lnb) {
    __shared__ float x_s[16][97];
    __shared__ float s_o[16 * 256];
    __shared__ float smean[16], srstd[16];
    int rg0 = blockIdx.x * 16;
    int b = rg0 / (K_ * HW_);
    int k = (rg0 / HW_) & 7;
    int pbase = rg0 % HW_;
    int tid = threadIdx.x;
    int tc = tid & 63;
    int c0 = tc * 4;
    int tr = tid >> 6;
    int r0 = tr * 4;

    for (int idx = tid; idx < 16 * C2_; idx += 256) {
        int r = idx & 15, c = idx >> 4;
        x_s[r][c] = F2[((b * C2_ + c) * HW_ + pbase + r) * K_ + k];
    }
    __syncthreads();

    float ak[4][4], av[4][4];
#pragma unroll
    for (int i = 0; i < 4; i++)
#pragma unroll
        for (int jj = 0; jj < 4; jj++) { ak[i][jj] = 0.f; av[i][jj] = 0.f; }

#pragma unroll 4
    for (int kd = 0; kd < C2_; kd++) {
        float4 wk4 = *(const float4*)&Wk[kd * E_ + c0];
        float4 wv4 = *(const float4*)&Wv[kd * E_ + c0];
#pragma unroll
        for (int i = 0; i < 4; i++) {
            float a = x_s[r0 + i][kd];
            ak[i][0] += a * wk4.x; ak[i][1] += a * wk4.y;
            ak[i][2] += a * wk4.z; ak[i][3] += a * wk4.w;
            av[i][0] += a * wv4.x; av[i][1] += a * wv4.y;
            av[i][2] += a * wv4.z; av[i][3] += a * wv4.w;
        }
    }

    int warp = tid >> 5, lane = tid & 31;
    float4 g4 = *(const float4*)&lng[c0];
    float4 b4 = *(const float4*)&lnb[c0];

#pragma unroll
    for (int mat = 0; mat < 2; mat++) {
#pragma unroll
        for (int i = 0; i < 4; i++)
#pragma unroll
            for (int jj = 0; jj < 4; jj++)
                s_o[(r0 + i) * 256 + c0 + jj] = (mat == 0 ? ak[i][jj] : av[i][jj]);
        __syncthreads();
#pragma unroll
        for (int rr = 0; rr < 2; rr++) {
            int row = warp * 2 + rr;
            float s = 0.f, q = 0.f;
#pragma unroll
            for (int jj = 0; jj < 8; jj++) {
                float v = s_o[row * 256 + lane + 32 * jj];
                s += v; q += v * v;
            }
#pragma unroll
            for (int off = 16; off >= 1; off >>= 1) {
                s += __shfl_xor_sync(0xffffffffu, s, off);
                q += __shfl_xor_sync(0xffffffffu, q, off);
            }
            if (lane == 0) {
                float mu = s * (1.f / 256.f);
                smean[row] = mu;
                srstd[row] = rsqrtf(q * (1.f / 256.f) - mu * mu + LN_EPS);
            }
        }
        __syncthreads();
        int h = c0 >> 6, cc = c0 & 63;
        float* dst = (mat == 0) ? g_K : g_V;
#pragma unroll
        for (int i = 0; i < 4; i++) {
            float mu = smean[r0 + i], rs = srstd[r0 + i];
            float v0 = (mat == 0 ? ak[i][0] : av[i][0]);
            float v1 = (mat == 0 ? ak[i][1] : av[i][1]);
            float v2 = (mat == 0 ? ak[i][2] : av[i][2]);
            float v3 = (mat == 0 ? ak[i][3] : av[i][3]);
            float4 o4;
            o4.x = tf32r((v0 - mu) * rs * g4.x + b4.x);
            o4.y = tf32r((v1 - mu) * rs * g4.y + b4.y);
            o4.z = tf32r((v2 - mu) * rs * g4.z + b4.z);
            o4.w = tf32r((v3 - mu) * rs * g4.w + b4.w);
            *(float4*)&dst[((((b * NH_ + h) * K_ + k) * HW_) + pbase + r0 + i) * HD_ + cc] = o4;
        }
        __syncthreads();
    }
}

// ------------------- kernel 4: Q projection + LN + scale (tf32 MMA) ---------
// grid: B*DZ*9 (64 p-rows each), 256 threads (8 warps): warp = (mt 0..3, nh 0..1)
// M=64, N=256, K=128. smem: xk[128][72] + bs[256][33]; s_o[64][260] aliased.
__global__ __launch_bounds__(256) void k_qproj(const float* __restrict__ F3,
                                               const float* __restrict__ lng,
                                               const float* __restrict__ lnb) {
    extern __shared__ float qsm[];
    float* xk = qsm;                  // [128][72]  (k-major x, conflict-free frags)
    float* bs = qsm + 128 * 72;       // [256][33]
    float* s_o = qsm;                 // alias, [64][260]
    __shared__ float smean[64], srstd[64];

    int bid = blockIdx.x;
    int p0 = (bid % 9) * 64;
    int z = (bid / 9) % DZ_;
    int b = bid / (9 * DZ_);

    int tid = threadIdx.x;
    int w = tid >> 5, lane = tid & 31;
    int g = lane >> 2, t = lane & 3;
    int mt = w & 3, nh = w >> 2;

    // load x (F3 is channel-major -> lanes vary p: coalesced LDG, clean STS)
    {
        int r = tid & 63;
        int cb = tid >> 6;
        for (int c = cb; c < C3_; c += 4)
            xk[c * 72 + r] = F3[(b * C3_ + c) * (DZ_ * HW_) + z * HW_ + p0 + r];
    }

    float4 acc[16];
#pragma unroll
    for (int n = 0; n < 16; n++) acc[n] = make_float4(0.f, 0.f, 0.f, 0.f);

    for (int kb = 0; kb < 4; kb++) {
        __syncthreads();
        {
            int kk = tid & 31;
            int n0 = tid >> 5;
            for (int n = n0; n < 256; n += 8)
                bs[n * 33 + kk] = g_WqT[n * C3_ + kb * 32 + kk];
        }
        __syncthreads();
#pragma unroll
        for (int kcl = 0; kcl < 4; kcl++) {
            int krow = kb * 32 + kcl * 8;
            int arow = mt * 16 + g;
            unsigned a0 = __float_as_uint(xk[(krow + t) * 72 + arow]);
            unsigned a1 = __float_as_uint(xk[(krow + t) * 72 + arow + 8]);
            unsigned a2 = __float_as_uint(xk[(krow + t + 4) * 72 + arow]);
            unsigned a3 = __float_as_uint(xk[(krow + t + 4) * 72 + arow + 8]);
#pragma unroll
            for (int n = 0; n < 16; n++) {
                const float* br = &bs[(nh * 128 + n * 8 + g) * 33 + kcl * 8];
                mma_tf32(acc[n], a0, a1, a2, a3,
                         __float_as_uint(br[t]), __float_as_uint(br[t + 4]));
            }
        }
    }
    __syncthreads();

    // stage D to s_o[row][col]
    {
        int rl = mt * 16 + g;
#pragma unroll
        for (int n = 0; n < 16; n++) {
            int col = nh * 128 + n * 8 + 2 * t;
            s_o[rl * 260 + col] = acc[n].x;
            s_o[rl * 260 + col + 1] = acc[n].y;
            s_o[(rl + 8) * 260 + col] = acc[n].z;
            s_o[(rl + 8) * 260 + col + 1] = acc[n].w;
        }
    }
    __syncthreads();

    // LN stats: warp w handles rows w*8 .. w*8+7
#pragma unroll
    for (int rr = 0; rr < 8; rr++) {
        int row = w * 8 + rr;
        float s = 0.f, q = 0.f;
#pragma unroll
        for (int jj = 0; jj < 8; jj++) {
            float v = s_o[row * 260 + lane + 32 * jj];
            s += v; q += v * v;
        }
#pragma unroll
        for (int off = 16; off >= 1; off >>= 1) {
            s += __shfl_xor_sync(0xffffffffu, s, off);
            q += __shfl_xor_sync(0xffffffffu, q, off);
        }
        if (lane == 0) {
            float mu = s * (1.f / 256.f);
            smean[row] = mu;
            srstd[row] = rsqrtf(q * (1.f / 256.f) - mu * mu + LN_EPS);
        }
    }
    __syncthreads();

    // epilogue: LN + scale + tf32 round, coalesced writes
    {
        int cl = (tid & 63) * 4;
        int rb = tid >> 6;
        float4 g4 = *(const float4*)&lng[cl];
        float4 b4 = *(const float4*)&lnb[cl];
        int h = cl >> 6, cc = cl & 63;
        const float qscale = 0.125f;
        long long obase = ((long long)(b * NH_ + h) * DZ_ + z) * HW_;
        for (int r = rb; r < 64; r += 4) {
            float mu = smean[r], rs = srstd[r];
            float v0 = s_o[r * 260 + cl], v1 = s_o[r * 260 + cl + 1];
            float v2 = s_o[r * 260 + cl + 2], v3 = s_o[r * 260 + cl + 3];
            float4 o4;
            o4.x = tf32r(((v0 - mu) * rs * g4.x + b4.x) * qscale);
            o4.y = tf32r(((v1 - mu) * rs * g4.y + b4.y) * qscale);
            o4.z = tf32r(((v2 - mu) * rs * g4.z + b4.z) * qscale);
            o4.w = tf32r(((v3 - mu) * rs * g4.w + b4.w) * qscale);
            *(float4*)&g_Q[(obase + p0 + r) * HD_ + cc] = o4;
        }
    }
}

// ------------------- kernel 5: flash attention (tf32 MMA, reg P) ------------
#define ST 68
__global__ __launch_bounds__(128) void k_attn(const float* __restrict__ lam_p,
                                              const void* __restrict__ D0_p,
                                              const void* __restrict__ slab_p) {
    extern __shared__ float sm[];
    float* Qs = sm;                       // [128][ST]
    float* Ks = sm + 128 * ST;            // [64][ST]
    float* Vs = sm + 192 * ST;            // [64][ST]

    int bid = blockIdx.x;
    int p0 = (bid % 9) * 64;
    int zp = (bid / 9) % (DZ_ / 2);
    int h = (bid / (9 * (DZ_ / 2))) % NH_;
    int b = bid / (9 * (DZ_ / 2) * NH_);
    int z0 = zp * 2;

    int D0 = flex_int(D0_p, 128);
    int slab = flex_int(slab_p, 16);
    float lamv = *lam_p;

    int kkz[2], cloz[2], chiz[2];
#pragma unroll
    for (int i = 0; i < 2; i++) {
        int zz = z0 + i;
        int zq = (int)llrint((double)(D0 - 1) * (double)zz / (double)(DZ_ - 1));
        int kk = zq / slab;
        if (kk < 0) kk = 0;
        if (kk > K_ - 1) kk = K_ - 1;
        kkz[i] = kk;
        cloz[i] = (kk - 1 < 0) ? 0 : kk - 1;
        chiz[i] = (kk + 1 > K_ - 1) ? K_ - 1 : kk + 1;
    }
    int cU_lo = min(cloz[0], cloz[1]);
    int cU_hi = max(chiz[0], chiz[1]);

    int tid = threadIdx.x;
    int w = tid >> 5;
    int lane = tid & 31;
    int g = lane >> 2;
    int t = lane & 3;
    int s0l = (lane & 28) + (t >> 1);
    bool odd = (t & 1);

    int wz = w >> 1;
    int zw = z0 + wz;
    int kk_w = kkz[wz], clo_w = cloz[wz], chi_w = chiz[wz];
    int prow = p0 + (w & 1) * 32;
    int qrow = w * 32;

    {
        long long qb0 = ((((long long)(b * NH_ + h) * DZ_ + z0) * HW_) + p0) * HD_;
#pragma unroll
        for (int it = 0; it < 16; it++) {
            int idx = tid + it * 128;
            int r = idx >> 4, v = (idx & 15) * 4;
            long long src = qb0 + (long long)(r >> 6) * (HW_ * HD_) + (long long)(r & 63) * 64 + v;
            *(float4*)&Qs[r * ST + v] = *(const float4*)&g_Q[src];
        }
    }

    float m00 = -1e30f, m01 = -1e30f, m10 = -1e30f, m11 = -1e30f;
    float l00 = 0.f, l01 = 0.f, l10 = 0.f, l11 = 0.f;
    float4 O0[8], O1[8];
#pragma unroll
    for (int n = 0; n < 8; n++) {
        O0[n] = make_float4(0.f, 0.f, 0.f, 0.f);
        O1[n] = make_float4(0.f, 0.f, 0.f, 0.f);
    }

    for (int c = cU_lo; c <= cU_hi; c++) {
        bool active = (c >= clo_w) && (c <= chi_w);
        float bias = (c == kk_w) ? 0.f : -0.5f;
        long long kb = (((long long)(b * NH_ + h) * K_ + c) * HW_) * HD_;
        const float* topo_c = &g_topo[(b * K_ + c) * HW_];
        for (int pk0 = 0; pk0 < HW_; pk0 += 64) {
            __syncthreads();
#pragma unroll
            for (int it = 0; it < 8; it++) {
                int idx = tid + it * 128;
                int r = idx >> 4, v = (idx & 15) * 4;
                long long off = kb + (long long)(pk0 + r) * 64 + v;
                *(float4*)&Ks[r * ST + v] = *(const float4*)&g_K[off];
                *(float4*)&Vs[r * ST + v] = *(const float4*)&g_V[off];
            }
            __syncthreads();
            if (!active) continue;

            // ---- S = Q*K^T ----
            float4 S0[8], S1[8];
#pragma unroll
            for (int n = 0; n < 8; n++) {
                S0[n] = make_float4(0.f, 0.f, 0.f, 0.f);
                S1[n] = make_float4(0.f, 0.f, 0.f, 0.f);
            }
#pragma unroll
            for (int kc = 0; kc < 8; kc++) {
                const float* qa = &Qs[(qrow + g) * ST + kc * 8];
                unsigned a00 = __float_as_uint(qa[t]);
                unsigned a02 = __float_as_uint(qa[t + 4]);
                unsigned a01 = __float_as_uint(qa[8 * ST + t]);
                unsigned a03 = __float_as_uint(qa[8 * ST + t + 4]);
                unsigned a10 = __float_as_uint(qa[16 * ST + t]);
                unsigned a12 = __float_as_uint(qa[16 * ST + t + 4]);
                unsigned a11 = __float_as_uint(qa[24 * ST + t]);
                unsigned a13 = __float_as_uint(qa[24 * ST + t + 4]);
#pragma unroll
                for (int n = 0; n < 8; n++) {
                    const float* kr = &Ks[(n * 8 + g) * ST + kc * 8];
                    unsigned b0 = __float_as_uint(kr[t]);
                    unsigned b1 = __float_as_uint(kr[t + 4]);
                    mma_tf32(S0[n], a00, a01, a02, a03, b0, b1);
                    mma_tf32(S1[n], a10, a11, a12, a13, b0, b1);
                }
            }

            // ---- bias + diag topo ----
            int rq0 = prow + g;
            int rq1 = prow + 16 + g;
#pragma unroll
            for (int n = 0; n < 8; n++) {
                int j0 = pk0 + n * 8 + 2 * t;
                int j1 = j0 + 1;
                S0[n].x += bias; S0[n].y += bias; S0[n].z += bias; S0[n].w += bias;
                S1[n].x += bias; S1[n].y += bias; S1[n].z += bias; S1[n].w += bias;
                if (rq0 == j0)     S0[n].x += lamv * topo_c[j0];
                if (rq0 == j1)     S0[n].y += lamv * topo_c[j1];
                if (rq0 + 8 == j0) S0[n].z += lamv * topo_c[j0];
                if (rq0 + 8 == j1) S0[n].w += lamv * topo_c[j1];
                if (rq1 == j0)     S1[n].x += lamv * topo_c[j0];
                if (rq1 == j1)     S1[n].y += lamv * topo_c[j1];
                if (rq1 + 8 == j0) S1[n].z += lamv * topo_c[j0];
                if (rq1 + 8 == j1) S1[n].w += lamv * topo_c[j1];
            }

            // ---- online softmax (P kept in S registers) ----
            float mxa = -1e30f, mxb = -1e30f, mxc = -1e30f, mxd = -1e30f;
#pragma unroll
            for (int n = 0; n < 8; n++) {
                mxa = fmaxf(mxa, fmaxf(S0[n].x, S0[n].y));
                mxb = fmaxf(mxb, fmaxf(S0[n].z, S0[n].w));
                mxc = fmaxf(mxc, fmaxf(S1[n].x, S1[n].y));
                mxd = fmaxf(mxd, fmaxf(S1[n].z, S1[n].w));
            }
#pragma unroll
            for (int off = 1; off <= 2; off <<= 1) {
                mxa = fmaxf(mxa, __shfl_xor_sync(0xffffffffu, mxa, off));
                mxb = fmaxf(mxb, __shfl_xor_sync(0xffffffffu, mxb, off));
                mxc = fmaxf(mxc, __shfl_xor_sync(0xffffffffu, mxc, off));
                mxd = fmaxf(mxd, __shfl_xor_sync(0xffffffffu, mxd, off));
            }
            float n00 = fmaxf(m00, mxa), n01 = fmaxf(m01, mxb);
            float n10 = fmaxf(m10, mxc), n11 = fmaxf(m11, mxd);
            float c00 = __expf(m00 - n00), c01 = __expf(m01 - n01);
            float c10 = __expf(m10 - n10), c11 = __expf(m11 - n11);
            float r00 = 0.f, r01 = 0.f, r10 = 0.f, r11 = 0.f;
#pragma unroll
            for (int n = 0; n < 8; n++) {
                S0[n].x = __expf(S0[n].x - n00); S0[n].y = __expf(S0[n].y - n00);
                S0[n].z = __expf(S0[n].z - n01); S0[n].w = __expf(S0[n].w - n01);
                S1[n].x = __expf(S1[n].x - n10); S1[n].y = __expf(S1[n].y - n10);
                S1[n].z = __expf(S1[n].z - n11); S1[n].w = __expf(S1[n].w - n11);
                r00 += S0[n].x + S0[n].y; r01 += S0[n].z + S0[n].w;
                r10 += S1[n].x + S1[n].y; r11 += S1[n].z + S1[n].w;
            }
#pragma unroll
            for (int off = 1; off <= 2; off <<= 1) {
                r00 += __shfl_xor_sync(0xffffffffu, r00, off);
                r01 += __shfl_xor_sync(0xffffffffu, r01, off);
                r10 += __shfl_xor_sync(0xffffffffu, r10, off);
                r11 += __shfl_xor_sync(0xffffffffu, r11, off);
            }
            l00 = l00 * c00 + r00; l01 = l01 * c01 + r01;
            l10 = l10 * c10 + r10; l11 = l11 * c11 + r11;
            m00 = n00; m01 = n01; m10 = n10; m11 = n11;
#pragma unroll
            for (int n = 0; n < 8; n++) {
                O0[n].x *= c00; O0[n].y *= c00; O0[n].z *= c01; O0[n].w *= c01;
                O1[n].x *= c10; O1[n].y *= c10; O1[n].z *= c11; O1[n].w *= c11;
            }

            // ---- O += P*V (P re-fragmented via shuffles) ----
#pragma unroll
            for (int kc = 0; kc < 8; kc++) {
                unsigned a00, a01, a02, a03, a10, a11, a12, a13;
                pfrag(S0[kc], s0l, odd, a00, a01, a02, a03);
                pfrag(S1[kc], s0l, odd, a10, a11, a12, a13);
#pragma unroll
                for (int n = 0; n < 8; n++) {
                    const float* vr = &Vs[(kc * 8 + t) * ST + n * 8 + g];
                    unsigned b0 = __float_as_uint(vr[0]);
                    unsigned b1 = __float_as_uint(vr[4 * ST]);
                    mma_tf32(O0[n], a00, a01, a02, a03, b0, b1);
                    mma_tf32(O1[n], a10, a11, a12, a13, b0, b1);
                }
            }
        }
    }

    float i00 = 1.f / l00, i01 = 1.f / l01, i10 = 1.f / l10, i11 = 1.f / l11;
    long long ob = ((long long)(b * DZ_ + zw) * HW_) * E_ + h * HD_;
    int rq0 = prow + g, rq1 = prow + 16 + g;
#pragma unroll
    for (int n = 0; n < 8; n++) {
        int col = n * 8 + 2 * t;
        *(float2*)&g_O[ob + (long long)rq0 * E_ + col] = make_float2(O0[n].x * i00, O0[n].y * i00);
        *(float2*)&g_O[ob + (long long)(rq0 + 8) * E_ + col] = make_float2(O0[n].z * i01, O0[n].w * i01);
        *(float2*)&g_O[ob + (long long)rq1 * E_ + col] = make_float2(O1[n].x * i10, O1[n].y * i10);
        *(float2*)&g_O[ob + (long long)(rq1 + 8) * E_ + col] = make_float2(O1[n].z * i11, O1[n].w * i11);
    }
}

// ------------------- kernel 6: output projection + residual (tf32 MMA) ------
// grid: B*DZ*9 (64 p-rows each), 256 threads. M=64, N=128, K=256.
// A loaded directly from gmem (g_O row-major); B (WpT) smem-tiled.
__global__ __launch_bounds__(256) void k_oproj(const float* __restrict__ F3,
                                               float* __restrict__ out) {
    extern __shared__ float osm[];
    float* bs = osm;                  // [128][33] = 4224 floats
    float* s_o = osm + 128 * 33;      // [128 cols][68 rows] = 8704 floats
    int bid = blockIdx.x;
    int p0 = (bid % 9) * 64;
    int z = (bid / 9) % DZ_;
    int b = bid / (9 * DZ_);

    int tid = threadIdx.x;
    int w = tid >> 5, lane = tid & 31;
    int g = lane >> 2, t = lane & 3;
    int mt = w & 3, nh = w >> 2;

    int rowl = (b * DZ_ + z) * HW_ + p0 + mt * 16 + g;
    const float* Al = &g_O[(long long)rowl * E_];
    const float* Ah = Al + 8LL * E_;

    float4 acc[8];
#pragma unroll
    for (int n = 0; n < 8; n++) acc[n] = make_float4(0.f, 0.f, 0.f, 0.f);

    for (int kb = 0; kb < 8; kb++) {
        __syncthreads();
        {
            int kk = tid & 31;
            int n0 = tid >> 5;
            for (int n = n0; n < 128; n += 8)
                bs[n * 33 + kk] = g_WpT[n * E_ + kb * 32 + kk];
        }
        __syncthreads();
#pragma unroll
        for (int kcl = 0; kcl < 4; kcl++) {
            int kcol = kb * 32 + kcl * 8;
            unsigned a0 = __float_as_uint(Al[kcol + t]);
            unsigned a1 = __float_as_uint(Ah[kcol + t]);
            unsigned a2 = __float_as_uint(Al[kcol + t + 4]);
            unsigned a3 = __float_as_uint(Ah[kcol + t + 4]);
#pragma unroll
            for (int n = 0; n < 8; n++) {
                const float* br = &bs[(nh * 64 + n * 8 + g) * 33 + kcl * 8];
                mma_tf32(acc[n], a0, a1, a2, a3,
                         __float_as_uint(br[t]), __float_as_uint(br[t + 4]));
            }
        }
    }
    __syncthreads();

    // stage transposed: s_o[col][row]
    {
        int rl = mt * 16 + g;
#pragma unroll
        for (int n = 0; n < 8; n++) {
            int col = nh * 64 + n * 8 + 2 * t;
            s_o[col * 68 + rl] = acc[n].x;
            s_o[(col + 1) * 68 + rl] = acc[n].y;
            s_o[col * 68 + rl + 8] = acc[n].z;
            s_o[(col + 1) * 68 + rl + 8] = acc[n].w;
        }
    }
    __syncthreads();

    // coalesced write (out fast dim is p) + residual
    {
        int r = tid & 63;
        int cb = tid >> 6;
        for (int c = cb; c < C3_; c += 4) {
            long long oi = (long long)(b * C3_ + c) * (DZ_ * HW_) + z * HW_ + p0 + r;
            out[oi] = F3[oi] + s_o[c * 68 + r];
        }
    }
}

// ----------------------------------- launch ---------------------------------
extern "C" void kernel_launch(void* const* d_in, const int* in_sizes, int n_in,
                              void* d_out, int out_size) {
    const float* F3  = (const float*)d_in[0];
    const float* F2  = (const float*)d_in[1];
    const float* Wq  = (const float*)d_in[2];
    const float* Wk  = (const float*)d_in[3];
    const float* Wv  = (const float*)d_in[4];
    const float* Wp  = (const float*)d_in[5];
    const float* lnqg = (const float*)d_in[6];
    const float* lnqb = (const float*)d_in[7];
    const float* lnkg = (const float*)d_in[8];
    const float* lnkb = (const float*)d_in[9];
    const float* w1   = (const float*)d_in[10];
    const float* bng  = (const float*)d_in[11];
    const float* bnb  = (const float*)d_in[12];
    const float* w2   = (const float*)d_in[13];
    const float* w2b  = (const float*)d_in[14];
    const float* lam  = (const float*)d_in[15];
    const void*  D0p  = d_in[16];
    const void*  slabp = d_in[17];
    float* out = (float*)d_out;

    int qproj_smem = (128 * 72 + 256 * 33) * (int)sizeof(float);   // 70656
    int attn_smem  = 256 * ST * (int)sizeof(float);                // 69632
    int oproj_smem = (128 * 33 + 128 * 68) * (int)sizeof(float);   // 51712
    static int cfg_done = 0;
    if (!cfg_done) {
        cudaFuncSetAttribute(k_qproj, cudaFuncAttributeMaxDynamicSharedMemorySize, qproj_smem);
        cudaFuncSetAttribute(k_attn, cudaFuncAttributeMaxDynamicSharedMemorySize, attn_smem);
        cudaFuncSetAttribute(k_oproj, cudaFuncAttributeMaxDynamicSharedMemorySize, oproj_smem);
        cfg_done = 1;
    }

    k_wtrans<<<(TOPO_ * C2_ * 9 + 255) / 256, 256>>>(w1);
    k_wprep<<<(C3_ * E_ + 255) / 256, 256>>>(Wq, Wp);
    k_conv1<<<dim3(6, B_ * K_), 384>>>(F2, bng, bnb);
    k_topo<<<B_ * K_, 192>>>(w2, w2b);
    k_kvproj<<<B_ * K_ * (HW_ / 16), 256>>>(F2, Wk, Wv, lnkg, lnkb);
    k_qproj<<<B_ * DZ_ * 9, 256, qproj_smem>>>(F3, lnqg, lnqb);
    k_attn<<<B_ * NH_ * (DZ_ / 2) * 9, 128, attn_smem>>>(lam, D0p, slabp);
    k_oproj<<<B_ * DZ_ * 9, 256, oproj_smem>>>(F3, out);
}

// round 6
// speedup vs baseline: 4.2492x; 1.3478x over previous
#include <cuda_runtime.h>
#include <cuda_bf16.h>
#include <math.h>

#define B_ 2
#define C3_ 128
#define DZ_ 32
#define HW_ 576
#define C2_ 96
#define K_ 8
#define E_ 256
#define NH_ 4
#define HD_ 64
#define TOPO_ 64
#define LN_EPS 1e-5f

// ------------------------- device scratch (no allocation) -------------------
__device__ float g_w1t[C2_ * 9 * TOPO_];
__device__ float g_h[B_ * K_ * HW_ * TOPO_];
__device__ float g_topo[B_ * K_ * HW_];
__device__ __nv_bfloat16 g_Q[B_ * NH_ * DZ_ * HW_ * HD_];   // (b,h,z,p,d) pre-scaled 1/8
__device__ __nv_bfloat16 g_K[B_ * NH_ * K_ * HW_ * HD_];    // (b,h,c,p,d)
__device__ __nv_bfloat16 g_Vt[B_ * NH_ * K_ * HD_ * HW_];   // (b,h,c,d,p)  TRANSPOSED
__device__ float g_O[B_ * DZ_ * HW_ * E_];
__device__ float g_WqT[E_ * C3_];
__device__ float g_WpT[C3_ * E_];
__device__ float g_WkT[E_ * C2_];
__device__ float g_WvT[E_ * C2_];

__device__ __forceinline__ int flex_int(const void* p, int dflt) {
    int v = *(const int*)p;
    if (v >= 1 && v <= 1000000) return v;
    float f = *(const float*)p;
    if (f >= 1.f && f <= 1000000.f) return (int)f;
    return dflt;
}

__device__ __forceinline__ unsigned pk2(float lo, float hi) {
    unsigned r;
    asm("cvt.rn.bf16x2.f32 %0, %1, %2;" : "=r"(r) : "f"(hi), "f"(lo));
    return r;
}

__device__ __forceinline__ void mma_tf32(float4& d,
                                         unsigned a0, unsigned a1, unsigned a2, unsigned a3,
                                         unsigned b0, unsigned b1) {
    asm volatile(
        "mma.sync.aligned.m16n8k8.row.col.f32.tf32.tf32.f32 "
        "{%0,%1,%2,%3}, {%4,%5,%6,%7}, {%8,%9}, {%0,%1,%2,%3};"
        : "+f"(d.x), "+f"(d.y), "+f"(d.z), "+f"(d.w)
        : "r"(a0), "r"(a1), "r"(a2), "r"(a3), "r"(b0), "r"(b1));
}

__device__ __forceinline__ void mma_bf16(float4& d,
                                         unsigned a0, unsigned a1, unsigned a2, unsigned a3,
                                         unsigned b0, unsigned b1) {
    asm volatile(
        "mma.sync.aligned.m16n8k16.row.col.f32.bf16.bf16.f32 "
        "{%0,%1,%2,%3}, {%4,%5,%6,%7}, {%8,%9}, {%0,%1,%2,%3};"
        : "+f"(d.x), "+f"(d.y), "+f"(d.z), "+f"(d.w)
        : "r"(a0), "r"(a1), "r"(a2), "r"(a3), "r"(b0), "r"(b1));
}

// ------------------------- kernel 0a: transpose conv1 weights ---------------
__global__ void k_wtrans(const float* __restrict__ w1) {
    int i = blockIdx.x * 256 + threadIdx.x;
    if (i < TOPO_ * C2_ * 9) {
        int o = i / (C2_ * 9);
        int r = i % (C2_ * 9);
        int c = r / 9, tap = r % 9;
        g_w1t[(c * 9 + tap) * TOPO_ + o] = w1[i];
    }
}

// ------------------------- kernel 0b: transpose Wq / Wp / Wk / Wv -----------
__global__ void k_wprep(const float* __restrict__ Wq, const float* __restrict__ Wp,
                        const float* __restrict__ Wk, const float* __restrict__ Wv) {
    int i = blockIdx.x * 256 + threadIdx.x;
    if (i < C3_ * E_) {
        int e = i / C3_, c = i % C3_;
        g_WqT[i] = Wq[c * E_ + e];
        g_WpT[c * E_ + e] = Wp[i];
    }
    if (i < C2_ * E_) {
        int e = i / C2_, c = i % C2_;
        g_WkT[i] = Wk[c * E_ + e];
        g_WvT[i] = Wv[c * E_ + e];
    }
}

// ------------------- kernel 1: conv1 3x3 (96->64) + BN + ReLU ---------------
__global__ __launch_bounds__(384) void k_conv1(const float* __restrict__ F2,
                                               const float* __restrict__ bng,
                                               const float* __restrict__ bnb) {
    __shared__ float in_s[16][6][26];
    __shared__ float w_s[16 * 9 * 64];
    int bk = blockIdx.y;
    int b = bk >> 3, k = bk & 7;
    int y0 = blockIdx.x * 4;
    int tid = threadIdx.x;
    int ig = tid >> 4;
    int j = tid & 15;
    int pl = ig * 4;
    int yrel = pl / 24;
    int x0 = pl % 24;
    int o0 = j * 4;
    float acc[4][4];
#pragma unroll
    for (int u = 0; u < 4; u++)
#pragma unroll
        for (int v = 0; v < 4; v++) acc[u][v] = 0.f;

    for (int c0 = 0; c0 < C2_; c0 += 16) {
        __syncthreads();
        for (int idx = tid; idx < 16 * 6 * 26; idx += 384) {
            int cc = idx / 156, rem = idx % 156;
            int yy = rem / 26, xx = rem % 26;
            int y = y0 - 1 + yy, x = xx - 1;
            float v = 0.f;
            if ((unsigned)y < 24u && (unsigned)x < 24u)
                v = F2[((b * C2_ + c0 + cc) * HW_ + y * 24 + x) * K_ + k];
            in_s[cc][yy][xx] = v;
        }
        for (int idx = tid; idx < 16 * 9 * 64; idx += 384)
            w_s[idx] = g_w1t[c0 * 9 * 64 + idx];
        __syncthreads();
        for (int cc = 0; cc < 16; cc++) {
#pragma unroll
            for (int dy = 0; dy < 3; dy++) {
                float rv[6];
#pragma unroll
                for (int u = 0; u < 6; u++) rv[u] = in_s[cc][yrel + dy][x0 + u];
#pragma unroll
                for (int dx = 0; dx < 3; dx++) {
                    float4 w4 = *(const float4*)&w_s[(cc * 9 + dy * 3 + dx) * 64 + o0];
#pragma unroll
                    for (int u = 0; u < 4; u++) {
                        float a = rv[u + dx];
                        acc[u][0] += a * w4.x;
                        acc[u][1] += a * w4.y;
                        acc[u][2] += a * w4.z;
                        acc[u][3] += a * w4.w;
                    }
                }
            }
        }
    }
    float invs = rsqrtf(1.f + LN_EPS);
    float s0 = bng[o0] * invs, s1 = bng[o0 + 1] * invs;
    float s2 = bng[o0 + 2] * invs, s3 = bng[o0 + 3] * invs;
    float b0 = bnb[o0], b1 = bnb[o0 + 1], b2 = bnb[o0 + 2], b3 = bnb[o0 + 3];
#pragma unroll
    for (int u = 0; u < 4; u++) {
        int p = (y0 + yrel) * 24 + x0 + u;
        float4 hv;
        hv.x = fmaxf(acc[u][0] * s0 + b0, 0.f);
        hv.y = fmaxf(acc[u][1] * s1 + b1, 0.f);
        hv.z = fmaxf(acc[u][2] * s2 + b2, 0.f);
        hv.w = fmaxf(acc[u][3] * s3 + b3, 0.f);
        *(float4*)&g_h[(bk * HW_ + p) * TOPO_ + o0] = hv;
    }
}

// ------------------- kernel 2: conv2 1x1 + neighbor-sum -> topo -------------
__global__ __launch_bounds__(192) void k_topo(const float* __restrict__ w2,
                                              const float* __restrict__ w2b) {
    __shared__ float sp[HW_];
    __shared__ float wsh[64];
    int bk = blockIdx.x;
    int tid = threadIdx.x;
    if (tid < 64) wsh[tid] = w2[tid];
    __syncthreads();
    for (int p = tid; p < HW_; p += 192) {
        const float* hp = &g_h[(bk * HW_ + p) * TOPO_];
        float s = w2b[0];
#pragma unroll
        for (int o = 0; o < 64; o += 4) {
            float4 hv = *(const float4*)&hp[o];
            s += hv.x * wsh[o] + hv.y * wsh[o + 1] + hv.z * wsh[o + 2] + hv.w * wsh[o + 3];
        }
        sp[p] = s;
    }
    __syncthreads();
    for (int p = tid; p < HW_; p += 192) {
        int y = p / 24, x = p % 24;
        float s = 0.f;
#pragma unroll
        for (int dy = -1; dy <= 1; dy++)
#pragma unroll
            for (int dx = -1; dx <= 1; dx++) {
                if (dy == 0 && dx == 0) continue;
                int yy = y + dy, xx = x + dx;
                if ((unsigned)yy < 24u && (unsigned)xx < 24u) s += sp[yy * 24 + xx];
            }
        g_topo[bk * HW_ + p] = sp[p] + 0.5f * s;
    }
}

// ------------------- kernel 3: K/V projection + LN (tf32 MMA, bf16 out) -----
// grid: B*K*9 (64 p-rows each), 256 threads (8 warps): warp = (mt 0..3, nh 0..1)
// M=64, K=96. Two N=256 passes: mat0 -> g_K, mat1 -> g_Vt (transposed).
__global__ __launch_bounds__(256) void k_kvproj(const float* __restrict__ F2,
                                                const float* __restrict__ lng,
                                                const float* __restrict__ lnb) {
    extern __shared__ float ksm[];
    float* xk = ksm;                  // [96][72]
    float* bs = ksm + 96 * 72;        // [256][33]
    float* s_o = ksm + 96 * 72;       // alias on bs region, [64][260]
    __shared__ float smean[64], srstd[64];

    int bid = blockIdx.x;
    int p0 = (bid % 9) * 64;
    int k = (bid / 9) % K_;
    int b = bid / (9 * K_);

    int tid = threadIdx.x;
    int w = tid >> 5, lane = tid & 31;
    int g = lane >> 2, t = lane & 3;
    int mt = w & 3, nh = w >> 2;

    {
        int r = tid & 63;
        int cb = tid >> 6;
        for (int c = cb; c < C2_; c += 4)
            xk[c * 72 + r] = F2[((b * C2_ + c) * HW_ + p0 + r) * K_ + k];
    }

    for (int mat = 0; mat < 2; mat++) {
        const float* WT = mat == 0 ? g_WkT : g_WvT;
        float4 acc[16];
#pragma unroll
        for (int n = 0; n < 16; n++) acc[n] = make_float4(0.f, 0.f, 0.f, 0.f);

        for (int kb = 0; kb < 3; kb++) {
            __syncthreads();
            {
                int kk = tid & 31;
                int n0 = tid >> 5;
                for (int n = n0; n < 256; n += 8)
                    bs[n * 33 + kk] = WT[n * C2_ + kb * 32 + kk];
            }
            __syncthreads();
#pragma unroll
            for (int kcl = 0; kcl < 4; kcl++) {
                int krow = kb * 32 + kcl * 8;
                int arow = mt * 16 + g;
                unsigned a0 = __float_as_uint(xk[(krow + t) * 72 + arow]);
                unsigned a1 = __float_as_uint(xk[(krow + t) * 72 + arow + 8]);
                unsigned a2 = __float_as_uint(xk[(krow + t + 4) * 72 + arow]);
                unsigned a3 = __float_as_uint(xk[(krow + t + 4) * 72 + arow + 8]);
#pragma unroll
                for (int n = 0; n < 16; n++) {
                    const float* br = &bs[(nh * 128 + n * 8 + g) * 33 + kcl * 8];
                    mma_tf32(acc[n], a0, a1, a2, a3,
                             __float_as_uint(br[t]), __float_as_uint(br[t + 4]));
                }
            }
        }
        __syncthreads();
        {
            int rl = mt * 16 + g;
#pragma unroll
            for (int n = 0; n < 16; n++) {
                int col = nh * 128 + n * 8 + 2 * t;
                s_o[rl * 260 + col] = acc[n].x;
                s_o[rl * 260 + col + 1] = acc[n].y;
                s_o[(rl + 8) * 260 + col] = acc[n].z;
                s_o[(rl + 8) * 260 + col + 1] = acc[n].w;
            }
        }
        __syncthreads();
#pragma unroll
        for (int rr = 0; rr < 8; rr++) {
            int row = w * 8 + rr;
            float s = 0.f, q = 0.f;
#pragma unroll
            for (int jj = 0; jj < 8; jj++) {
                float v = s_o[row * 260 + lane + 32 * jj];
                s += v; q += v * v;
            }
#pragma unroll
            for (int off = 16; off >= 1; off >>= 1) {
                s += __shfl_xor_sync(0xffffffffu, s, off);
                q += __shfl_xor_sync(0xffffffffu, q, off);
            }
            if (lane == 0) {
                float mu = s * (1.f / 256.f);
                smean[row] = mu;
                srstd[row] = rsqrtf(q * (1.f / 256.f) - mu * mu + LN_EPS);
            }
        }
        __syncthreads();

        if (mat == 0) {
            // K: layout (b,h,c,p,d), 8B stores
            int cl = (tid & 63) * 4;
            int rb = tid >> 6;
            float4 g4 = *(const float4*)&lng[cl];
            float4 b4 = *(const float4*)&lnb[cl];
            int h = cl >> 6, cc = cl & 63;
            long long obase = ((long long)(b * NH_ + h) * K_ + k) * HW_;
            for (int r = rb; r < 64; r += 4) {
                float mu = smean[r], rs = srstd[r];
                float v0 = (s_o[r * 260 + cl] - mu) * rs * g4.x + b4.x;
                float v1 = (s_o[r * 260 + cl + 1] - mu) * rs * g4.y + b4.y;
                float v2 = (s_o[r * 260 + cl + 2] - mu) * rs * g4.z + b4.z;
                float v3 = (s_o[r * 260 + cl + 3] - mu) * rs * g4.w + b4.w;
                uint2 u = make_uint2(pk2(v0, v1), pk2(v2, v3));
                *(uint2*)&g_K[(obase + p0 + r) * HD_ + cc] = u;
            }
        } else {
            // V: transposed layout (b,h,c,d,p)
            int e = tid;                        // 0..255
            float ge = lng[e], be = lnb[e];
            int h = e >> 6, d = e & 63;
            long long vb = (((long long)(b * NH_ + h) * K_ + k) * HD_ + d) * HW_ + p0;
#pragma unroll
            for (int rb2 = 0; rb2 < 16; rb2++) {
                int r = rb2 * 4;
                float v0 = (s_o[r * 260 + e] - smean[r]) * srstd[r] * ge + be;
                float v1 = (s_o[(r + 1) * 260 + e] - smean[r + 1]) * srstd[r + 1] * ge + be;
                float v2 = (s_o[(r + 2) * 260 + e] - smean[r + 2]) * srstd[r + 2] * ge + be;
                float v3 = (s_o[(r + 3) * 260 + e] - smean[r + 3]) * srstd[r + 3] * ge + be;
                uint2 u = make_uint2(pk2(v0, v1), pk2(v2, v3));
                *(uint2*)&g_Vt[vb + r] = u;
            }
        }
    }
}

// ------------------- kernel 4: Q projection + LN + scale (tf32 MMA) ---------
__global__ __launch_bounds__(256) void k_qproj(const float* __restrict__ F3,
                                               const float* __restrict__ lng,
                                               const float* __restrict__ lnb) {
    extern __shared__ float qsm[];
    float* xk = qsm;                  // [128][72]
    float* bs = qsm + 128 * 72;       // [256][33]
    float* s_o = qsm;                 // alias, [64][260]
    __shared__ float smean[64], srstd[64];

    int bid = blockIdx.x;
    int p0 = (bid % 9) * 64;
    int z = (bid / 9) % DZ_;
    int b = bid / (9 * DZ_);

    int tid = threadIdx.x;
    int w = tid >> 5, lane = tid & 31;
    int g = lane >> 2, t = lane & 3;
    int mt = w & 3, nh = w >> 2;

    {
        int r = tid & 63;
        int cb = tid >> 6;
        for (int c = cb; c < C3_; c += 4)
            xk[c * 72 + r] = F3[(b * C3_ + c) * (DZ_ * HW_) + z * HW_ + p0 + r];
    }

    float4 acc[16];
#pragma unroll
    for (int n = 0; n < 16; n++) acc[n] = make_float4(0.f, 0.f, 0.f, 0.f);

    for (int kb = 0; kb < 4; kb++) {
        __syncthreads();
        {
            int kk = tid & 31;
            int n0 = tid >> 5;
            for (int n = n0; n < 256; n += 8)
                bs[n * 33 + kk] = g_WqT[n * C3_ + kb * 32 + kk];
        }
        __syncthreads();
#pragma unroll
        for (int kcl = 0; kcl < 4; kcl++) {
            int krow = kb * 32 + kcl * 8;
            int arow = mt * 16 + g;
            unsigned a0 = __float_as_uint(xk[(krow + t) * 72 + arow]);
            unsigned a1 = __float_as_uint(xk[(krow + t) * 72 + arow + 8]);
            unsigned a2 = __float_as_uint(xk[(krow + t + 4) * 72 + arow]);
            unsigned a3 = __float_as_uint(xk[(krow + t + 4) * 72 + arow + 8]);
#pragma unroll
            for (int n = 0; n < 16; n++) {
                const float* br = &bs[(nh * 128 + n * 8 + g) * 33 + kcl * 8];
                mma_tf32(acc[n], a0, a1, a2, a3,
                         __float_as_uint(br[t]), __float_as_uint(br[t + 4]));
            }
        }
    }
    __syncthreads();

    {
        int rl = mt * 16 + g;
#pragma unroll
        for (int n = 0; n < 16; n++) {
            int col = nh * 128 + n * 8 + 2 * t;
            s_o[rl * 260 + col] = acc[n].x;
            s_o[rl * 260 + col + 1] = acc[n].y;
            s_o[(rl + 8) * 260 + col] = acc[n].z;
            s_o[(rl + 8) * 260 + col + 1] = acc[n].w;
        }
    }
    __syncthreads();

#pragma unroll
    for (int rr = 0; rr < 8; rr++) {
        int row = w * 8 + rr;
        float s = 0.f, q = 0.f;
#pragma unroll
        for (int jj = 0; jj < 8; jj++) {
            float v = s_o[row * 260 + lane + 32 * jj];
            s += v; q += v * v;
        }
#pragma unroll
        for (int off = 16; off >= 1; off >>= 1) {
            s += __shfl_xor_sync(0xffffffffu, s, off);
            q += __shfl_xor_sync(0xffffffffu, q, off);
        }
        if (lane == 0) {
            float mu = s * (1.f / 256.f);
            smean[row] = mu;
            srstd[row] = rsqrtf(q * (1.f / 256.f) - mu * mu + LN_EPS);
        }
    }
    __syncthreads();

    {
        int cl = (tid & 63) * 4;
        int rb = tid >> 6;
        float4 g4 = *(const float4*)&lng[cl];
        float4 b4 = *(const float4*)&lnb[cl];
        int h = cl >> 6, cc = cl & 63;
        const float qscale = 0.125f;
        long long obase = ((long long)(b * NH_ + h) * DZ_ + z) * HW_;
        for (int r = rb; r < 64; r += 4) {
            float mu = smean[r], rs = srstd[r];
            float v0 = ((s_o[r * 260 + cl] - mu) * rs * g4.x + b4.x) * qscale;
            float v1 = ((s_o[r * 260 + cl + 1] - mu) * rs * g4.y + b4.y) * qscale;
            float v2 = ((s_o[r * 260 + cl + 2] - mu) * rs * g4.z + b4.z) * qscale;
            float v3 = ((s_o[r * 260 + cl + 3] - mu) * rs * g4.w + b4.w) * qscale;
            uint2 u = make_uint2(pk2(v0, v1), pk2(v2, v3));
            *(uint2*)&g_Q[(obase + p0 + r) * HD_ + cc] = u;
        }
    }
}

// ------------------- kernel 5: flash attention (bf16 MMA) -------------------
// grid: B*NH*(DZ/2)*9 blocks, 128 threads. smem tiles stride 72 bf16 (36 words:
// all fragment b32 loads hit distinct banks).
#define BST 72
__global__ __launch_bounds__(128) void k_attn(const float* __restrict__ lam_p,
                                              const void* __restrict__ D0_p,
                                              const void* __restrict__ slab_p) {
    extern __shared__ __nv_bfloat16 bsm[];
    __nv_bfloat16* Qs = bsm;                   // [128][BST]
    __nv_bfloat16* Ks = bsm + 128 * BST;       // [64][BST]  (key, dim)
    __nv_bfloat16* Vs = bsm + 192 * BST;       // [64][BST]  (dim, key)

    int bid = blockIdx.x;
    int p0 = (bid % 9) * 64;
    int zp = (bid / 9) % (DZ_ / 2);
    int h = (bid / (9 * (DZ_ / 2))) % NH_;
    int b = bid / (9 * (DZ_ / 2) * NH_);
    int z0 = zp * 2;

    int D0 = flex_int(D0_p, 128);
    int slab = flex_int(slab_p, 16);
    float lamv = *lam_p;

    int kkz[2], cloz[2], chiz[2];
#pragma unroll
    for (int i = 0; i < 2; i++) {
        int zz = z0 + i;
        int zq = (int)llrint((double)(D0 - 1) * (double)zz / (double)(DZ_ - 1));
        int kk = zq / slab;
        if (kk < 0) kk = 0;
        if (kk > K_ - 1) kk = K_ - 1;
        kkz[i] = kk;
        cloz[i] = (kk - 1 < 0) ? 0 : kk - 1;
        chiz[i] = (kk + 1 > K_ - 1) ? K_ - 1 : kk + 1;
    }
    int cU_lo = min(cloz[0], cloz[1]);
    int cU_hi = max(chiz[0], chiz[1]);

    int tid = threadIdx.x;
    int w = tid >> 5;
    int lane = tid & 31;
    int g = lane >> 2;
    int t = lane & 3;

    int wz = w >> 1;
    int zw = z0 + wz;
    int kk_w = kkz[wz], clo_w = cloz[wz], chi_w = chiz[wz];
    int prow = p0 + (w & 1) * 32;
    int qrow = w * 32;

    // load Q: 128 rows x 64 bf16 (8 uint4 per row)
    {
        long long qb0 = ((((long long)(b * NH_ + h) * DZ_ + z0) * HW_) + p0) * HD_;
#pragma unroll
        for (int it = 0; it < 8; it++) {
            int idx = tid + it * 128;
            int r = idx >> 3, v = (idx & 7) * 8;
            long long src = qb0 + (long long)(r >> 6) * (HW_ * HD_) + (long long)(r & 63) * 64 + v;
            *(uint4*)&Qs[r * BST + v] = *(const uint4*)&g_Q[src];
        }
    }

    float m00 = -1e30f, m01 = -1e30f, m10 = -1e30f, m11 = -1e30f;
    float l00 = 0.f, l01 = 0.f, l10 = 0.f, l11 = 0.f;
    float4 O0[8], O1[8];
#pragma unroll
    for (int n = 0; n < 8; n++) {
        O0[n] = make_float4(0.f, 0.f, 0.f, 0.f);
        O1[n] = make_float4(0.f, 0.f, 0.f, 0.f);
    }

    for (int c = cU_lo; c <= cU_hi; c++) {
        bool active = (c >= clo_w) && (c <= chi_w);
        float bias = (c == kk_w) ? 0.f : -0.5f;
        long long kb = (((long long)(b * NH_ + h) * K_ + c) * HW_) * HD_;
        long long vb = (((long long)(b * NH_ + h) * K_ + c) * HD_) * HW_;
        const float* topo_c = &g_topo[(b * K_ + c) * HW_];
        for (int pk0 = 0; pk0 < HW_; pk0 += 64) {
            __syncthreads();
#pragma unroll
            for (int it = 0; it < 4; it++) {
                int idx = tid + it * 128;
                int r = idx >> 3, v = (idx & 7) * 8;
                *(uint4*)&Ks[r * BST + v] = *(const uint4*)&g_K[kb + (long long)(pk0 + r) * 64 + v];
                *(uint4*)&Vs[r * BST + v] = *(const uint4*)&g_Vt[vb + (long long)r * HW_ + pk0 + v];
            }
            __syncthreads();
            if (!active) continue;

            // ---- S = Q*K^T (bf16 m16n8k16) ----
            float4 S0[8], S1[8];
#pragma unroll
            for (int n = 0; n < 8; n++) {
                S0[n] = make_float4(0.f, 0.f, 0.f, 0.f);
                S1[n] = make_float4(0.f, 0.f, 0.f, 0.f);
            }
#pragma unroll
            for (int kc = 0; kc < 4; kc++) {
                int kc16 = kc * 16;
                const __nv_bfloat16* qa = &Qs[(qrow + g) * BST + kc16];
                unsigned a00 = *(const unsigned*)&qa[2 * t];
                unsigned a01 = *(const unsigned*)&qa[8 * BST + 2 * t];
                unsigned a02 = *(const unsigned*)&qa[2 * t + 8];
                unsigned a03 = *(const unsigned*)&qa[8 * BST + 2 * t + 8];
                unsigned a10 = *(const unsigned*)&qa[16 * BST + 2 * t];
                unsigned a11 = *(const unsigned*)&qa[24 * BST + 2 * t];
                unsigned a12 = *(const unsigned*)&qa[16 * BST + 2 * t + 8];
                unsigned a13 = *(const unsigned*)&qa[24 * BST + 2 * t + 8];
#pragma unroll
                for (int n = 0; n < 8; n++) {
                    const __nv_bfloat16* kr = &Ks[(n * 8 + g) * BST + kc16];
                    unsigned b0 = *(const unsigned*)&kr[2 * t];
                    unsigned b1 = *(const unsigned*)&kr[2 * t + 8];
                    mma_bf16(S0[n], a00, a01, a02, a03, b0, b1);
                    mma_bf16(S1[n], a10, a11, a12, a13, b0, b1);
                }
            }

            // ---- bias + diag topo ----
            int rq0 = prow + g;
            int rq1 = prow + 16 + g;
#pragma unroll
            for (int n = 0; n < 8; n++) {
                int j0 = pk0 + n * 8 + 2 * t;
                int j1 = j0 + 1;
                S0[n].x += bias; S0[n].y += bias; S0[n].z += bias; S0[n].w += bias;
                S1[n].x += bias; S1[n].y += bias; S1[n].z += bias; S1[n].w += bias;
                if (rq0 == j0)     S0[n].x += lamv * topo_c[j0];
                if (rq0 == j1)     S0[n].y += lamv * topo_c[j1];
                if (rq0 + 8 == j0) S0[n].z += lamv * topo_c[j0];
                if (rq0 + 8 == j1) S0[n].w += lamv * topo_c[j1];
                if (rq1 == j0)     S1[n].x += lamv * topo_c[j0];
                if (rq1 == j1)     S1[n].y += lamv * topo_c[j1];
                if (rq1 + 8 == j0) S1[n].z += lamv * topo_c[j0];
                if (rq1 + 8 == j1) S1[n].w += lamv * topo_c[j1];
            }

            // ---- online softmax ----
            float mxa = -1e30f, mxb = -1e30f, mxc = -1e30f, mxd = -1e30f;
#pragma unroll
            for (int n = 0; n < 8; n++) {
                mxa = fmaxf(mxa, fmaxf(S0[n].x, S0[n].y));
                mxb = fmaxf(mxb, fmaxf(S0[n].z, S0[n].w));
                mxc = fmaxf(mxc, fmaxf(S1[n].x, S1[n].y));
                mxd = fmaxf(mxd, fmaxf(S1[n].z, S1[n].w));
            }
#pragma unroll
            for (int off = 1; off <= 2; off <<= 1) {
                mxa = fmaxf(mxa, __shfl_xor_sync(0xffffffffu, mxa, off));
                mxb = fmaxf(mxb, __shfl_xor_sync(0xffffffffu, mxb, off));
                mxc = fmaxf(mxc, __shfl_xor_sync(0xffffffffu, mxc, off));
                mxd = fmaxf(mxd, __shfl_xor_sync(0xffffffffu, mxd, off));
            }
            float n00 = fmaxf(m00, mxa), n01 = fmaxf(m01, mxb);
            float n10 = fmaxf(m10, mxc), n11 = fmaxf(m11, mxd);
            float c00 = __expf(m00 - n00), c01 = __expf(m01 - n01);
            float c10 = __expf(m10 - n10), c11 = __expf(m11 - n11);
            float r00 = 0.f, r01 = 0.f, r10 = 0.f, r11 = 0.f;
#pragma unroll
            for (int n = 0; n < 8; n++) {
                S0[n].x = __expf(S0[n].x - n00); S0[n].y = __expf(S0[n].y - n00);
                S0[n].z = __expf(S0[n].z - n01); S0[n].w = __expf(S0[n].w - n01);
                S1[n].x = __expf(S1[n].x - n10); S1[n].y = __expf(S1[n].y - n10);
                S1[n].z = __expf(S1[n].z - n11); S1[n].w = __expf(S1[n].w - n11);
                r00 += S0[n].x + S0[n].y; r01 += S0[n].z + S0[n].w;
                r10 += S1[n].x + S1[n].y; r11 += S1[n].z + S1[n].w;
            }
#pragma unroll
            for (int off = 1; off <= 2; off <<= 1) {
                r00 += __shfl_xor_sync(0xffffffffu, r00, off);
                r01 += __shfl_xor_sync(0xffffffffu, r01, off);
                r10 += __shfl_xor_sync(0xffffffffu, r10, off);
                r11 += __shfl_xor_sync(0xffffffffu, r11, off);
            }
            l00 = l00 * c00 + r00; l01 = l01 * c01 + r01;
            l10 = l10 * c10 + r10; l11 = l11 * c11 + r11;
            m00 = n00; m01 = n01; m10 = n10; m11 = n11;
#pragma unroll
            for (int n = 0; n < 8; n++) {
                O0[n].x *= c00; O0[n].y *= c00; O0[n].z *= c01; O0[n].w *= c01;
                O1[n].x *= c10; O1[n].y *= c10; O1[n].z *= c11; O1[n].w *= c11;
            }

            // ---- O += P*V: D-frag cols == A-frag k-pairs, just pack bf16x2 ----
#pragma unroll
            for (int kc = 0; kc < 4; kc++) {
                int kc16 = kc * 16;
                unsigned a00 = pk2(S0[2 * kc].x, S0[2 * kc].y);
                unsigned a01 = pk2(S0[2 * kc].z, S0[2 * kc].w);
                unsigned a02 = pk2(S0[2 * kc + 1].x, S0[2 * kc + 1].y);
                unsigned a03 = pk2(S0[2 * kc + 1].z, S0[2 * kc + 1].w);
                unsigned a10 = pk2(S1[2 * kc].x, S1[2 * kc].y);
                unsigned a11 = pk2(S1[2 * kc].z, S1[2 * kc].w);
                unsigned a12 = pk2(S1[2 * kc + 1].x, S1[2 * kc + 1].y);
                unsigned a13 = pk2(S1[2 * kc + 1].z, S1[2 * kc + 1].w);
#pragma unroll
                for (int n = 0; n < 8; n++) {
                    const __nv_bfloat16* vr = &Vs[(n * 8 + g) * BST + kc16];
                    unsigned b0 = *(const unsigned*)&vr[2 * t];
                    unsigned b1 = *(const unsigned*)&vr[2 * t + 8];
                    mma_bf16(O0[n], a00, a01, a02, a03, b0, b1);
                    mma_bf16(O1[n], a10, a11, a12, a13, b0, b1);
                }
            }
        }
    }

    float i00 = 1.f / l00, i01 = 1.f / l01, i10 = 1.f / l10, i11 = 1.f / l11;
    long long ob = ((long long)(b * DZ_ + zw) * HW_) * E_ + h * HD_;
    int rq0 = prow + g, rq1 = prow + 16 + g;
#pragma unroll
    for (int n = 0; n < 8; n++) {
        int col = n * 8 + 2 * t;
        *(float2*)&g_O[ob + (long long)rq0 * E_ + col] = make_float2(O0[n].x * i00, O0[n].y * i00);
        *(float2*)&g_O[ob + (long long)(rq0 + 8) * E_ + col] = make_float2(O0[n].z * i01, O0[n].w * i01);
        *(float2*)&g_O[ob + (long long)rq1 * E_ + col] = make_float2(O1[n].x * i10, O1[n].y * i10);
        *(float2*)&g_O[ob + (long long)(rq1 + 8) * E_ + col] = make_float2(O1[n].z * i11, O1[n].w * i11);
    }
}

// ------------------- kernel 6: output projection + residual (tf32 MMA) ------
__global__ __launch_bounds__(256) void k_oproj(const float* __restrict__ F3,
                                               float* __restrict__ out) {
    extern __shared__ float osm[];
    float* bs = osm;                  // [128][33]
    float* s_o = osm + 128 * 33;      // [128 cols][68 rows]
    int bid = blockIdx.x;
    int p0 = (bid % 9) * 64;
    int z = (bid / 9) % DZ_;
    int b = bid / (9 * DZ_);

    int tid = threadIdx.x;
    int w = tid >> 5, lane = tid & 31;
    int g = lane >> 2, t = lane & 3;
    int mt = w & 3, nh = w >> 2;

    int rowl = (b * DZ_ + z) * HW_ + p0 + mt * 16 + g;
    const float* Al = &g_O[(long long)rowl * E_];
    const float* Ah = Al + 8LL * E_;

    float4 acc[8];
#pragma unroll
    for (int n = 0; n < 8; n++) acc[n] = make_float4(0.f, 0.f, 0.f, 0.f);

    for (int kb = 0; kb < 8; kb++) {
        __syncthreads();
        {
            int kk = tid & 31;
            int n0 = tid >> 5;
            for (int n = n0; n < 128; n += 8)
                bs[n * 33 + kk] = g_WpT[n * E_ + kb * 32 + kk];
        }
        __syncthreads();
#pragma unroll
        for (int kcl = 0; kcl < 4; kcl++) {
            int kcol = kb * 32 + kcl * 8;
            unsigned a0 = __float_as_uint(Al[kcol + t]);
            unsigned a1 = __float_as_uint(Ah[kcol + t]);
            unsigned a2 = __float_as_uint(Al[kcol + t + 4]);
            unsigned a3 = __float_as_uint(Ah[kcol + t + 4]);
#pragma unroll
            for (int n = 0; n < 8; n++) {
                const float* br = &bs[(nh * 64 + n * 8 + g) * 33 + kcl * 8];
                mma_tf32(acc[n], a0, a1, a2, a3,
                         __float_as_uint(br[t]), __float_as_uint(br[t + 4]));
            }
        }
    }
    __syncthreads();

    {
        int rl = mt * 16 + g;
#pragma unroll
        for (int n = 0; n < 8; n++) {
            int col = nh * 64 + n * 8 + 2 * t;
            s_o[col * 68 + rl] = acc[n].x;
            s_o[(col + 1) * 68 + rl] = acc[n].y;
            s_o[col * 68 + rl + 8] = acc[n].z;
            s_o[(col + 1) * 68 + rl + 8] = acc[n].w;
        }
    }
    __syncthreads();

    {
        int r = tid & 63;
        int cb = tid >> 6;
        for (int c = cb; c < C3_; c += 4) {
            long long oi = (long long)(b * C3_ + c) * (DZ_ * HW_) + z * HW_ + p0 + r;
            out[oi] = F3[oi] + s_o[c * 68 + r];
        }
    }
}

// ----------------------------------- launch ---------------------------------
extern "C" void kernel_launch(void* const* d_in, const int* in_sizes, int n_in,
                              void* d_out, int out_size) {
    const float* F3  = (const float*)d_in[0];
    const float* F2  = (const float*)d_in[1];
    const float* Wq  = (const float*)d_in[2];
    const float* Wk  = (const float*)d_in[3];
    const float* Wv  = (const float*)d_in[4];
    const float* Wp  = (const float*)d_in[5];
    const float* lnqg = (const float*)d_in[6];
    const float* lnqb = (const float*)d_in[7];
    const float* lnkg = (const float*)d_in[8];
    const float* lnkb = (const float*)d_in[9];
    const float* w1   = (const float*)d_in[10];
    const float* bng  = (const float*)d_in[11];
    const float* bnb  = (const float*)d_in[12];
    const float* w2   = (const float*)d_in[13];
    const float* w2b  = (const float*)d_in[14];
    const float* lam  = (const float*)d_in[15];
    const void*  D0p  = d_in[16];
    const void*  slabp = d_in[17];
    float* out = (float*)d_out;

    int kvproj_smem = (96 * 72 + 64 * 260) * (int)sizeof(float);   // 94208
    int qproj_smem  = (128 * 72 + 256 * 33) * (int)sizeof(float);  // 70656
    int attn_smem   = 256 * BST * (int)sizeof(__nv_bfloat16);      // 36864
    int oproj_smem  = (128 * 33 + 128 * 68) * (int)sizeof(float);  // 51712
    static int cfg_done = 0;
    if (!cfg_done) {
        cudaFuncSetAttribute(k_kvproj, cudaFuncAttributeMaxDynamicSharedMemorySize, kvproj_smem);
        cudaFuncSetAttribute(k_qproj, cudaFuncAttributeMaxDynamicSharedMemorySize, qproj_smem);
        cudaFuncSetAttribute(k_attn, cudaFuncAttributeMaxDynamicSharedMemorySize, attn_smem);
        cudaFuncSetAttribute(k_oproj, cudaFuncAttributeMaxDynamicSharedMemorySize, oproj_smem);
        cfg_done = 1;
    }

    k_wtrans<<<(TOPO_ * C2_ * 9 + 255) / 256, 256>>>(w1);
    k_wprep<<<(C3_ * E_ + 255) / 256, 256>>>(Wq, Wp, Wk, Wv);
    k_conv1<<<dim3(6, B_ * K_), 384>>>(F2, bng, bnb);
    k_topo<<<B_ * K_, 192>>>(w2, w2b);
    k_kvproj<<<B_ * K_ * 9, 256, kvproj_smem>>>(F2, lnkg, lnkb);
    k_qproj<<<B_ * DZ_ * 9, 256, qproj_smem>>>(F3, lnqg, lnqb);
    k_attn<<<B_ * NH_ * (DZ_ / 2) * 9, 128, attn_smem>>>(lam, D0p, slabp);
    k_oproj<<<B_ * DZ_ * 9, 256, oproj_smem>>>(F3, out);
}

// round 7
// speedup vs baseline: 4.5206x; 1.0639x over previous
#include <cuda_runtime.h>
#include <cuda_bf16.h>
#include <math.h>

#define B_ 2
#define C3_ 128
#define DZ_ 32
#define HW_ 576
#define C2_ 96
#define K_ 8
#define E_ 256
#define NH_ 4
#define HD_ 64
#define TOPO_ 64
#define LN_EPS 1e-5f
#define LOG2E_ 1.4426950408889634f

// ------------------------- device scratch (no allocation) -------------------
__device__ float g_w1t[C2_ * 9 * TOPO_];
__device__ float g_h[B_ * K_ * HW_ * TOPO_];
__device__ float g_topo[B_ * K_ * HW_];
__device__ __nv_bfloat16 g_Q[B_ * NH_ * DZ_ * HW_ * HD_];   // pre-scaled by log2e/8
__device__ __nv_bfloat16 g_K[B_ * NH_ * K_ * HW_ * HD_];    // (b,h,c,p,d)
__device__ __nv_bfloat16 g_Vt[B_ * NH_ * K_ * HD_ * HW_];   // (b,h,c,d,p) transposed
__device__ float g_O[B_ * DZ_ * HW_ * E_];
__device__ float g_WqT[E_ * C3_];
__device__ float g_WpT[C3_ * E_];
__device__ float g_WkT[E_ * C2_];
__device__ float g_WvT[E_ * C2_];

__device__ __forceinline__ int flex_int(const void* p, int dflt) {
    int v = *(const int*)p;
    if (v >= 1 && v <= 1000000) return v;
    float f = *(const float*)p;
    if (f >= 1.f && f <= 1000000.f) return (int)f;
    return dflt;
}

__device__ __forceinline__ unsigned pk2(float lo, float hi) {
    unsigned r;
    asm("cvt.rn.bf16x2.f32 %0, %1, %2;" : "=r"(r) : "f"(hi), "f"(lo));
    return r;
}

__device__ __forceinline__ float ex2(float x) {
    float y;
    asm("ex2.approx.f32 %0, %1;" : "=f"(y) : "f"(x));
    return y;
}

__device__ __forceinline__ void ldsm4(unsigned& r0, unsigned& r1,
                                      unsigned& r2, unsigned& r3, unsigned addr) {
    asm volatile("ldmatrix.sync.aligned.m8n8.x4.shared.b16 {%0,%1,%2,%3}, [%4];"
                 : "=r"(r0), "=r"(r1), "=r"(r2), "=r"(r3) : "r"(addr));
}

__device__ __forceinline__ void mma_tf32(float4& d,
                                         unsigned a0, unsigned a1, unsigned a2, unsigned a3,
                                         unsigned b0, unsigned b1) {
    asm volatile(
        "mma.sync.aligned.m16n8k8.row.col.f32.tf32.tf32.f32 "
        "{%0,%1,%2,%3}, {%4,%5,%6,%7}, {%8,%9}, {%0,%1,%2,%3};"
        : "+f"(d.x), "+f"(d.y), "+f"(d.z), "+f"(d.w)
        : "r"(a0), "r"(a1), "r"(a2), "r"(a3), "r"(b0), "r"(b1));
}

__device__ __forceinline__ void mma_bf16(float4& d,
                                         unsigned a0, unsigned a1, unsigned a2, unsigned a3,
                                         unsigned b0, unsigned b1) {
    asm volatile(
        "mma.sync.aligned.m16n8k16.row.col.f32.bf16.bf16.f32 "
        "{%0,%1,%2,%3}, {%4,%5,%6,%7}, {%8,%9}, {%0,%1,%2,%3};"
        : "+f"(d.x), "+f"(d.y), "+f"(d.z), "+f"(d.w)
        : "r"(a0), "r"(a1), "r"(a2), "r"(a3), "r"(b0), "r"(b1));
}

// ------------------------- kernel 0: all weight prep ------------------------
__global__ void k_wprep(const float* __restrict__ w1,
                        const float* __restrict__ Wq, const float* __restrict__ Wp,
                        const float* __restrict__ Wk, const float* __restrict__ Wv) {
    int i = blockIdx.x * 256 + threadIdx.x;
    if (i < TOPO_ * C2_ * 9) {
        int o = i / (C2_ * 9);
        int r = i % (C2_ * 9);
        int c = r / 9, tap = r % 9;
        g_w1t[(c * 9 + tap) * TOPO_ + o] = w1[i];
    }
    if (i < C3_ * E_) {
        int e = i / C3_, c = i % C3_;
        g_WqT[i] = Wq[c * E_ + e];
        g_WpT[c * E_ + e] = Wp[i];
    }
    if (i < C2_ * E_) {
        int e = i / C2_, c = i % C2_;
        g_WkT[i] = Wk[c * E_ + e];
        g_WvT[i] = Wv[c * E_ + e];
    }
}

// ------------------- kernel 1: conv1 3x3 (96->64) + BN + ReLU ---------------
__global__ __launch_bounds__(384) void k_conv1(const float* __restrict__ F2,
                                               const float* __restrict__ bng,
                                               const float* __restrict__ bnb) {
    __shared__ float in_s[16][6][26];
    __shared__ float w_s[16 * 9 * 64];
    int bk = blockIdx.y;
    int b = bk >> 3, k = bk & 7;
    int y0 = blockIdx.x * 4;
    int tid = threadIdx.x;
    int ig = tid >> 4;
    int j = tid & 15;
    int pl = ig * 4;
    int yrel = pl / 24;
    int x0 = pl % 24;
    int o0 = j * 4;
    float acc[4][4];
#pragma unroll
    for (int u = 0; u < 4; u++)
#pragma unroll
        for (int v = 0; v < 4; v++) acc[u][v] = 0.f;

    for (int c0 = 0; c0 < C2_; c0 += 16) {
        __syncthreads();
        for (int idx = tid; idx < 16 * 6 * 26; idx += 384) {
            int cc = idx / 156, rem = idx % 156;
            int yy = rem / 26, xx = rem % 26;
            int y = y0 - 1 + yy, x = xx - 1;
            float v = 0.f;
            if ((unsigned)y < 24u && (unsigned)x < 24u)
                v = F2[((b * C2_ + c0 + cc) * HW_ + y * 24 + x) * K_ + k];
            in_s[cc][yy][xx] = v;
        }
        for (int idx = tid; idx < 16 * 9 * 64; idx += 384)
            w_s[idx] = g_w1t[c0 * 9 * 64 + idx];
        __syncthreads();
        for (int cc = 0; cc < 16; cc++) {
#pragma unroll
            for (int dy = 0; dy < 3; dy++) {
                float rv[6];
#pragma unroll
                for (int u = 0; u < 6; u++) rv[u] = in_s[cc][yrel + dy][x0 + u];
#pragma unroll
                for (int dx = 0; dx < 3; dx++) {
                    float4 w4 = *(const float4*)&w_s[(cc * 9 + dy * 3 + dx) * 64 + o0];
#pragma unroll
                    for (int u = 0; u < 4; u++) {
                        float a = rv[u + dx];
                        acc[u][0] += a * w4.x;
                        acc[u][1] += a * w4.y;
                        acc[u][2] += a * w4.z;
                        acc[u][3] += a * w4.w;
                    }
                }
            }
        }
    }
    float invs = rsqrtf(1.f + LN_EPS);
    float s0 = bng[o0] * invs, s1 = bng[o0 + 1] * invs;
    float s2 = bng[o0 + 2] * invs, s3 = bng[o0 + 3] * invs;
    float b0 = bnb[o0], b1 = bnb[o0 + 1], b2 = bnb[o0 + 2], b3 = bnb[o0 + 3];
#pragma unroll
    for (int u = 0; u < 4; u++) {
        int p = (y0 + yrel) * 24 + x0 + u;
        float4 hv;
        hv.x = fmaxf(acc[u][0] * s0 + b0, 0.f);
        hv.y = fmaxf(acc[u][1] * s1 + b1, 0.f);
        hv.z = fmaxf(acc[u][2] * s2 + b2, 0.f);
        hv.w = fmaxf(acc[u][3] * s3 + b3, 0.f);
        *(float4*)&g_h[(bk * HW_ + p) * TOPO_ + o0] = hv;
    }
}

// ------------------- kernel 2: conv2 1x1 + neighbor-sum -> topo -------------
__global__ __launch_bounds__(192) void k_topo(const float* __restrict__ w2,
                                              const float* __restrict__ w2b) {
    __shared__ float sp[HW_];
    __shared__ float wsh[64];
    int bk = blockIdx.x;
    int tid = threadIdx.x;
    if (tid < 64) wsh[tid] = w2[tid];
    __syncthreads();
    for (int p = tid; p < HW_; p += 192) {
        const float* hp = &g_h[(bk * HW_ + p) * TOPO_];
        float s = w2b[0];
#pragma unroll
        for (int o = 0; o < 64; o += 4) {
            float4 hv = *(const float4*)&hp[o];
            s += hv.x * wsh[o] + hv.y * wsh[o + 1] + hv.z * wsh[o + 2] + hv.w * wsh[o + 3];
        }
        sp[p] = s;
    }
    __syncthreads();
    for (int p = tid; p < HW_; p += 192) {
        int y = p / 24, x = p % 24;
        float s = 0.f;
#pragma unroll
        for (int dy = -1; dy <= 1; dy++)
#pragma unroll
            for (int dx = -1; dx <= 1; dx++) {
                if (dy == 0 && dx == 0) continue;
                int yy = y + dy, xx = x + dx;
                if ((unsigned)yy < 24u && (unsigned)xx < 24u) s += sp[yy * 24 + xx];
            }
        g_topo[bk * HW_ + p] = sp[p] + 0.5f * s;
    }
}

// ------------------- kernel 3: K/V projection + LN (tf32 MMA, bf16 out) -----
__global__ __launch_bounds__(256) void k_kvproj(const float* __restrict__ F2,
                                                const float* __restrict__ lng,
                                                const float* __restrict__ lnb) {
    extern __shared__ float ksm[];
    float* xk = ksm;                  // [96][72]
    float* bs = ksm + 96 * 72;        // [256][33]
    float* s_o = ksm + 96 * 72;       // alias, [64][260]
    __shared__ float smean[64], srstd[64];

    int bid = blockIdx.x;
    int p0 = (bid % 9) * 64;
    int k = (bid / 9) % K_;
    int b = bid / (9 * K_);

    int tid = threadIdx.x;
    int w = tid >> 5, lane = tid & 31;
    int g = lane >> 2, t = lane & 3;
    int mt = w & 3, nh = w >> 2;

    {
        int r = tid & 63;
        int cb = tid >> 6;
        for (int c = cb; c < C2_; c += 4)
            xk[c * 72 + r] = F2[((b * C2_ + c) * HW_ + p0 + r) * K_ + k];
    }

    for (int mat = 0; mat < 2; mat++) {
        const float* WT = mat == 0 ? g_WkT : g_WvT;
        float4 acc[16];
#pragma unroll
        for (int n = 0; n < 16; n++) acc[n] = make_float4(0.f, 0.f, 0.f, 0.f);

        for (int kb = 0; kb < 3; kb++) {
            __syncthreads();
            {
                int kk = tid & 31;
                int n0 = tid >> 5;
                for (int n = n0; n < 256; n += 8)
                    bs[n * 33 + kk] = WT[n * C2_ + kb * 32 + kk];
            }
            __syncthreads();
#pragma unroll
            for (int kcl = 0; kcl < 4; kcl++) {
                int krow = kb * 32 + kcl * 8;
                int arow = mt * 16 + g;
                unsigned a0 = __float_as_uint(xk[(krow + t) * 72 + arow]);
                unsigned a1 = __float_as_uint(xk[(krow + t) * 72 + arow + 8]);
                unsigned a2 = __float_as_uint(xk[(krow + t + 4) * 72 + arow]);
                unsigned a3 = __float_as_uint(xk[(krow + t + 4) * 72 + arow + 8]);
#pragma unroll
                for (int n = 0; n < 16; n++) {
                    const float* br = &bs[(nh * 128 + n * 8 + g) * 33 + kcl * 8];
                    mma_tf32(acc[n], a0, a1, a2, a3,
                             __float_as_uint(br[t]), __float_as_uint(br[t + 4]));
                }
            }
        }
        __syncthreads();
        {
            int rl = mt * 16 + g;
#pragma unroll
            for (int n = 0; n < 16; n++) {
                int col = nh * 128 + n * 8 + 2 * t;
                s_o[rl * 260 + col] = acc[n].x;
                s_o[rl * 260 + col + 1] = acc[n].y;
                s_o[(rl + 8) * 260 + col] = acc[n].z;
                s_o[(rl + 8) * 260 + col + 1] = acc[n].w;
            }
        }
        __syncthreads();
#pragma unroll
        for (int rr = 0; rr < 8; rr++) {
            int row = w * 8 + rr;
            float s = 0.f, q = 0.f;
#pragma unroll
            for (int jj = 0; jj < 8; jj++) {
                float v = s_o[row * 260 + lane + 32 * jj];
                s += v; q += v * v;
            }
#pragma unroll
            for (int off = 16; off >= 1; off >>= 1) {
                s += __shfl_xor_sync(0xffffffffu, s, off);
                q += __shfl_xor_sync(0xffffffffu, q, off);
            }
            if (lane == 0) {
                float mu = s * (1.f / 256.f);
                smean[row] = mu;
                srstd[row] = rsqrtf(q * (1.f / 256.f) - mu * mu + LN_EPS);
            }
        }
        __syncthreads();

        if (mat == 0) {
            int cl = (tid & 63) * 4;
            int rb = tid >> 6;
            float4 g4 = *(const float4*)&lng[cl];
            float4 b4 = *(const float4*)&lnb[cl];
            int h = cl >> 6, cc = cl & 63;
            long long obase = ((long long)(b * NH_ + h) * K_ + k) * HW_;
            for (int r = rb; r < 64; r += 4) {
                float mu = smean[r], rs = srstd[r];
                float v0 = (s_o[r * 260 + cl] - mu) * rs * g4.x + b4.x;
                float v1 = (s_o[r * 260 + cl + 1] - mu) * rs * g4.y + b4.y;
                float v2 = (s_o[r * 260 + cl + 2] - mu) * rs * g4.z + b4.z;
                float v3 = (s_o[r * 260 + cl + 3] - mu) * rs * g4.w + b4.w;
                uint2 u = make_uint2(pk2(v0, v1), pk2(v2, v3));
                *(uint2*)&g_K[(obase + p0 + r) * HD_ + cc] = u;
            }
        } else {
            int e = tid;
            float ge = lng[e], be = lnb[e];
            int h = e >> 6, d = e & 63;
            long long vb = (((long long)(b * NH_ + h) * K_ + k) * HD_ + d) * HW_ + p0;
#pragma unroll
            for (int rb2 = 0; rb2 < 16; rb2++) {
                int r = rb2 * 4;
                float v0 = (s_o[r * 260 + e] - smean[r]) * srstd[r] * ge + be;
                float v1 = (s_o[(r + 1) * 260 + e] - smean[r + 1]) * srstd[r + 1] * ge + be;
                float v2 = (s_o[(r + 2) * 260 + e] - smean[r + 2]) * srstd[r + 2] * ge + be;
                float v3 = (s_o[(r + 3) * 260 + e] - smean[r + 3]) * srstd[r + 3] * ge + be;
                uint2 u = make_uint2(pk2(v0, v1), pk2(v2, v3));
                *(uint2*)&g_Vt[vb + r] = u;
            }
        }
    }
}

// ------------------- kernel 4: Q projection + LN + scale (tf32 MMA) ---------
__global__ __launch_bounds__(256) void k_qproj(const float* __restrict__ F3,
                                               const float* __restrict__ lng,
                                               const float* __restrict__ lnb) {
    extern __shared__ float qsm[];
    float* xk = qsm;                  // [128][72]
    float* bs = qsm + 128 * 72;       // [256][33]
    float* s_o = qsm;                 // alias, [64][260]
    __shared__ float smean[64], srstd[64];

    int bid = blockIdx.x;
    int p0 = (bid % 9) * 64;
    int z = (bid / 9) % DZ_;
    int b = bid / (9 * DZ_);

    int tid = threadIdx.x;
    int w = tid >> 5, lane = tid & 31;
    int g = lane >> 2, t = lane & 3;
    int mt = w & 3, nh = w >> 2;

    {
        int r = tid & 63;
        int cb = tid >> 6;
        for (int c = cb; c < C3_; c += 4)
            xk[c * 72 + r] = F3[(b * C3_ + c) * (DZ_ * HW_) + z * HW_ + p0 + r];
    }

    float4 acc[16];
#pragma unroll
    for (int n = 0; n < 16; n++) acc[n] = make_float4(0.f, 0.f, 0.f, 0.f);

    for (int kb = 0; kb < 4; kb++) {
        __syncthreads();
        {
            int kk = tid & 31;
            int n0 = tid >> 5;
            for (int n = n0; n < 256; n += 8)
                bs[n * 33 + kk] = g_WqT[n * C3_ + kb * 32 + kk];
        }
        __syncthreads();
#pragma unroll
        for (int kcl = 0; kcl < 4; kcl++) {
            int krow = kb * 32 + kcl * 8;
            int arow = mt * 16 + g;
            unsigned a0 = __float_as_uint(xk[(krow + t) * 72 + arow]);
            unsigned a1 = __float_as_uint(xk[(krow + t) * 72 + arow + 8]);
            unsigned a2 = __float_as_uint(xk[(krow + t + 4) * 72 + arow]);
            unsigned a3 = __float_as_uint(xk[(krow + t + 4) * 72 + arow + 8]);
#pragma unroll
            for (int n = 0; n < 16; n++) {
                const float* br = &bs[(nh * 128 + n * 8 + g) * 33 + kcl * 8];
                mma_tf32(acc[n], a0, a1, a2, a3,
                         __float_as_uint(br[t]), __float_as_uint(br[t + 4]));
            }
        }
    }
    __syncthreads();

    {
        int rl = mt * 16 + g;
#pragma unroll
        for (int n = 0; n < 16; n++) {
            int col = nh * 128 + n * 8 + 2 * t;
            s_o[rl * 260 + col] = acc[n].x;
            s_o[rl * 260 + col + 1] = acc[n].y;
            s_o[(rl + 8) * 260 + col] = acc[n].z;
            s_o[(rl + 8) * 260 + col + 1] = acc[n].w;
        }
    }
    __syncthreads();

#pragma unroll
    for (int rr = 0; rr < 8; rr++) {
        int row = w * 8 + rr;
        float s = 0.f, q = 0.f;
#pragma unroll
        for (int jj = 0; jj < 8; jj++) {
            float v = s_o[row * 260 + lane + 32 * jj];
            s += v; q += v * v;
        }
#pragma unroll
        for (int off = 16; off >= 1; off >>= 1) {
            s += __shfl_xor_sync(0xffffffffu, s, off);
            q += __shfl_xor_sync(0xffffffffu, q, off);
        }
        if (lane == 0) {
            float mu = s * (1.f / 256.f);
            smean[row] = mu;
            srstd[row] = rsqrtf(q * (1.f / 256.f) - mu * mu + LN_EPS);
        }
    }
    __syncthreads();

    {
        int cl = (tid & 63) * 4;
        int rb = tid >> 6;
        float4 g4 = *(const float4*)&lng[cl];
        float4 b4 = *(const float4*)&lnb[cl];
        int h = cl >> 6, cc = cl & 63;
        const float qscale = 0.125f * LOG2E_;   // fold log2e for exp2 softmax
        long long obase = ((long long)(b * NH_ + h) * DZ_ + z) * HW_;
        for (int r = rb; r < 64; r += 4) {
            float mu = smean[r], rs = srstd[r];
            float v0 = ((s_o[r * 260 + cl] - mu) * rs * g4.x + b4.x) * qscale;
            float v1 = ((s_o[r * 260 + cl + 1] - mu) * rs * g4.y + b4.y) * qscale;
            float v2 = ((s_o[r * 260 + cl + 2] - mu) * rs * g4.z + b4.z) * qscale;
            float v3 = ((s_o[r * 260 + cl + 3] - mu) * rs * g4.w + b4.w) * qscale;
            uint2 u = make_uint2(pk2(v0, v1), pk2(v2, v3));
            *(uint2*)&g_Q[(obase + p0 + r) * HD_ + cc] = u;
        }
    }
}

// ------------------- kernel 5: flash attention (bf16 MMA + LDSM, exp2) ------
#define BST 72
__global__ __launch_bounds__(128) void k_attn(const float* __restrict__ lam_p,
                                              const void* __restrict__ D0_p,
                                              const void* __restrict__ slab_p) {
    extern __shared__ __nv_bfloat16 bsm[];
    __nv_bfloat16* Qs = bsm;                   // [128][BST]
    __nv_bfloat16* Ks = bsm + 128 * BST;       // [64][BST]
    __nv_bfloat16* Vs = bsm + 192 * BST;       // [64][BST]

    int bid = blockIdx.x;
    int p0 = (bid % 9) * 64;
    int zp = (bid / 9) % (DZ_ / 2);
    int h = (bid / (9 * (DZ_ / 2))) % NH_;
    int b = bid / (9 * (DZ_ / 2) * NH_);
    int z0 = zp * 2;

    int D0 = flex_int(D0_p, 128);
    int slab = flex_int(slab_p, 16);
    float lam2 = (*lam_p) * LOG2E_;

    int kkz[2], cloz[2], chiz[2];
#pragma unroll
    for (int i = 0; i < 2; i++) {
        int zz = z0 + i;
        int zq = (int)llrint((double)(D0 - 1) * (double)zz / (double)(DZ_ - 1));
        int kk = zq / slab;
        if (kk < 0) kk = 0;
        if (kk > K_ - 1) kk = K_ - 1;
        kkz[i] = kk;
        cloz[i] = (kk - 1 < 0) ? 0 : kk - 1;
        chiz[i] = (kk + 1 > K_ - 1) ? K_ - 1 : kk + 1;
    }
    int cU_lo = min(cloz[0], cloz[1]);
    int cU_hi = max(chiz[0], chiz[1]);

    int tid = threadIdx.x;
    int w = tid >> 5;
    int lane = tid & 31;
    int g = lane >> 2;
    int t = lane & 3;

    int wz = w >> 1;
    int zw = z0 + wz;
    int kk_w = kkz[wz], clo_w = cloz[wz], chi_w = chiz[wz];
    int prow = p0 + (w & 1) * 32;
    int qrow = w * 32;

    unsigned qb_s = (unsigned)__cvta_generic_to_shared(Qs);
    unsigned kb_s = (unsigned)__cvta_generic_to_shared(Ks);
    unsigned vb_s = (unsigned)__cvta_generic_to_shared(Vs);
    // ldmatrix per-lane address offset: rows (lane&7) + ((lane>>3)&1)*8, col +((lane>>4)&1)*8
    unsigned laneoff = (((lane & 7) + ((lane >> 3) & 1) * 8) * BST + ((lane >> 4) & 1) * 8) * 2;

    // load Q: 128 rows x 64 bf16
    {
        long long qb0 = ((((long long)(b * NH_ + h) * DZ_ + z0) * HW_) + p0) * HD_;
#pragma unroll
        for (int it = 0; it < 8; it++) {
            int idx = tid + it * 128;
            int r = idx >> 3, v = (idx & 7) * 8;
            long long src = qb0 + (long long)(r >> 6) * (HW_ * HD_) + (long long)(r & 63) * 64 + v;
            *(uint4*)&Qs[r * BST + v] = *(const uint4*)&g_Q[src];
        }
    }

    float l00 = 0.f, l01 = 0.f, l10 = 0.f, l11 = 0.f;
    float4 O0[8], O1[8];
#pragma unroll
    for (int n = 0; n < 8; n++) {
        O0[n] = make_float4(0.f, 0.f, 0.f, 0.f);
        O1[n] = make_float4(0.f, 0.f, 0.f, 0.f);
    }

    for (int c = cU_lo; c <= cU_hi; c++) {
        bool active = (c >= clo_w) && (c <= chi_w);
        float bias2 = (c == kk_w) ? 0.f : -0.5f * LOG2E_;
        long long kb = (((long long)(b * NH_ + h) * K_ + c) * HW_) * HD_;
        long long vb = (((long long)(b * NH_ + h) * K_ + c) * HD_) * HW_;
        const float* topo_c = &g_topo[(b * K_ + c) * HW_];
        for (int pk0 = 0; pk0 < HW_; pk0 += 64) {
            __syncthreads();
#pragma unroll
            for (int it = 0; it < 4; it++) {
                int idx = tid + it * 128;
                int r = idx >> 3, v = (idx & 7) * 8;
                *(uint4*)&Ks[r * BST + v] = *(const uint4*)&g_K[kb + (long long)(pk0 + r) * 64 + v];
                *(uint4*)&Vs[r * BST + v] = *(const uint4*)&g_Vt[vb + (long long)r * HW_ + pk0 + v];
            }
            __syncthreads();
            if (!active) continue;

            // ---- S = Q*K^T (bf16 mma, LDSM fragments) ----
            float4 S0[8], S1[8];
#pragma unroll
            for (int n = 0; n < 8; n++) {
                S0[n] = make_float4(0.f, 0.f, 0.f, 0.f);
                S1[n] = make_float4(0.f, 0.f, 0.f, 0.f);
            }
#pragma unroll
            for (int kc = 0; kc < 4; kc++) {
                int kc16 = kc * 16;
                unsigned a00, a01, a02, a03, a10, a11, a12, a13;
                ldsm4(a00, a01, a02, a03, qb_s + (qrow * BST + kc16) * 2 + laneoff);
                ldsm4(a10, a11, a12, a13, qb_s + ((qrow + 16) * BST + kc16) * 2 + laneoff);
#pragma unroll
                for (int n2 = 0; n2 < 4; n2++) {
                    unsigned b0, b1, b2, b3;
                    ldsm4(b0, b1, b2, b3, kb_s + ((n2 * 16) * BST + kc16) * 2 + laneoff);
                    mma_bf16(S0[2 * n2],     a00, a01, a02, a03, b0, b2);
                    mma_bf16(S0[2 * n2 + 1], a00, a01, a02, a03, b1, b3);
                    mma_bf16(S1[2 * n2],     a10, a11, a12, a13, b0, b2);
                    mma_bf16(S1[2 * n2 + 1], a10, a11, a12, a13, b1, b3);
                }
            }

            // ---- bias + diag topo + exp2 (no-max softmax; shift 0 is exact) ----
            int rq0 = prow + g;
            int rq1 = prow + 16 + g;
#pragma unroll
            for (int n = 0; n < 8; n++) {
                int j0 = pk0 + n * 8 + 2 * t;
                int j1 = j0 + 1;
                float d00 = bias2, d01 = bias2, d02 = bias2, d03 = bias2;
                float d10 = bias2, d11 = bias2, d12 = bias2, d13 = bias2;
                if (rq0 == j0)     d00 += lam2 * topo_c[j0];
                if (rq0 == j1)     d01 += lam2 * topo_c[j1];
                if (rq0 + 8 == j0) d02 += lam2 * topo_c[j0];
                if (rq0 + 8 == j1) d03 += lam2 * topo_c[j1];
                if (rq1 == j0)     d10 += lam2 * topo_c[j0];
                if (rq1 == j1)     d11 += lam2 * topo_c[j1];
                if (rq1 + 8 == j0) d12 += lam2 * topo_c[j0];
                if (rq1 + 8 == j1) d13 += lam2 * topo_c[j1];
                S0[n].x = ex2(S0[n].x + d00); S0[n].y = ex2(S0[n].y + d01);
                S0[n].z = ex2(S0[n].z + d02); S0[n].w = ex2(S0[n].w + d03);
                S1[n].x = ex2(S1[n].x + d10); S1[n].y = ex2(S1[n].y + d11);
                S1[n].z = ex2(S1[n].z + d12); S1[n].w = ex2(S1[n].w + d13);
                l00 += S0[n].x + S0[n].y; l01 += S0[n].z + S0[n].w;
                l10 += S1[n].x + S1[n].y; l11 += S1[n].z + S1[n].w;
            }

            // ---- O += P*V (pack P to bf16x2; B frags via LDSM) ----
#pragma unroll
            for (int kc = 0; kc < 4; kc++) {
                int kc16 = kc * 16;
                unsigned a00 = pk2(S0[2 * kc].x, S0[2 * kc].y);
                unsigned a01 = pk2(S0[2 * kc].z, S0[2 * kc].w);
                unsigned a02 = pk2(S0[2 * kc + 1].x, S0[2 * kc + 1].y);
                unsigned a03 = pk2(S0[2 * kc + 1].z, S0[2 * kc + 1].w);
                unsigned a10 = pk2(S1[2 * kc].x, S1[2 * kc].y);
                unsigned a11 = pk2(S1[2 * kc].z, S1[2 * kc].w);
                unsigned a12 = pk2(S1[2 * kc + 1].x, S1[2 * kc + 1].y);
                unsigned a13 = pk2(S1[2 * kc + 1].z, S1[2 * kc + 1].w);
#pragma unroll
                for (int n2 = 0; n2 < 4; n2++) {
                    unsigned b0, b1, b2, b3;
                    ldsm4(b0, b1, b2, b3, vb_s + ((n2 * 16) * BST + kc16) * 2 + laneoff);
                    mma_bf16(O0[2 * n2],     a00, a01, a02, a03, b0, b2);
                    mma_bf16(O0[2 * n2 + 1], a00, a01, a02, a03, b1, b3);
                    mma_bf16(O1[2 * n2],     a10, a11, a12, a13, b0, b2);
                    mma_bf16(O1[2 * n2 + 1], a10, a11, a12, a13, b1, b3);
                }
            }
        }
    }

    // deferred l reduction across the quad
#pragma unroll
    for (int off = 1; off <= 2; off <<= 1) {
        l00 += __shfl_xor_sync(0xffffffffu, l00, off);
        l01 += __shfl_xor_sync(0xffffffffu, l01, off);
        l10 += __shfl_xor_sync(0xffffffffu, l10, off);
        l11 += __shfl_xor_sync(0xffffffffu, l11, off);
    }

    float i00 = 1.f / l00, i01 = 1.f / l01, i10 = 1.f / l10, i11 = 1.f / l11;
    long long ob = ((long long)(b * DZ_ + zw) * HW_) * E_ + h * HD_;
    int rq0 = prow + g, rq1 = prow + 16 + g;
#pragma unroll
    for (int n = 0; n < 8; n++) {
        int col = n * 8 + 2 * t;
        *(float2*)&g_O[ob + (long long)rq0 * E_ + col] = make_float2(O0[n].x * i00, O0[n].y * i00);
        *(float2*)&g_O[ob + (long long)(rq0 + 8) * E_ + col] = make_float2(O0[n].z * i01, O0[n].w * i01);
        *(float2*)&g_O[ob + (long long)rq1 * E_ + col] = make_float2(O1[n].x * i10, O1[n].y * i10);
        *(float2*)&g_O[ob + (long long)(rq1 + 8) * E_ + col] = make_float2(O1[n].z * i11, O1[n].w * i11);
    }
}

// ------------------- kernel 6: output projection + residual (tf32 MMA) ------
__global__ __launch_bounds__(256) void k_oproj(const float* __restrict__ F3,
                                               float* __restrict__ out) {
    extern __shared__ float osm[];
    float* bs = osm;                  // [128][33]
    float* s_o = osm + 128 * 33;      // [128 cols][68 rows]
    int bid = blockIdx.x;
    int p0 = (bid % 9) * 64;
    int z = (bid / 9) % DZ_;
    int b = bid / (9 * DZ_);

    int tid = threadIdx.x;
    int w = tid >> 5, lane = tid & 31;
    int g = lane >> 2, t = lane & 3;
    int mt = w & 3, nh = w >> 2;

    int rowl = (b * DZ_ + z) * HW_ + p0 + mt * 16 + g;
    const float* Al = &g_O[(long long)rowl * E_];
    const float* Ah = Al + 8LL * E_;

    float4 acc[8];
#pragma unroll
    for (int n = 0; n < 8; n++) acc[n] = make_float4(0.f, 0.f, 0.f, 0.f);

    for (int kb = 0; kb < 8; kb++) {
        __syncthreads();
        {
            int kk = tid & 31;
            int n0 = tid >> 5;
            for (int n = n0; n < 128; n += 8)
                bs[n * 33 + kk] = g_WpT[n * E_ + kb * 32 + kk];
        }
        __syncthreads();
#pragma unroll
        for (int kcl = 0; kcl < 4; kcl++) {
            int kcol = kb * 32 + kcl * 8;
            unsigned a0 = __float_as_uint(Al[kcol + t]);
            unsigned a1 = __float_as_uint(Ah[kcol + t]);
            unsigned a2 = __float_as_uint(Al[kcol + t + 4]);
            unsigned a3 = __float_as_uint(Ah[kcol + t + 4]);
#pragma unroll
            for (int n = 0; n < 8; n++) {
                const float* br = &bs[(nh * 64 + n * 8 + g) * 33 + kcl * 8];
                mma_tf32(acc[n], a0, a1, a2, a3,
                         __float_as_uint(br[t]), __float_as_uint(br[t + 4]));
            }
        }
    }
    __syncthreads();

    {
        int rl = mt * 16 + g;
#pragma unroll
        for (int n = 0; n < 8; n++) {
            int col = nh * 64 + n * 8 + 2 * t;
            s_o[col * 68 + rl] = acc[n].x;
            s_o[(col + 1) * 68 + rl] = acc[n].y;
            s_o[col * 68 + rl + 8] = acc[n].z;
            s_o[(col + 1) * 68 + rl + 8] = acc[n].w;
        }
    }
    __syncthreads();

    {
        int r = tid & 63;
        int cb = tid >> 6;
        for (int c = cb; c < C3_; c += 4) {
            long long oi = (long long)(b * C3_ + c) * (DZ_ * HW_) + z * HW_ + p0 + r;
            out[oi] = F3[oi] + s_o[c * 68 + r];
        }
    }
}

// ----------------------------------- launch ---------------------------------
extern "C" void kernel_launch(void* const* d_in, const int* in_sizes, int n_in,
                              void* d_out, int out_size) {
    const float* F3  = (const float*)d_in[0];
    const float* F2  = (const float*)d_in[1];
    const float* Wq  = (const float*)d_in[2];
    const float* Wk  = (const float*)d_in[3];
    const float* Wv  = (const float*)d_in[4];
    const float* Wp  = (const float*)d_in[5];
    const float* lnqg = (const float*)d_in[6];
    const float* lnqb = (const float*)d_in[7];
    const float* lnkg = (const float*)d_in[8];
    const float* lnkb = (const float*)d_in[9];
    const float* w1   = (const float*)d_in[10];
    const float* bng  = (const float*)d_in[11];
    const float* bnb  = (const float*)d_in[12];
    const float* w2   = (const float*)d_in[13];
    const float* w2b  = (const float*)d_in[14];
    const float* lam  = (const float*)d_in[15];
    const void*  D0p  = d_in[16];
    const void*  slabp = d_in[17];
    float* out = (float*)d_out;

    int kvproj_smem = (96 * 72 + 64 * 260) * (int)sizeof(float);   // 94208
    int qproj_smem  = (128 * 72 + 256 * 33) * (int)sizeof(float);  // 70656
    int attn_smem   = 256 * BST * (int)sizeof(__nv_bfloat16);      // 36864
    int oproj_smem  = (128 * 33 + 128 * 68) * (int)sizeof(float);  // 51712
    static int cfg_done = 0;
    if (!cfg_done) {
        cudaFuncSetAttribute(k_kvproj, cudaFuncAttributeMaxDynamicSharedMemorySize, kvproj_smem);
        cudaFuncSetAttribute(k_qproj, cudaFuncAttributeMaxDynamicSharedMemorySize, qproj_smem);
        cudaFuncSetAttribute(k_attn, cudaFuncAttributeMaxDynamicSharedMemorySize, attn_smem);
        cudaFuncSetAttribute(k_oproj, cudaFuncAttributeMaxDynamicSharedMemorySize, oproj_smem);
        cfg_done = 1;
    }

    k_wprep<<<(TOPO_ * C2_ * 9 + 255) / 256, 256>>>(w1, Wq, Wp, Wk, Wv);
    k_conv1<<<dim3(6, B_ * K_), 384>>>(F2, bng, bnb);
    k_topo<<<B_ * K_, 192>>>(w2, w2b);
    k_kvproj<<<B_ * K_ * 9, 256, kvproj_smem>>>(F2, lnkg, lnkb);
    k_qproj<<<B_ * DZ_ * 9, 256, qproj_smem>>>(F3, lnqg, lnqb);
    k_attn<<<B_ * NH_ * (DZ_ / 2) * 9, 128, attn_smem>>>(lam, D0p, slabp);
    k_oproj<<<B_ * DZ_ * 9, 256, oproj_smem>>>(F3, out);
}

// round 8
// speedup vs baseline: 4.8234x; 1.0670x over previous
#include <cuda_runtime.h>
#include <cuda_bf16.h>
#include <math.h>

#define B_ 2
#define C3_ 128
#define DZ_ 32
#define HW_ 576
#define C2_ 96
#define K_ 8
#define E_ 256
#define NH_ 4
#define HD_ 64
#define TOPO_ 64
#define LN_EPS 1e-5f
#define LOG2E_ 1.4426950408889634f

// ------------------------- device scratch (no allocation) -------------------
__device__ float g_w1t[C2_ * 9 * TOPO_];
__device__ float g_h[B_ * K_ * HW_ * TOPO_];
__device__ float g_topo[B_ * K_ * HW_];
__device__ __nv_bfloat16 g_Q[B_ * NH_ * DZ_ * HW_ * HD_];   // pre-scaled by log2e/8
__device__ __nv_bfloat16 g_K[B_ * NH_ * K_ * HW_ * HD_];    // (b,h,c,p,d)
__device__ __nv_bfloat16 g_Vt[B_ * NH_ * K_ * HD_ * HW_];   // (b,h,c,d,p) transposed
__device__ float g_O[B_ * DZ_ * HW_ * E_];
__device__ float g_WqT[E_ * C3_];
__device__ float g_WpT[C3_ * E_];
__device__ float g_WkT[E_ * C2_];
__device__ float g_WvT[E_ * C2_];

__device__ __forceinline__ int flex_int(const void* p, int dflt) {
    int v = *(const int*)p;
    if (v >= 1 && v <= 1000000) return v;
    float f = *(const float*)p;
    if (f >= 1.f && f <= 1000000.f) return (int)f;
    return dflt;
}

__device__ __forceinline__ unsigned pk2(float lo, float hi) {
    unsigned r;
    asm("cvt.rn.bf16x2.f32 %0, %1, %2;" : "=r"(r) : "f"(hi), "f"(lo));
    return r;
}

__device__ __forceinline__ float ex2(float x) {
    float y;
    asm("ex2.approx.f32 %0, %1;" : "=f"(y) : "f"(x));
    return y;
}

__device__ __forceinline__ void ldsm4(unsigned& r0, unsigned& r1,
                                      unsigned& r2, unsigned& r3, unsigned addr) {
    asm volatile("ldmatrix.sync.aligned.m8n8.x4.shared.b16 {%0,%1,%2,%3}, [%4];"
                 : "=r"(r0), "=r"(r1), "=r"(r2), "=r"(r3) : "r"(addr));
}

__device__ __forceinline__ void mma_tf32(float4& d,
                                         unsigned a0, unsigned a1, unsigned a2, unsigned a3,
                                         unsigned b0, unsigned b1) {
    asm volatile(
        "mma.sync.aligned.m16n8k8.row.col.f32.tf32.tf32.f32 "
        "{%0,%1,%2,%3}, {%4,%5,%6,%7}, {%8,%9}, {%0,%1,%2,%3};"
        : "+f"(d.x), "+f"(d.y), "+f"(d.z), "+f"(d.w)
        : "r"(a0), "r"(a1), "r"(a2), "r"(a3), "r"(b0), "r"(b1));
}

__device__ __forceinline__ void mma_bf16(float4& d,
                                         unsigned a0, unsigned a1, unsigned a2, unsigned a3,
                                         unsigned b0, unsigned b1) {
    asm volatile(
        "mma.sync.aligned.m16n8k16.row.col.f32.bf16.bf16.f32 "
        "{%0,%1,%2,%3}, {%4,%5,%6,%7}, {%8,%9}, {%0,%1,%2,%3};"
        : "+f"(d.x), "+f"(d.y), "+f"(d.z), "+f"(d.w)
        : "r"(a0), "r"(a1), "r"(a2), "r"(a3), "r"(b0), "r"(b1));
}

// ------------------------- kernel 0: all weight prep ------------------------
__global__ void k_wprep(const float* __restrict__ w1,
                        const float* __restrict__ Wq, const float* __restrict__ Wp,
                        const float* __restrict__ Wk, const float* __restrict__ Wv) {
    int i = blockIdx.x * 256 + threadIdx.x;
    if (i < TOPO_ * C2_ * 9) {
        int o = i / (C2_ * 9);
        int r = i % (C2_ * 9);
        int c = r / 9, tap = r % 9;
        g_w1t[(c * 9 + tap) * TOPO_ + o] = w1[i];
    }
    if (i < C3_ * E_) {
        int e = i / C3_, c = i % C3_;
        g_WqT[i] = Wq[c * E_ + e];
        g_WpT[c * E_ + e] = Wp[i];
    }
    if (i < C2_ * E_) {
        int e = i / C2_, c = i % C2_;
        g_WkT[i] = Wk[c * E_ + e];
        g_WvT[i] = Wv[c * E_ + e];
    }
}

// ===================== fused front: conv1 | qproj | kvproj ==================
// job 0..95:    conv1 (bk = job/6, y-tile = job%6)
// job 96..671:  qproj (576 blocks)
// job 672..959: kvproj (288 blocks; even=K, odd=V)

__device__ void conv1_body(int job, const float* __restrict__ F2,
                           const float* __restrict__ bng,
                           const float* __restrict__ bnb, float* sm) {
    float* in_s = sm;            // [16][6][26] = 2496
    float* w_s = sm + 2496;      // [16*9*64] = 9216
    int bk = job / 6;
    int y0 = (job % 6) * 4;
    int b = bk >> 3, k = bk & 7;
    int tid = threadIdx.x;
    int pg = tid >> 3;           // 0..31: pixel group (3 consecutive x)
    int og = tid & 7;            // 0..7: 8 outputs each
    int pl = pg * 3;
    int yrel = pl / 24;
    int x0 = pl % 24;
    int o0 = og * 8;
    float acc[3][8];
#pragma unroll
    for (int u = 0; u < 3; u++)
#pragma unroll
        for (int v = 0; v < 8; v++) acc[u][v] = 0.f;

    for (int c0 = 0; c0 < C2_; c0 += 16) {
        __syncthreads();
        for (int idx = tid; idx < 16 * 6 * 26; idx += 256) {
            int cc = idx / 156, rem = idx % 156;
            int yy = rem / 26, xx = rem % 26;
            int y = y0 - 1 + yy, x = xx - 1;
            float v = 0.f;
            if ((unsigned)y < 24u && (unsigned)x < 24u)
                v = F2[((b * C2_ + c0 + cc) * HW_ + y * 24 + x) * K_ + k];
            in_s[cc * 156 + yy * 26 + xx] = v;
        }
        for (int idx = tid; idx < 16 * 9 * 64; idx += 256)
            w_s[idx] = g_w1t[c0 * 9 * 64 + idx];
        __syncthreads();
        for (int cc = 0; cc < 16; cc++) {
#pragma unroll
            for (int dy = 0; dy < 3; dy++) {
                float rv[5];
#pragma unroll
                for (int u = 0; u < 5; u++) rv[u] = in_s[cc * 156 + (yrel + dy) * 26 + x0 + u];
#pragma unroll
                for (int dx = 0; dx < 3; dx++) {
                    const float* wp = &w_s[(cc * 9 + dy * 3 + dx) * 64 + o0];
                    float4 wa = *(const float4*)wp;
                    float4 wb = *(const float4*)(wp + 4);
#pragma unroll
                    for (int u = 0; u < 3; u++) {
                        float a = rv[u + dx];
                        acc[u][0] += a * wa.x; acc[u][1] += a * wa.y;
                        acc[u][2] += a * wa.z; acc[u][3] += a * wa.w;
                        acc[u][4] += a * wb.x; acc[u][5] += a * wb.y;
                        acc[u][6] += a * wb.z; acc[u][7] += a * wb.w;
                    }
                }
            }
        }
    }
    float invs = rsqrtf(1.f + LN_EPS);
    float sg[8], sb[8];
#pragma unroll
    for (int v = 0; v < 8; v++) { sg[v] = bng[o0 + v] * invs; sb[v] = bnb[o0 + v]; }
#pragma unroll
    for (int u = 0; u < 3; u++) {
        int p = (y0 + yrel) * 24 + x0 + u;
        float4 h0, h1;
        h0.x = fmaxf(acc[u][0] * sg[0] + sb[0], 0.f);
        h0.y = fmaxf(acc[u][1] * sg[1] + sb[1], 0.f);
        h0.z = fmaxf(acc[u][2] * sg[2] + sb[2], 0.f);
        h0.w = fmaxf(acc[u][3] * sg[3] + sb[3], 0.f);
        h1.x = fmaxf(acc[u][4] * sg[4] + sb[4], 0.f);
        h1.y = fmaxf(acc[u][5] * sg[5] + sb[5], 0.f);
        h1.z = fmaxf(acc[u][6] * sg[6] + sb[6], 0.f);
        h1.w = fmaxf(acc[u][7] * sg[7] + sb[7], 0.f);
        *(float4*)&g_h[(bk * HW_ + p) * TOPO_ + o0] = h0;
        *(float4*)&g_h[(bk * HW_ + p) * TOPO_ + o0 + 4] = h1;
    }
}

__device__ void qproj_body(int job, const float* __restrict__ F3,
                           const float* __restrict__ lng,
                           const float* __restrict__ lnb, float* qsm) {
    float* xk = qsm;                  // [128][72]
    float* bs = qsm + 128 * 72;       // [256][33]
    float* s_o = qsm;                 // alias, [64][260]
    __shared__ float smean[64], srstd[64];

    int p0 = (job % 9) * 64;
    int z = (job / 9) % DZ_;
    int b = job / (9 * DZ_);

    int tid = threadIdx.x;
    int w = tid >> 5, lane = tid & 31;
    int g = lane >> 2, t = lane & 3;
    int mt = w & 3, nh = w >> 2;

    {
        int r = tid & 63;
        int cb = tid >> 6;
        for (int c = cb; c < C3_; c += 4)
            xk[c * 72 + r] = F3[(b * C3_ + c) * (DZ_ * HW_) + z * HW_ + p0 + r];
    }

    float4 acc[16];
#pragma unroll
    for (int n = 0; n < 16; n++) acc[n] = make_float4(0.f, 0.f, 0.f, 0.f);

    for (int kb = 0; kb < 4; kb++) {
        __syncthreads();
        {
            int kk = tid & 31;
            int n0 = tid >> 5;
            for (int n = n0; n < 256; n += 8)
                bs[n * 33 + kk] = g_WqT[n * C3_ + kb * 32 + kk];
        }
        __syncthreads();
#pragma unroll
        for (int kcl = 0; kcl < 4; kcl++) {
            int krow = kb * 32 + kcl * 8;
            int arow = mt * 16 + g;
            unsigned a0 = __float_as_uint(xk[(krow + t) * 72 + arow]);
            unsigned a1 = __float_as_uint(xk[(krow + t) * 72 + arow + 8]);
            unsigned a2 = __float_as_uint(xk[(krow + t + 4) * 72 + arow]);
            unsigned a3 = __float_as_uint(xk[(krow + t + 4) * 72 + arow + 8]);
#pragma unroll
            for (int n = 0; n < 16; n++) {
                const float* br = &bs[(nh * 128 + n * 8 + g) * 33 + kcl * 8];
                mma_tf32(acc[n], a0, a1, a2, a3,
                         __float_as_uint(br[t]), __float_as_uint(br[t + 4]));
            }
        }
    }
    __syncthreads();

    {
        int rl = mt * 16 + g;
#pragma unroll
        for (int n = 0; n < 16; n++) {
            int col = nh * 128 + n * 8 + 2 * t;
            s_o[rl * 260 + col] = acc[n].x;
            s_o[rl * 260 + col + 1] = acc[n].y;
            s_o[(rl + 8) * 260 + col] = acc[n].z;
            s_o[(rl + 8) * 260 + col + 1] = acc[n].w;
        }
    }
    __syncthreads();

#pragma unroll
    for (int rr = 0; rr < 8; rr++) {
        int row = w * 8 + rr;
        float s = 0.f, q = 0.f;
#pragma unroll
        for (int jj = 0; jj < 8; jj++) {
            float v = s_o[row * 260 + lane + 32 * jj];
            s += v; q += v * v;
        }
#pragma unroll
        for (int off = 16; off >= 1; off >>= 1) {
            s += __shfl_xor_sync(0xffffffffu, s, off);
            q += __shfl_xor_sync(0xffffffffu, q, off);
        }
        if (lane == 0) {
            float mu = s * (1.f / 256.f);
            smean[row] = mu;
            srstd[row] = rsqrtf(q * (1.f / 256.f) - mu * mu + LN_EPS);
        }
    }
    __syncthreads();

    {
        int cl = (tid & 63) * 4;
        int rb = tid >> 6;
        float4 g4 = *(const float4*)&lng[cl];
        float4 b4 = *(const float4*)&lnb[cl];
        int h = cl >> 6, cc = cl & 63;
        const float qscale = 0.125f * LOG2E_;
        long long obase = ((long long)(b * NH_ + h) * DZ_ + z) * HW_;
        for (int r = rb; r < 64; r += 4) {
            float mu = smean[r], rs = srstd[r];
            float v0 = ((s_o[r * 260 + cl] - mu) * rs * g4.x + b4.x) * qscale;
            float v1 = ((s_o[r * 260 + cl + 1] - mu) * rs * g4.y + b4.y) * qscale;
            float v2 = ((s_o[r * 260 + cl + 2] - mu) * rs * g4.z + b4.z) * qscale;
            float v3 = ((s_o[r * 260 + cl + 3] - mu) * rs * g4.w + b4.w) * qscale;
            uint2 u = make_uint2(pk2(v0, v1), pk2(v2, v3));
            *(uint2*)&g_Q[(obase + p0 + r) * HD_ + cc] = u;
        }
    }
}

__device__ void kvproj_body(int job, const float* __restrict__ F2,
                            const float* __restrict__ lng,
                            const float* __restrict__ lnb, float* ksm) {
    float* xk = ksm;                  // [96][72]
    float* bs = ksm + 96 * 72;        // [256][33]
    float* s_o = ksm + 96 * 72;       // alias, [64][260]
    __shared__ float smean[64], srstd[64];

    int mat = job & 1;
    int sp = job >> 1;
    int p0 = (sp % 9) * 64;
    int k = (sp / 9) % K_;
    int b = sp / (9 * K_);

    int tid = threadIdx.x;
    int w = tid >> 5, lane = tid & 31;
    int g = lane >> 2, t = lane & 3;
    int mt = w & 3, nh = w >> 2;

    {
        int r = tid & 63;
        int cb = tid >> 6;
        for (int c = cb; c < C2_; c += 4)
            xk[c * 72 + r] = F2[((b * C2_ + c) * HW_ + p0 + r) * K_ + k];
    }

    const float* WT = mat == 0 ? g_WkT : g_WvT;
    float4 acc[16];
#pragma unroll
    for (int n = 0; n < 16; n++) acc[n] = make_float4(0.f, 0.f, 0.f, 0.f);

    for (int kb = 0; kb < 3; kb++) {
        __syncthreads();
        {
            int kk = tid & 31;
            int n0 = tid >> 5;
            for (int n = n0; n < 256; n += 8)
                bs[n * 33 + kk] = WT[n * C2_ + kb * 32 + kk];
        }
        __syncthreads();
#pragma unroll
        for (int kcl = 0; kcl < 4; kcl++) {
            int krow = kb * 32 + kcl * 8;
            int arow = mt * 16 + g;
            unsigned a0 = __float_as_uint(xk[(krow + t) * 72 + arow]);
            unsigned a1 = __float_as_uint(xk[(krow + t) * 72 + arow + 8]);
            unsigned a2 = __float_as_uint(xk[(krow + t + 4) * 72 + arow]);
            unsigned a3 = __float_as_uint(xk[(krow + t + 4) * 72 + arow + 8]);
#pragma unroll
            for (int n = 0; n < 16; n++) {
                const float* br = &bs[(nh * 128 + n * 8 + g) * 33 + kcl * 8];
                mma_tf32(acc[n], a0, a1, a2, a3,
                         __float_as_uint(br[t]), __float_as_uint(br[t + 4]));
            }
        }
    }
    __syncthreads();
    {
        int rl = mt * 16 + g;
#pragma unroll
        for (int n = 0; n < 16; n++) {
            int col = nh * 128 + n * 8 + 2 * t;
            s_o[rl * 260 + col] = acc[n].x;
            s_o[rl * 260 + col + 1] = acc[n].y;
            s_o[(rl + 8) * 260 + col] = acc[n].z;
            s_o[(rl + 8) * 260 + col + 1] = acc[n].w;
        }
    }
    __syncthreads();
#pragma unroll
    for (int rr = 0; rr < 8; rr++) {
        int row = w * 8 + rr;
        float s = 0.f, q = 0.f;
#pragma unroll
        for (int jj = 0; jj < 8; jj++) {
            float v = s_o[row * 260 + lane + 32 * jj];
            s += v; q += v * v;
        }
#pragma unroll
        for (int off = 16; off >= 1; off >>= 1) {
            s += __shfl_xor_sync(0xffffffffu, s, off);
            q += __shfl_xor_sync(0xffffffffu, q, off);
        }
        if (lane == 0) {
            float mu = s * (1.f / 256.f);
            smean[row] = mu;
            srstd[row] = rsqrtf(q * (1.f / 256.f) - mu * mu + LN_EPS);
        }
    }
    __syncthreads();

    if (mat == 0) {
        int cl = (tid & 63) * 4;
        int rb = tid >> 6;
        float4 g4 = *(const float4*)&lng[cl];
        float4 b4 = *(const float4*)&lnb[cl];
        int h = cl >> 6, cc = cl & 63;
        long long obase = ((long long)(b * NH_ + h) * K_ + k) * HW_;
        for (int r = rb; r < 64; r += 4) {
            float mu = smean[r], rs = srstd[r];
            float v0 = (s_o[r * 260 + cl] - mu) * rs * g4.x + b4.x;
            float v1 = (s_o[r * 260 + cl + 1] - mu) * rs * g4.y + b4.y;
            float v2 = (s_o[r * 260 + cl + 2] - mu) * rs * g4.z + b4.z;
            float v3 = (s_o[r * 260 + cl + 3] - mu) * rs * g4.w + b4.w;
            uint2 u = make_uint2(pk2(v0, v1), pk2(v2, v3));
            *(uint2*)&g_K[(obase + p0 + r) * HD_ + cc] = u;
        }
    } else {
        int e = tid;
        float ge = lng[e], be = lnb[e];
        int h = e >> 6, d = e & 63;
        long long vb = (((long long)(b * NH_ + h) * K_ + k) * HD_ + d) * HW_ + p0;
#pragma unroll
        for (int rb2 = 0; rb2 < 16; rb2++) {
            int r = rb2 * 4;
            float v0 = (s_o[r * 260 + e] - smean[r]) * srstd[r] * ge + be;
            float v1 = (s_o[(r + 1) * 260 + e] - smean[r + 1]) * srstd[r + 1] * ge + be;
            float v2 = (s_o[(r + 2) * 260 + e] - smean[r + 2]) * srstd[r + 2] * ge + be;
            float v3 = (s_o[(r + 3) * 260 + e] - smean[r + 3]) * srstd[r + 3] * ge + be;
            uint2 u = make_uint2(pk2(v0, v1), pk2(v2, v3));
            *(uint2*)&g_Vt[vb + r] = u;
        }
    }
}

#define NJ_CONV 96
#define NJ_Q 576
#define NJ_KV 288
__global__ __launch_bounds__(256) void k_front(const float* __restrict__ F2,
                                               const float* __restrict__ F3,
                                               const float* __restrict__ bng,
                                               const float* __restrict__ bnb,
                                               const float* __restrict__ lnkg,
                                               const float* __restrict__ lnkb,
                                               const float* __restrict__ lnqg,
                                               const float* __restrict__ lnqb) {
    extern __shared__ float fsm[];
    int job = blockIdx.x;
    if (job < NJ_CONV) {
        conv1_body(job, F2, bng, bnb, fsm);
    } else if (job < NJ_CONV + NJ_Q) {
        qproj_body(job - NJ_CONV, F3, lnqg, lnqb, fsm);
    } else {
        kvproj_body(job - NJ_CONV - NJ_Q, F2, lnkg, lnkb, fsm);
    }
}

// ------------------- kernel 2: conv2 1x1 + neighbor-sum -> topo -------------
__global__ __launch_bounds__(192) void k_topo(const float* __restrict__ w2,
                                              const float* __restrict__ w2b) {
    __shared__ float sp[HW_];
    __shared__ float wsh[64];
    int bk = blockIdx.x;
    int tid = threadIdx.x;
    if (tid < 64) wsh[tid] = w2[tid];
    __syncthreads();
    for (int p = tid; p < HW_; p += 192) {
        const float* hp = &g_h[(bk * HW_ + p) * TOPO_];
        float s = w2b[0];
#pragma unroll
        for (int o = 0; o < 64; o += 4) {
            float4 hv = *(const float4*)&hp[o];
            s += hv.x * wsh[o] + hv.y * wsh[o + 1] + hv.z * wsh[o + 2] + hv.w * wsh[o + 3];
        }
        sp[p] = s;
    }
    __syncthreads();
    for (int p = tid; p < HW_; p += 192) {
        int y = p / 24, x = p % 24;
        float s = 0.f;
#pragma unroll
        for (int dy = -1; dy <= 1; dy++)
#pragma unroll
            for (int dx = -1; dx <= 1; dx++) {
                if (dy == 0 && dx == 0) continue;
                int yy = y + dy, xx = x + dx;
                if ((unsigned)yy < 24u && (unsigned)xx < 24u) s += sp[yy * 24 + xx];
            }
        g_topo[bk * HW_ + p] = sp[p] + 0.5f * s;
    }
}

// ------------------- kernel 5: flash attention (bf16 MMA + LDSM, exp2) ------
#define BST 72
__global__ __launch_bounds__(128) void k_attn(const float* __restrict__ lam_p,
                                              const void* __restrict__ D0_p,
                                              const void* __restrict__ slab_p) {
    extern __shared__ __nv_bfloat16 bsm[];
    __nv_bfloat16* Qs = bsm;                   // [128][BST]
    __nv_bfloat16* Ks = bsm + 128 * BST;       // [64][BST]
    __nv_bfloat16* Vs = bsm + 192 * BST;       // [64][BST]

    int bid = blockIdx.x;
    int p0 = (bid % 9) * 64;
    int zp = (bid / 9) % (DZ_ / 2);
    int h = (bid / (9 * (DZ_ / 2))) % NH_;
    int b = bid / (9 * (DZ_ / 2) * NH_);
    int z0 = zp * 2;

    int D0 = flex_int(D0_p, 128);
    int slab = flex_int(slab_p, 16);
    float lam2 = (*lam_p) * LOG2E_;

    int kkz[2], cloz[2], chiz[2];
#pragma unroll
    for (int i = 0; i < 2; i++) {
        int zz = z0 + i;
        int zq = (int)llrint((double)(D0 - 1) * (double)zz / (double)(DZ_ - 1));
        int kk = zq / slab;
        if (kk < 0) kk = 0;
        if (kk > K_ - 1) kk = K_ - 1;
        kkz[i] = kk;
        cloz[i] = (kk - 1 < 0) ? 0 : kk - 1;
        chiz[i] = (kk + 1 > K_ - 1) ? K_ - 1 : kk + 1;
    }
    int cU_lo = min(cloz[0], cloz[1]);
    int cU_hi = max(chiz[0], chiz[1]);

    int tid = threadIdx.x;
    int w = tid >> 5;
    int lane = tid & 31;
    int g = lane >> 2;
    int t = lane & 3;

    int wz = w >> 1;
    int zw = z0 + wz;
    int kk_w = kkz[wz], clo_w = cloz[wz], chi_w = chiz[wz];
    int prow = p0 + (w & 1) * 32;
    int qrow = w * 32;

    unsigned qb_s = (unsigned)__cvta_generic_to_shared(Qs);
    unsigned kb_s = (unsigned)__cvta_generic_to_shared(Ks);
    unsigned vb_s = (unsigned)__cvta_generic_to_shared(Vs);
    unsigned laneoff = (((lane & 7) + ((lane >> 3) & 1) * 8) * BST + ((lane >> 4) & 1) * 8) * 2;

    {
        long long qb0 = ((((long long)(b * NH_ + h) * DZ_ + z0) * HW_) + p0) * HD_;
#pragma unroll
        for (int it = 0; it < 8; it++) {
            int idx = tid + it * 128;
            int r = idx >> 3, v = (idx & 7) * 8;
            long long src = qb0 + (long long)(r >> 6) * (HW_ * HD_) + (long long)(r & 63) * 64 + v;
            *(uint4*)&Qs[r * BST + v] = *(const uint4*)&g_Q[src];
        }
    }

    float l00 = 0.f, l01 = 0.f, l10 = 0.f, l11 = 0.f;
    float4 O0[8], O1[8];
#pragma unroll
    for (int n = 0; n < 8; n++) {
        O0[n] = make_float4(0.f, 0.f, 0.f, 0.f);
        O1[n] = make_float4(0.f, 0.f, 0.f, 0.f);
    }

    for (int c = cU_lo; c <= cU_hi; c++) {
        bool active = (c >= clo_w) && (c <= chi_w);
        float bias2 = (c == kk_w) ? 0.f : -0.5f * LOG2E_;
        long long kb = (((long long)(b * NH_ + h) * K_ + c) * HW_) * HD_;
        long long vb = (((long long)(b * NH_ + h) * K_ + c) * HD_) * HW_;
        const float* topo_c = &g_topo[(b * K_ + c) * HW_];
        for (int pk0 = 0; pk0 < HW_; pk0 += 64) {
            __syncthreads();
#pragma unroll
            for (int it = 0; it < 4; it++) {
                int idx = tid + it * 128;
                int r = idx >> 3, v = (idx & 7) * 8;
                *(uint4*)&Ks[r * BST + v] = *(const uint4*)&g_K[kb + (long long)(pk0 + r) * 64 + v];
                *(uint4*)&Vs[r * BST + v] = *(const uint4*)&g_Vt[vb + (long long)r * HW_ + pk0 + v];
            }
            __syncthreads();
            if (!active) continue;

            float4 S0[8], S1[8];
#pragma unroll
            for (int n = 0; n < 8; n++) {
                S0[n] = make_float4(0.f, 0.f, 0.f, 0.f);
                S1[n] = make_float4(0.f, 0.f, 0.f, 0.f);
            }
#pragma unroll
            for (int kc = 0; kc < 4; kc++) {
                int kc16 = kc * 16;
                unsigned a00, a01, a02, a03, a10, a11, a12, a13;
                ldsm4(a00, a01, a02, a03, qb_s + (qrow * BST + kc16) * 2 + laneoff);
                ldsm4(a10, a11, a12, a13, qb_s + ((qrow + 16) * BST + kc16) * 2 + laneoff);
#pragma unroll
                for (int n2 = 0; n2 < 4; n2++) {
                    unsigned b0, b1, b2, b3;
                    ldsm4(b0, b1, b2, b3, kb_s + ((n2 * 16) * BST + kc16) * 2 + laneoff);
                    mma_bf16(S0[2 * n2],     a00, a01, a02, a03, b0, b2);
                    mma_bf16(S0[2 * n2 + 1], a00, a01, a02, a03, b1, b3);
                    mma_bf16(S1[2 * n2],     a10, a11, a12, a13, b0, b2);
                    mma_bf16(S1[2 * n2 + 1], a10, a11, a12, a13, b1, b3);
                }
            }

            int rq0 = prow + g;
            int rq1 = prow + 16 + g;
#pragma unroll
            for (int n = 0; n < 8; n++) {
                int j0 = pk0 + n * 8 + 2 * t;
                int j1 = j0 + 1;
                float d00 = bias2, d01 = bias2, d02 = bias2, d03 = bias2;
                float d10 = bias2, d11 = bias2, d12 = bias2, d13 = bias2;
                if (rq0 == j0)     d00 += lam2 * topo_c[j0];
                if (rq0 == j1)     d01 += lam2 * topo_c[j1];
                if (rq0 + 8 == j0) d02 += lam2 * topo_c[j0];
                if (rq0 + 8 == j1) d03 += lam2 * topo_c[j1];
                if (rq1 == j0)     d10 += lam2 * topo_c[j0];
                if (rq1 == j1)     d11 += lam2 * topo_c[j1];
                if (rq1 + 8 == j0) d12 += lam2 * topo_c[j0];
                if (rq1 + 8 == j1) d13 += lam2 * topo_c[j1];
                S0[n].x = ex2(S0[n].x + d00); S0[n].y = ex2(S0[n].y + d01);
                S0[n].z = ex2(S0[n].z + d02); S0[n].w = ex2(S0[n].w + d03);
                S1[n].x = ex2(S1[n].x + d10); S1[n].y = ex2(S1[n].y + d11);
                S1[n].z = ex2(S1[n].z + d12); S1[n].w = ex2(S1[n].w + d13);
                l00 += S0[n].x + S0[n].y; l01 += S0[n].z + S0[n].w;
                l10 += S1[n].x + S1[n].y; l11 += S1[n].z + S1[n].w;
            }

#pragma unroll
            for (int kc = 0; kc < 4; kc++) {
                int kc16 = kc * 16;
                unsigned a00 = pk2(S0[2 * kc].x, S0[2 * kc].y);
                unsigned a01 = pk2(S0[2 * kc].z, S0[2 * kc].w);
                unsigned a02 = pk2(S0[2 * kc + 1].x, S0[2 * kc + 1].y);
                unsigned a03 = pk2(S0[2 * kc + 1].z, S0[2 * kc + 1].w);
                unsigned a10 = pk2(S1[2 * kc].x, S1[2 * kc].y);
                unsigned a11 = pk2(S1[2 * kc].z, S1[2 * kc].w);
                unsigned a12 = pk2(S1[2 * kc + 1].x, S1[2 * kc + 1].y);
                unsigned a13 = pk2(S1[2 * kc + 1].z, S1[2 * kc + 1].w);
#pragma unroll
                for (int n2 = 0; n2 < 4; n2++) {
                    unsigned b0, b1, b2, b3;
                    ldsm4(b0, b1, b2, b3, vb_s + ((n2 * 16) * BST + kc16) * 2 + laneoff);
                    mma_bf16(O0[2 * n2],     a00, a01, a02, a03, b0, b2);
                    mma_bf16(O0[2 * n2 + 1], a00, a01, a02, a03, b1, b3);
                    mma_bf16(O1[2 * n2],     a10, a11, a12, a13, b0, b2);
                    mma_bf16(O1[2 * n2 + 1], a10, a11, a12, a13, b1, b3);
                }
            }
        }
    }

#pragma unroll
    for (int off = 1; off <= 2; off <<= 1) {
        l00 += __shfl_xor_sync(0xffffffffu, l00, off);
        l01 += __shfl_xor_sync(0xffffffffu, l01, off);
        l10 += __shfl_xor_sync(0xffffffffu, l10, off);
        l11 += __shfl_xor_sync(0xffffffffu, l11, off);
    }

    float i00 = 1.f / l00, i01 = 1.f / l01, i10 = 1.f / l10, i11 = 1.f / l11;
    long long ob = ((long long)(b * DZ_ + zw) * HW_) * E_ + h * HD_;
    int rq0 = prow + g, rq1 = prow + 16 + g;
#pragma unroll
    for (int n = 0; n < 8; n++) {
        int col = n * 8 + 2 * t;
        *(float2*)&g_O[ob + (long long)rq0 * E_ + col] = make_float2(O0[n].x * i00, O0[n].y * i00);
        *(float2*)&g_O[ob + (long long)(rq0 + 8) * E_ + col] = make_float2(O0[n].z * i01, O0[n].w * i01);
        *(float2*)&g_O[ob + (long long)rq1 * E_ + col] = make_float2(O1[n].x * i10, O1[n].y * i10);
        *(float2*)&g_O[ob + (long long)(rq1 + 8) * E_ + col] = make_float2(O1[n].z * i11, O1[n].w * i11);
    }
}

// ------------------- kernel 6: output projection + residual (tf32 MMA) ------
__global__ __launch_bounds__(256) void k_oproj(const float* __restrict__ F3,
                                               float* __restrict__ out) {
    extern __shared__ float osm[];
    float* bs = osm;                  // [128][33]
    float* s_o = osm + 128 * 33;      // [128 cols][68 rows]
    int bid = blockIdx.x;
    int p0 = (bid % 9) * 64;
    int z = (bid / 9) % DZ_;
    int b = bid / (9 * DZ_);

    int tid = threadIdx.x;
    int w = tid >> 5, lane = tid & 31;
    int g = lane >> 2, t = lane & 3;
    int mt = w & 3, nh = w >> 2;

    int rowl = (b * DZ_ + z) * HW_ + p0 + mt * 16 + g;
    const float* Al = &g_O[(long long)rowl * E_];
    const float* Ah = Al + 8LL * E_;

    float4 acc[8];
#pragma unroll
    for (int n = 0; n < 8; n++) acc[n] = make_float4(0.f, 0.f, 0.f, 0.f);

    for (int kb = 0; kb < 8; kb++) {
        __syncthreads();
        {
            int kk = tid & 31;
            int n0 = tid >> 5;
            for (int n = n0; n < 128; n += 8)
                bs[n * 33 + kk] = g_WpT[n * E_ + kb * 32 + kk];
        }
        __syncthreads();
#pragma unroll
        for (int kcl = 0; kcl < 4; kcl++) {
            int kcol = kb * 32 + kcl * 8;
            unsigned a0 = __float_as_uint(Al[kcol + t]);
            unsigned a1 = __float_as_uint(Ah[kcol + t]);
            unsigned a2 = __float_as_uint(Al[kcol + t + 4]);
            unsigned a3 = __float_as_uint(Ah[kcol + t + 4]);
#pragma unroll
            for (int n = 0; n < 8; n++) {
                const float* br = &bs[(nh * 64 + n * 8 + g) * 33 + kcl * 8];
                mma_tf32(acc[n], a0, a1, a2, a3,
                         __float_as_uint(br[t]), __float_as_uint(br[t + 4]));
            }
        }
    }
    __syncthreads();

    {
        int rl = mt * 16 + g;
#pragma unroll
        for (int n = 0; n < 8; n++) {
            int col = nh * 64 + n * 8 + 2 * t;
            s_o[col * 68 + rl] = acc[n].x;
            s_o[(col + 1) * 68 + rl] = acc[n].y;
            s_o[col * 68 + rl + 8] = acc[n].z;
            s_o[(col + 1) * 68 + rl + 8] = acc[n].w;
        }
    }
    __syncthreads();

    {
        int r = tid & 63;
        int cb = tid >> 6;
        for (int c = cb; c < C3_; c += 4) {
            long long oi = (long long)(b * C3_ + c) * (DZ_ * HW_) + z * HW_ + p0 + r;
            out[oi] = F3[oi] + s_o[c * 68 + r];
        }
    }
}

// ----------------------------------- launch ---------------------------------
extern "C" void kernel_launch(void* const* d_in, const int* in_sizes, int n_in,
                              void* d_out, int out_size) {
    const float* F3  = (const float*)d_in[0];
    const float* F2  = (const float*)d_in[1];
    const float* Wq  = (const float*)d_in[2];
    const float* Wk  = (const float*)d_in[3];
    const float* Wv  = (const float*)d_in[4];
    const float* Wp  = (const float*)d_in[5];
    const float* lnqg = (const float*)d_in[6];
    const float* lnqb = (const float*)d_in[7];
    const float* lnkg = (const float*)d_in[8];
    const float* lnkb = (const float*)d_in[9];
    const float* w1   = (const float*)d_in[10];
    const float* bng  = (const float*)d_in[11];
    const float* bnb  = (const float*)d_in[12];
    const float* w2   = (const float*)d_in[13];
    const float* w2b  = (const float*)d_in[14];
    const float* lam  = (const float*)d_in[15];
    const void*  D0p  = d_in[16];
    const void*  slabp = d_in[17];
    float* out = (float*)d_out;

    int front_smem = (96 * 72 + 64 * 260) * (int)sizeof(float);   // 94208 (max of jobs)
    int attn_smem  = 256 * BST * (int)sizeof(__nv_bfloat16);      // 36864
    int oproj_smem = (128 * 33 + 128 * 68) * (int)sizeof(float);  // 51712
    static int cfg_done = 0;
    if (!cfg_done) {
        cudaFuncSetAttribute(k_front, cudaFuncAttributeMaxDynamicSharedMemorySize, front_smem);
        cudaFuncSetAttribute(k_attn, cudaFuncAttributeMaxDynamicSharedMemorySize, attn_smem);
        cudaFuncSetAttribute(k_oproj, cudaFuncAttributeMaxDynamicSharedMemorySize, oproj_smem);
        cfg_done = 1;
    }

    k_wprep<<<(TOPO_ * C2_ * 9 + 255) / 256, 256>>>(w1, Wq, Wp, Wk, Wv);
    k_front<<<NJ_CONV + NJ_Q + NJ_KV, 256, front_smem>>>(F2, F3, bng, bnb,
                                                         lnkg, lnkb, lnqg, lnqb);
    k_topo<<<B_ * K_, 192>>>(w2, w2b);
    k_attn<<<B_ * NH_ * (DZ_ / 2) * 9, 128, attn_smem>>>(lam, D0p, slabp);
    k_oproj<<<B_ * DZ_ * 9, 256, oproj_smem>>>(F3, out);
}